// round 5
// baseline (speedup 1.0000x reference)
#include <cuda_runtime.h>
#include <cuda_fp16.h>
#include <math.h>
#include <stdint.h>

#define T_TOT   16384
#define H_DIM   1024
#define I_DIM   512
#define E_NUM   8
#define TOPK    2
#define NASSIGN (T_TOT * TOPK)
#define KC      64

typedef __half hf;

// ======================= scratch =======================
__device__ int   g_topk_idx[NASSIGN];
__device__ float g_topk_w[NASSIGN];
__device__ int   g_cnt[E_NUM];
__device__ int   g_off[E_NUM];
__device__ int   g_fill[E_NUM];
__device__ int   g_tok[NASSIGN];
__device__ float g_aw[NASSIGN];
__device__ int   g_pos[NASSIGN];

__device__ __align__(16) hf g_xhi[(size_t)T_TOT * H_DIM];
__device__ __align__(16) hf g_xlo[(size_t)T_TOT * H_DIM];
__device__ __align__(16) hf g_wgT[(size_t)E_NUM * I_DIM * H_DIM];
__device__ __align__(16) hf g_wuT[(size_t)E_NUM * I_DIM * H_DIM];
__device__ __align__(16) hf g_wdT[(size_t)E_NUM * H_DIM * I_DIM];
__device__ __align__(16) hf g_swgT[(size_t)I_DIM * H_DIM];
__device__ __align__(16) hf g_swuT[(size_t)I_DIM * H_DIM];
__device__ __align__(16) hf g_swdT[(size_t)H_DIM * I_DIM];
__device__ __align__(16) hf g_ihi[(size_t)NASSIGN * I_DIM];
__device__ __align__(16) hf g_ilo[(size_t)NASSIGN * I_DIM];
__device__ __align__(16) hf g_sihi[(size_t)T_TOT * I_DIM];
__device__ __align__(16) hf g_silo[(size_t)T_TOT * I_DIM];
__device__ __align__(16) hf g_dtmp[(size_t)NASSIGN * H_DIM];   // fp16 now (64 MB)

// ======================= helpers =======================
__device__ __forceinline__ uint32_t smem_u32(const void* p) {
    uint32_t a;
    asm("{ .reg .u64 t; cvta.to.shared.u64 t, %1; cvt.u32.u64 %0, t; }" : "=r"(a) : "l"(p));
    return a;
}
__device__ __forceinline__ void cp16(uint32_t dst, const void* src) {
    asm volatile("cp.async.cg.shared.global [%0], [%1], 16;" :: "r"(dst), "l"(src));
}
__device__ __forceinline__ void cp_commit() { asm volatile("cp.async.commit_group;" ::: "memory"); }
template <int N>
__device__ __forceinline__ void cp_wait() { asm volatile("cp.async.wait_group %0;" :: "n"(N) : "memory"); }

__device__ __forceinline__ void ldsm4(uint32_t* r, uint32_t addr) {
    asm volatile("ldmatrix.sync.aligned.m8n8.x4.shared.b16 {%0,%1,%2,%3}, [%4];"
                 : "=r"(r[0]), "=r"(r[1]), "=r"(r[2]), "=r"(r[3]) : "r"(addr));
}
__device__ __forceinline__ void mma16816(float* d, const uint32_t* a, uint32_t b0, uint32_t b1) {
    asm volatile("mma.sync.aligned.m16n8k16.row.col.f32.f16.f16.f32 "
                 "{%0,%1,%2,%3}, {%4,%5,%6,%7}, {%8,%9}, {%0,%1,%2,%3};"
                 : "+f"(d[0]), "+f"(d[1]), "+f"(d[2]), "+f"(d[3])
                 : "r"(a[0]), "r"(a[1]), "r"(a[2]), "r"(a[3]), "r"(b0), "r"(b1));
}
__device__ __forceinline__ float gelu_exact(float x) {
    return 0.5f * x * (1.0f + erff(x * 0.70710678118654752f));
}
__device__ __forceinline__ void splitpair(float v0, float v1, uint32_t& h, uint32_t& l) {
    __half2 ph = __floats2half2_rn(v0, v1);
    float r0 = v0 - __low2float(ph);
    float r1 = v1 - __high2float(ph);
    __half2 pl = __floats2half2_rn(r0, r1);
    h = *reinterpret_cast<uint32_t*>(&ph);
    l = *reinterpret_cast<uint32_t*>(&pl);
}

// ======================= routing =======================
__global__ void init_kernel() {
    if (threadIdx.x < E_NUM) g_cnt[threadIdx.x] = 0;
}

__global__ void __launch_bounds__(256) router_kernel(const float* __restrict__ X,
                                                     const float* __restrict__ GW) {
    __shared__ float sgw[E_NUM * H_DIM];
    for (int i = threadIdx.x; i < E_NUM * H_DIM; i += 256) sgw[i] = GW[i];
    __syncthreads();
    const int warp = threadIdx.x >> 5, lane = threadIdx.x & 31;
    const int t = blockIdx.x * 8 + warp;
    if (t >= T_TOT) return;
    const float* x = X + (size_t)t * H_DIM;
    float acc[E_NUM];
#pragma unroll
    for (int e = 0; e < E_NUM; e++) acc[e] = 0.0f;
    for (int h = lane; h < H_DIM; h += 32) {
        const float xv = x[h];
#pragma unroll
        for (int e = 0; e < E_NUM; e++) acc[e] = fmaf(xv, sgw[e * H_DIM + h], acc[e]);
    }
#pragma unroll
    for (int e = 0; e < E_NUM; e++)
#pragma unroll
        for (int o = 16; o > 0; o >>= 1) acc[e] += __shfl_down_sync(0xffffffffu, acc[e], o);
    if (lane == 0) {
        float l0 = -1e30f, l1 = -1e30f;
        int i0 = 0, i1 = 0;
#pragma unroll
        for (int e = 0; e < E_NUM; e++) {
            const float v = acc[e];
            if (v > l0)      { l1 = l0; i1 = i0; l0 = v; i0 = e; }
            else if (v > l1) { l1 = v; i1 = e; }
        }
        const float w1 = expf(l1 - l0);
        const float inv = 1.0f / (1.0f + w1);
        g_topk_idx[t * 2 + 0] = i0;
        g_topk_idx[t * 2 + 1] = i1;
        g_topk_w[t * 2 + 0] = inv;
        g_topk_w[t * 2 + 1] = w1 * inv;
        atomicAdd(&g_cnt[i0], 1);
        atomicAdd(&g_cnt[i1], 1);
    }
}

__global__ void scan_kernel() {
    if (threadIdx.x == 0) {
        int s = 0;
        for (int e = 0; e < E_NUM; e++) { g_off[e] = s; g_fill[e] = s; s += g_cnt[e]; }
    }
}

__global__ void __launch_bounds__(256) scatter_kernel() {
    const int t = blockIdx.x * 256 + threadIdx.x;
    if (t >= T_TOT) return;
#pragma unroll
    for (int k = 0; k < TOPK; k++) {
        const int e = g_topk_idx[t * 2 + k];
        const float w = g_topk_w[t * 2 + k];
        const int p = atomicAdd(&g_fill[e], 1);
        g_tok[p] = t;
        g_aw[p] = w;
        g_pos[t * 2 + k] = p;
    }
}

// ======================= preprocessing =======================
__global__ void __launch_bounds__(256) split_x_kernel(const float* __restrict__ X) {
    const size_t i = ((size_t)blockIdx.x * 256 + threadIdx.x) * 8;
    const float4 a = *(const float4*)(X + i);
    const float4 b = *(const float4*)(X + i + 4);
    uint32_t h0, l0, h1, l1, h2, l2, h3, l3;
    splitpair(a.x, a.y, h0, l0);
    splitpair(a.z, a.w, h1, l1);
    splitpair(b.x, b.y, h2, l2);
    splitpair(b.z, b.w, h3, l3);
    uint4 H = {h0, h1, h2, h3}, L = {l0, l1, l2, l3};
    *(uint4*)(g_xhi + i) = H;
    *(uint4*)(g_xlo + i) = L;
}

__global__ void __launch_bounds__(256) trans_round_kernel(const float* __restrict__ src,
                                                          hf* __restrict__ dst,
                                                          int R, int C) {
    __shared__ float t[32][33];
    const size_t sb = (size_t)blockIdx.z * R * C;
    const int c0 = blockIdx.x * 32, r0 = blockIdx.y * 32;
    const int tx = threadIdx.x & 31, ty = threadIdx.x >> 5;
#pragma unroll
    for (int j = 0; j < 32; j += 8)
        t[ty + j][tx] = src[sb + (size_t)(r0 + ty + j) * C + c0 + tx];
    __syncthreads();
#pragma unroll
    for (int j = 0; j < 32; j += 8) {
        dst[sb + (size_t)(c0 + ty + j) * R + r0 + tx] = __float2half_rn(t[tx][ty + j]);
    }
}

// ======================= gate+up GEMM (3-stage pipeline) =======================
#define GU_AH  0u
#define GU_AL  16384u
#define GU_BG  32768u
#define GU_BU  40960u
#define STAGE  49152u
#define GEMM_SMEM (3 * 49152)

template <bool ROUTED>
__global__ void __launch_bounds__(256) gu_mma_kernel(const hf* __restrict__ Bg,
                                                     const hf* __restrict__ Bu,
                                                     hf* __restrict__ oHi,
                                                     hf* __restrict__ oLo) {
    const int e   = ROUTED ? blockIdx.z : 0;
    const int cnt = ROUTED ? g_cnt[e] : T_TOT;
    const int off = ROUTED ? g_off[e] : 0;
    const int mb  = blockIdx.y * 128;
    if (mb >= cnt) return;
    const int nb  = blockIdx.x * 64;

    extern __shared__ char dsm[];
    __shared__ int stok[128];
    const uint32_t sb = smem_u32(dsm);

    const int tid = threadIdx.x;
    if (tid < 128) {
        int r = mb + tid;
        if (r >= cnt) r = cnt - 1;
        stok[tid] = ROUTED ? g_tok[off + r] : r;
    }
    __syncthreads();

    const int cx = tid & 7;
    const int rb = tid >> 3;
    const uint32_t so = (uint32_t)rb * 128u + (uint32_t)(((cx ^ (rb & 7))) * 16);
    const size_t wofs = (size_t)e * I_DIM * H_DIM;

    const hf *aHiP[4], *aLoP[4], *bgP[2], *buP[2];
#pragma unroll
    for (int j = 0; j < 4; j++) {
        const size_t arow = (size_t)stok[rb + 32 * j] * H_DIM + cx * 8;
        aHiP[j] = g_xhi + arow;
        aLoP[j] = g_xlo + arow;
    }
#pragma unroll
    for (int j = 0; j < 2; j++) {
        const size_t brow = wofs + (size_t)(nb + rb + 32 * j) * H_DIM + cx * 8;
        bgP[j] = Bg + brow;
        buP[j] = Bu + brow;
    }

    const int warp = tid >> 5, lane = tid & 31;
    const int m0 = (warp & 3) * 32;
    const int n0 = (warp >> 2) * 32;
    const int hl = lane >> 4;
    const int l15 = lane & 15;

    uint32_t aRow[2], aXor[2], bRow[2], bXor[2];
#pragma unroll
    for (int mt = 0; mt < 2; mt++) {
        const int r = m0 + mt * 16 + l15;
        aRow[mt] = (uint32_t)r * 128u;
        aXor[mt] = (uint32_t)(r & 7);
    }
#pragma unroll
    for (int p = 0; p < 2; p++) {
        const int r = n0 + p * 16 + l15;
        bRow[p] = (uint32_t)r * 128u;
        bXor[p] = (uint32_t)(r & 7);
    }

    float accg[2][4][4], accu[2][4][4];
#pragma unroll
    for (int mt = 0; mt < 2; mt++)
#pragma unroll
        for (int nt = 0; nt < 4; nt++)
#pragma unroll
            for (int q = 0; q < 4; q++) { accg[mt][nt][q] = 0.0f; accu[mt][nt][q] = 0.0f; }

    const int NCH = H_DIM / KC;   // 16
    // prologue: chunks 0,1
#pragma unroll
    for (int pc = 0; pc < 2; pc++) {
        const uint32_t d = sb + (uint32_t)pc * STAGE;
        const int k0 = pc * KC;
#pragma unroll
        for (int j = 0; j < 4; j++) {
            cp16(d + GU_AH + so + j * 4096u, aHiP[j] + k0);
            cp16(d + GU_AL + so + j * 4096u, aLoP[j] + k0);
        }
#pragma unroll
        for (int j = 0; j < 2; j++) {
            cp16(d + GU_BG + so + j * 4096u, bgP[j] + k0);
            cp16(d + GU_BU + so + j * 4096u, buP[j] + k0);
        }
        cp_commit();
    }

    int wst = 2;   // next stage slot to write: (c+2)%3, starts at 2
    for (int c = 0; c < NCH; c++) {
        cp_wait<1>();
        __syncthreads();
        if (c + 2 < NCH) {
            const uint32_t d = sb + (uint32_t)wst * STAGE;
            const int k0 = (c + 2) * KC;
#pragma unroll
            for (int j = 0; j < 4; j++) {
                cp16(d + GU_AH + so + j * 4096u, aHiP[j] + k0);
                cp16(d + GU_AL + so + j * 4096u, aLoP[j] + k0);
            }
#pragma unroll
            for (int j = 0; j < 2; j++) {
                cp16(d + GU_BG + so + j * 4096u, bgP[j] + k0);
                cp16(d + GU_BU + so + j * 4096u, buP[j] + k0);
            }
        }
        cp_commit();

        const uint32_t st = sb + (uint32_t)((wst + 1) % 3) * STAGE;   // stage c%3
        wst = (wst + 1) % 3;
#pragma unroll
        for (int kk = 0; kk < 4; kk++) {
            const uint32_t ku = (uint32_t)(2 * kk + hl);
            uint32_t ah[2][4], al[2][4];
#pragma unroll
            for (int mt = 0; mt < 2; mt++) {
                const uint32_t ao = aRow[mt] + ((ku ^ aXor[mt]) << 4);
                ldsm4(ah[mt], st + GU_AH + ao);
                ldsm4(al[mt], st + GU_AL + ao);
            }
            uint32_t bg[2][4], bu[2][4];
#pragma unroll
            for (int p = 0; p < 2; p++) {
                const uint32_t bo = bRow[p] + ((ku ^ bXor[p]) << 4);
                ldsm4(bg[p], st + GU_BG + bo);
                ldsm4(bu[p], st + GU_BU + bo);
            }
#pragma unroll
            for (int mt = 0; mt < 2; mt++)
#pragma unroll
                for (int p = 0; p < 2; p++)
#pragma unroll
                    for (int q = 0; q < 2; q++) {
                        const int nt = 2 * p + q;
                        mma16816(accg[mt][nt], ah[mt], bg[p][q], bg[p][q + 2]);
                        mma16816(accg[mt][nt], al[mt], bg[p][q], bg[p][q + 2]);
                        mma16816(accu[mt][nt], ah[mt], bu[p][q], bu[p][q + 2]);
                        mma16816(accu[mt][nt], al[mt], bu[p][q], bu[p][q + 2]);
                    }
        }
    }

    // epilogue
    const int colq = (lane & 3) * 2;
#pragma unroll
    for (int mt = 0; mt < 2; mt++) {
#pragma unroll
        for (int half = 0; half < 2; half++) {
            const int gm = mb + m0 + mt * 16 + (lane >> 2) + half * 8;
            if (gm >= cnt) continue;
            const size_t orow = ((size_t)(ROUTED ? off + gm : gm)) * I_DIM;
#pragma unroll
            for (int nt = 0; nt < 4; nt++) {
                const float g0 = accg[mt][nt][half * 2 + 0];
                const float g1 = accg[mt][nt][half * 2 + 1];
                const float u0 = accu[mt][nt][half * 2 + 0];
                const float u1 = accu[mt][nt][half * 2 + 1];
                const float v0 = gelu_exact(g0) * u0;
                const float v1 = gelu_exact(g1) * u1;
                uint32_t h, l;
                splitpair(v0, v1, h, l);
                const size_t oc = orow + nb + n0 + nt * 8 + colq;
                *(uint32_t*)(oHi + oc) = h;
                *(uint32_t*)(oLo + oc) = l;
            }
        }
    }
}

// ======================= down GEMM (3-stage pipeline) =======================
#define DN_AH 0u
#define DN_AL 16384u
#define DN_B  32768u

template <bool ROUTED>
__global__ void __launch_bounds__(256) dn_mma_kernel(const hf* __restrict__ AHi,
                                                     const hf* __restrict__ ALo,
                                                     const hf* __restrict__ B,
                                                     float* __restrict__ out,
                                                     hf* __restrict__ dtmp) {
    const int e   = ROUTED ? blockIdx.z : 0;
    const int cnt = ROUTED ? g_cnt[e] : T_TOT;
    const int off = ROUTED ? g_off[e] : 0;
    const int mb  = blockIdx.y * 128;
    if (mb >= cnt) return;
    const int nb  = blockIdx.x * 128;

    extern __shared__ char dsm[];
    const uint32_t sb = smem_u32(dsm);
    const int tid = threadIdx.x;

    const int cx = tid & 7;
    const int rb = tid >> 3;
    const uint32_t so = (uint32_t)rb * 128u + (uint32_t)(((cx ^ (rb & 7))) * 16);
    const size_t wofs = (size_t)e * H_DIM * I_DIM;

    const hf *aHiP[4], *aLoP[4], *bP[4];
#pragma unroll
    for (int j = 0; j < 4; j++) {
        int lr = mb + rb + 32 * j;
        if (lr >= cnt) lr = cnt - 1;
        const size_t arow = (size_t)(off + lr) * I_DIM + cx * 8;
        aHiP[j] = AHi + arow;
        aLoP[j] = ALo + arow;
        const size_t brow = wofs + (size_t)(nb + rb + 32 * j) * I_DIM + cx * 8;
        bP[j] = B + brow;
    }

    const int warp = tid >> 5, lane = tid & 31;
    const int m0 = (warp & 3) * 32;
    const int n0 = (warp >> 2) * 64;
    const int hl = lane >> 4;
    const int l15 = lane & 15;

    uint32_t aRow[2], aXor[2], bRow[4], bXor[4];
#pragma unroll
    for (int mt = 0; mt < 2; mt++) {
        const int r = m0 + mt * 16 + l15;
        aRow[mt] = (uint32_t)r * 128u;
        aXor[mt] = (uint32_t)(r & 7);
    }
#pragma unroll
    for (int p = 0; p < 4; p++) {
        const int r = n0 + p * 16 + l15;
        bRow[p] = (uint32_t)r * 128u;
        bXor[p] = (uint32_t)(r & 7);
    }

    float acc[2][8][4];
#pragma unroll
    for (int mt = 0; mt < 2; mt++)
#pragma unroll
        for (int nt = 0; nt < 8; nt++)
#pragma unroll
            for (int q = 0; q < 4; q++) acc[mt][nt][q] = 0.0f;

    const int NCH = I_DIM / KC;   // 8
#pragma unroll
    for (int pc = 0; pc < 2; pc++) {
        const uint32_t d = sb + (uint32_t)pc * STAGE;
        const int k0 = pc * KC;
#pragma unroll
        for (int j = 0; j < 4; j++) {
            cp16(d + DN_AH + so + j * 4096u, aHiP[j] + k0);
            cp16(d + DN_AL + so + j * 4096u, aLoP[j] + k0);
            cp16(d + DN_B  + so + j * 4096u, bP[j] + k0);
        }
        cp_commit();
    }

    int wst = 2;
    for (int c = 0; c < NCH; c++) {
        cp_wait<1>();
        __syncthreads();
        if (c + 2 < NCH) {
            const uint32_t d = sb + (uint32_t)wst * STAGE;
            const int k0 = (c + 2) * KC;
#pragma unroll
            for (int j = 0; j < 4; j++) {
                cp16(d + DN_AH + so + j * 4096u, aHiP[j] + k0);
                cp16(d + DN_AL + so + j * 4096u, aLoP[j] + k0);
                cp16(d + DN_B  + so + j * 4096u, bP[j] + k0);
            }
        }
        cp_commit();

        const uint32_t st = sb + (uint32_t)((wst + 1) % 3) * STAGE;
        wst = (wst + 1) % 3;
#pragma unroll
        for (int kk = 0; kk < 4; kk++) {
            const uint32_t ku = (uint32_t)(2 * kk + hl);
            uint32_t ah[2][4], al[2][4];
#pragma unroll
            for (int mt = 0; mt < 2; mt++) {
                const uint32_t ao = aRow[mt] + ((ku ^ aXor[mt]) << 4);
                ldsm4(ah[mt], st + DN_AH + ao);
                ldsm4(al[mt], st + DN_AL + ao);
            }
            uint32_t bh[4][4];
#pragma unroll
            for (int p = 0; p < 4; p++) {
                const uint32_t bo = bRow[p] + ((ku ^ bXor[p]) << 4);
                ldsm4(bh[p], st + DN_B + bo);
            }
#pragma unroll
            for (int mt = 0; mt < 2; mt++)
#pragma unroll
                for (int p = 0; p < 4; p++)
#pragma unroll
                    for (int q = 0; q < 2; q++) {
                        const int nt = 2 * p + q;
                        mma16816(acc[mt][nt], ah[mt], bh[p][q], bh[p][q + 2]);
                        mma16816(acc[mt][nt], al[mt], bh[p][q], bh[p][q + 2]);
                    }
        }
    }

    const int colq = (lane & 3) * 2;
#pragma unroll
    for (int mt = 0; mt < 2; mt++) {
#pragma unroll
        for (int half = 0; half < 2; half++) {
            const int gm = mb + m0 + mt * 16 + (lane >> 2) + half * 8;
            if (gm >= cnt) continue;
            if (ROUTED) {
                const float w = g_aw[off + gm];
                hf* op = dtmp + (size_t)(off + gm) * H_DIM + nb + n0 + colq;
#pragma unroll
                for (int nt = 0; nt < 8; nt++) {
                    __half2 v = __floats2half2_rn(w * acc[mt][nt][half * 2 + 0],
                                                  w * acc[mt][nt][half * 2 + 1]);
                    *(__half2*)(op + nt * 8) = v;
                }
            } else {
                float* op = out + (size_t)gm * H_DIM + nb + n0 + colq;
#pragma unroll
                for (int nt = 0; nt < 8; nt++) {
                    float2 v = {acc[mt][nt][half * 2 + 0], acc[mt][nt][half * 2 + 1]};
                    *(float2*)(op + nt * 8) = v;
                }
            }
        }
    }
}

// ======================= combine =======================
__global__ void __launch_bounds__(256) combine_kernel(float* __restrict__ out) {
    const int t = blockIdx.x;
    const int p0 = g_pos[t * 2 + 0];
    const int p1 = g_pos[t * 2 + 1];
    const int c = threadIdx.x * 4;
    const __half2* a2 = (const __half2*)(g_dtmp + (size_t)p0 * H_DIM + c);
    const __half2* b2 = (const __half2*)(g_dtmp + (size_t)p1 * H_DIM + c);
    const float2 a0 = __half22float2(a2[0]), a1 = __half22float2(a2[1]);
    const float2 b0 = __half22float2(b2[0]), b1 = __half22float2(b2[1]);
    float4 o = *(const float4*)(out + (size_t)t * H_DIM + c);
    o.x += a0.x + b0.x;
    o.y += a0.y + b0.y;
    o.z += a1.x + b1.x;
    o.w += a1.y + b1.y;
    *(float4*)(out + (size_t)t * H_DIM + c) = o;
}

// ======================= launch =======================
extern "C" void kernel_launch(void* const* d_in, const int* in_sizes, int n_in,
                              void* d_out, int out_size) {
    const float* X   = (const float*)d_in[0];
    const float* GW  = (const float*)d_in[1];
    const float* Wg  = (const float*)d_in[2];
    const float* Wu  = (const float*)d_in[3];
    const float* Wd  = (const float*)d_in[4];
    const float* sWg = (const float*)d_in[5];
    const float* sWu = (const float*)d_in[6];
    const float* sWd = (const float*)d_in[7];
    float* out = (float*)d_out;

    cudaFuncSetAttribute(gu_mma_kernel<true>,  cudaFuncAttributeMaxDynamicSharedMemorySize, GEMM_SMEM);
    cudaFuncSetAttribute(gu_mma_kernel<false>, cudaFuncAttributeMaxDynamicSharedMemorySize, GEMM_SMEM);
    cudaFuncSetAttribute(dn_mma_kernel<true>,  cudaFuncAttributeMaxDynamicSharedMemorySize, GEMM_SMEM);
    cudaFuncSetAttribute(dn_mma_kernel<false>, cudaFuncAttributeMaxDynamicSharedMemorySize, GEMM_SMEM);

    hf *wgT, *wuT, *wdT, *sgT, *suT, *sdT, *ihi, *ilo, *sihi, *silo, *dtmp;
    cudaGetSymbolAddress((void**)&wgT, g_wgT);
    cudaGetSymbolAddress((void**)&wuT, g_wuT);
    cudaGetSymbolAddress((void**)&wdT, g_wdT);
    cudaGetSymbolAddress((void**)&sgT, g_swgT);
    cudaGetSymbolAddress((void**)&suT, g_swuT);
    cudaGetSymbolAddress((void**)&sdT, g_swdT);
    cudaGetSymbolAddress((void**)&ihi, g_ihi);   cudaGetSymbolAddress((void**)&ilo, g_ilo);
    cudaGetSymbolAddress((void**)&sihi, g_sihi); cudaGetSymbolAddress((void**)&silo, g_silo);
    cudaGetSymbolAddress((void**)&dtmp, g_dtmp);

    // routing
    init_kernel<<<1, 32>>>();
    router_kernel<<<T_TOT / 8, 256>>>(X, GW);
    scan_kernel<<<1, 32>>>();
    scatter_kernel<<<T_TOT / 256, 256>>>();

    // preprocessing
    split_x_kernel<<<(T_TOT * H_DIM) / (256 * 8), 256>>>(X);
    trans_round_kernel<<<dim3(I_DIM / 32, H_DIM / 32, E_NUM), 256>>>(Wg, wgT, H_DIM, I_DIM);
    trans_round_kernel<<<dim3(I_DIM / 32, H_DIM / 32, E_NUM), 256>>>(Wu, wuT, H_DIM, I_DIM);
    trans_round_kernel<<<dim3(H_DIM / 32, I_DIM / 32, E_NUM), 256>>>(Wd, wdT, I_DIM, H_DIM);
    trans_round_kernel<<<dim3(I_DIM / 32, H_DIM / 32, 1), 256>>>(sWg, sgT, H_DIM, I_DIM);
    trans_round_kernel<<<dim3(I_DIM / 32, H_DIM / 32, 1), 256>>>(sWu, suT, H_DIM, I_DIM);
    trans_round_kernel<<<dim3(H_DIM / 32, I_DIM / 32, 1), 256>>>(sWd, sdT, I_DIM, H_DIM);

    // shared expert
    gu_mma_kernel<false><<<dim3(I_DIM / 64, T_TOT / 128, 1), 256, GEMM_SMEM>>>(
        sgT, suT, sihi, silo);
    dn_mma_kernel<false><<<dim3(H_DIM / 128, T_TOT / 128, 1), 256, GEMM_SMEM>>>(
        sihi, silo, sdT, out, dtmp);

    // routed experts
    gu_mma_kernel<true><<<dim3(I_DIM / 64, T_TOT / 128, E_NUM), 256, GEMM_SMEM>>>(
        wgT, wuT, ihi, ilo);
    dn_mma_kernel<true><<<dim3(H_DIM / 128, T_TOT / 128, E_NUM), 256, GEMM_SMEM>>>(
        ihi, ilo, wdT, out, dtmp);
    combine_kernel<<<T_TOT, 256>>>(out);
}

// round 6
// speedup vs baseline: 1.1777x; 1.1777x over previous
#include <cuda_runtime.h>
#include <cuda_fp16.h>
#include <math.h>
#include <stdint.h>

#define T_TOT   16384
#define H_DIM   1024
#define I_DIM   512
#define E_NUM   8
#define TOPK    2
#define NASSIGN (T_TOT * TOPK)
#define KC      64

typedef __half hf;

// ======================= scratch =======================
__device__ int   g_topk_idx[NASSIGN];
__device__ float g_topk_w[NASSIGN];
__device__ int   g_cnt[E_NUM];
__device__ int   g_off[E_NUM];
__device__ int   g_fill[E_NUM];
__device__ int   g_tok[NASSIGN];
__device__ float g_aw[NASSIGN];
__device__ int   g_pos[NASSIGN];

__device__ __align__(16) hf g_xhi[(size_t)T_TOT * H_DIM];
__device__ __align__(16) hf g_xlo[(size_t)T_TOT * H_DIM];
__device__ __align__(16) hf g_wgT[(size_t)E_NUM * I_DIM * H_DIM];
__device__ __align__(16) hf g_wuT[(size_t)E_NUM * I_DIM * H_DIM];
__device__ __align__(16) hf g_wdT[(size_t)E_NUM * H_DIM * I_DIM];
__device__ __align__(16) hf g_swgT[(size_t)I_DIM * H_DIM];
__device__ __align__(16) hf g_swuT[(size_t)I_DIM * H_DIM];
__device__ __align__(16) hf g_swdT[(size_t)H_DIM * I_DIM];
__device__ __align__(16) hf g_ihi[(size_t)NASSIGN * I_DIM];
__device__ __align__(16) hf g_ilo[(size_t)NASSIGN * I_DIM];
__device__ __align__(16) hf g_sihi[(size_t)T_TOT * I_DIM];
__device__ __align__(16) hf g_silo[(size_t)T_TOT * I_DIM];
__device__ __align__(16) hf g_dtmp[(size_t)NASSIGN * H_DIM];   // fp16 (64 MB)

// ======================= helpers =======================
__device__ __forceinline__ uint32_t smem_u32(const void* p) {
    uint32_t a;
    asm("{ .reg .u64 t; cvta.to.shared.u64 t, %1; cvt.u32.u64 %0, t; }" : "=r"(a) : "l"(p));
    return a;
}
__device__ __forceinline__ void cp16(uint32_t dst, const void* src) {
    asm volatile("cp.async.cg.shared.global [%0], [%1], 16;" :: "r"(dst), "l"(src));
}
__device__ __forceinline__ void cp_commit() { asm volatile("cp.async.commit_group;" ::: "memory"); }
template <int N>
__device__ __forceinline__ void cp_wait() { asm volatile("cp.async.wait_group %0;" :: "n"(N) : "memory"); }

__device__ __forceinline__ void ldsm4(uint32_t* r, uint32_t addr) {
    asm volatile("ldmatrix.sync.aligned.m8n8.x4.shared.b16 {%0,%1,%2,%3}, [%4];"
                 : "=r"(r[0]), "=r"(r[1]), "=r"(r[2]), "=r"(r[3]) : "r"(addr));
}
__device__ __forceinline__ void mma16816(float* d, const uint32_t* a, uint32_t b0, uint32_t b1) {
    asm volatile("mma.sync.aligned.m16n8k16.row.col.f32.f16.f16.f32 "
                 "{%0,%1,%2,%3}, {%4,%5,%6,%7}, {%8,%9}, {%0,%1,%2,%3};"
                 : "+f"(d[0]), "+f"(d[1]), "+f"(d[2]), "+f"(d[3])
                 : "r"(a[0]), "r"(a[1]), "r"(a[2]), "r"(a[3]), "r"(b0), "r"(b1));
}
__device__ __forceinline__ float gelu_exact(float x) {
    return 0.5f * x * (1.0f + erff(x * 0.70710678118654752f));
}
__device__ __forceinline__ void splitpair(float v0, float v1, uint32_t& h, uint32_t& l) {
    __half2 ph = __floats2half2_rn(v0, v1);
    float r0 = v0 - __low2float(ph);
    float r1 = v1 - __high2float(ph);
    __half2 pl = __floats2half2_rn(r0, r1);
    h = *reinterpret_cast<uint32_t*>(&ph);
    l = *reinterpret_cast<uint32_t*>(&pl);
}

// ======================= routing =======================
__global__ void init_kernel() {
    if (threadIdx.x < E_NUM) g_cnt[threadIdx.x] = 0;
}

__global__ void __launch_bounds__(256) router_kernel(const float* __restrict__ X,
                                                     const float* __restrict__ GW) {
    __shared__ float sgw[E_NUM * H_DIM];
    for (int i = threadIdx.x; i < E_NUM * H_DIM; i += 256) sgw[i] = GW[i];
    __syncthreads();
    const int warp = threadIdx.x >> 5, lane = threadIdx.x & 31;
    const int t = blockIdx.x * 8 + warp;
    if (t >= T_TOT) return;
    const float* x = X + (size_t)t * H_DIM;
    float acc[E_NUM];
#pragma unroll
    for (int e = 0; e < E_NUM; e++) acc[e] = 0.0f;
    for (int h = lane; h < H_DIM; h += 32) {
        const float xv = x[h];
#pragma unroll
        for (int e = 0; e < E_NUM; e++) acc[e] = fmaf(xv, sgw[e * H_DIM + h], acc[e]);
    }
#pragma unroll
    for (int e = 0; e < E_NUM; e++)
#pragma unroll
        for (int o = 16; o > 0; o >>= 1) acc[e] += __shfl_down_sync(0xffffffffu, acc[e], o);
    if (lane == 0) {
        float l0 = -1e30f, l1 = -1e30f;
        int i0 = 0, i1 = 0;
#pragma unroll
        for (int e = 0; e < E_NUM; e++) {
            const float v = acc[e];
            if (v > l0)      { l1 = l0; i1 = i0; l0 = v; i0 = e; }
            else if (v > l1) { l1 = v; i1 = e; }
        }
        const float w1 = expf(l1 - l0);
        const float inv = 1.0f / (1.0f + w1);
        g_topk_idx[t * 2 + 0] = i0;
        g_topk_idx[t * 2 + 1] = i1;
        g_topk_w[t * 2 + 0] = inv;
        g_topk_w[t * 2 + 1] = w1 * inv;
        atomicAdd(&g_cnt[i0], 1);
        atomicAdd(&g_cnt[i1], 1);
    }
}

__global__ void scan_kernel() {
    if (threadIdx.x == 0) {
        int s = 0;
        for (int e = 0; e < E_NUM; e++) { g_off[e] = s; g_fill[e] = s; s += g_cnt[e]; }
    }
}

__global__ void __launch_bounds__(256) scatter_kernel() {
    const int t = blockIdx.x * 256 + threadIdx.x;
    if (t >= T_TOT) return;
#pragma unroll
    for (int k = 0; k < TOPK; k++) {
        const int e = g_topk_idx[t * 2 + k];
        const float w = g_topk_w[t * 2 + k];
        const int p = atomicAdd(&g_fill[e], 1);
        g_tok[p] = t;
        g_aw[p] = w;
        g_pos[t * 2 + k] = p;
    }
}

// ======================= preprocessing =======================
__global__ void __launch_bounds__(256) split_x_kernel(const float* __restrict__ X) {
    const size_t i = ((size_t)blockIdx.x * 256 + threadIdx.x) * 8;
    const float4 a = *(const float4*)(X + i);
    const float4 b = *(const float4*)(X + i + 4);
    uint32_t h0, l0, h1, l1, h2, l2, h3, l3;
    splitpair(a.x, a.y, h0, l0);
    splitpair(a.z, a.w, h1, l1);
    splitpair(b.x, b.y, h2, l2);
    splitpair(b.z, b.w, h3, l3);
    uint4 H = {h0, h1, h2, h3}, L = {l0, l1, l2, l3};
    *(uint4*)(g_xhi + i) = H;
    *(uint4*)(g_xlo + i) = L;
}

__global__ void __launch_bounds__(256) trans_round_kernel(const float* __restrict__ src,
                                                          hf* __restrict__ dst,
                                                          int R, int C) {
    __shared__ float t[32][33];
    const size_t sb = (size_t)blockIdx.z * R * C;
    const int c0 = blockIdx.x * 32, r0 = blockIdx.y * 32;
    const int tx = threadIdx.x & 31, ty = threadIdx.x >> 5;
#pragma unroll
    for (int j = 0; j < 32; j += 8)
        t[ty + j][tx] = src[sb + (size_t)(r0 + ty + j) * C + c0 + tx];
    __syncthreads();
#pragma unroll
    for (int j = 0; j < 32; j += 8) {
        dst[sb + (size_t)(c0 + ty + j) * R + r0 + tx] = __float2half_rn(t[tx][ty + j]);
    }
}

// ======================= gate+up GEMM (2-stage, 96KB, 2 CTA/SM) =======================
#define GU_AH  0u
#define GU_AL  16384u
#define GU_BG  32768u
#define GU_BU  40960u
#define STAGE  49152u
#define GEMM_SMEM (2 * 49152)

template <bool ROUTED>
__global__ void __launch_bounds__(256) gu_mma_kernel(const hf* __restrict__ Bg,
                                                     const hf* __restrict__ Bu,
                                                     hf* __restrict__ oHi,
                                                     hf* __restrict__ oLo) {
    const int e   = ROUTED ? blockIdx.z : 0;
    const int cnt = ROUTED ? g_cnt[e] : T_TOT;
    const int off = ROUTED ? g_off[e] : 0;
    const int mb  = blockIdx.y * 128;
    if (mb >= cnt) return;
    const int nb  = blockIdx.x * 64;

    extern __shared__ char dsm[];
    __shared__ int stok[128];
    const uint32_t sb = smem_u32(dsm);

    const int tid = threadIdx.x;
    if (tid < 128) {
        int r = mb + tid;
        if (r >= cnt) r = cnt - 1;
        stok[tid] = ROUTED ? g_tok[off + r] : r;
    }
    __syncthreads();

    const int cx = tid & 7;
    const int rb = tid >> 3;
    const uint32_t so = (uint32_t)rb * 128u + (uint32_t)(((cx ^ (rb & 7))) * 16);
    const size_t wofs = (size_t)e * I_DIM * H_DIM;

    const hf *aHiP[4], *aLoP[4], *bgP[2], *buP[2];
#pragma unroll
    for (int j = 0; j < 4; j++) {
        const size_t arow = (size_t)stok[rb + 32 * j] * H_DIM + cx * 8;
        aHiP[j] = g_xhi + arow;
        aLoP[j] = g_xlo + arow;
    }
#pragma unroll
    for (int j = 0; j < 2; j++) {
        const size_t brow = wofs + (size_t)(nb + rb + 32 * j) * H_DIM + cx * 8;
        bgP[j] = Bg + brow;
        buP[j] = Bu + brow;
    }

    const int warp = tid >> 5, lane = tid & 31;
    const int m0 = (warp & 3) * 32;
    const int n0 = (warp >> 2) * 32;
    const int hl = lane >> 4;
    const int l15 = lane & 15;

    uint32_t aRow[2], aXor[2], bRow[2], bXor[2];
#pragma unroll
    for (int mt = 0; mt < 2; mt++) {
        const int r = m0 + mt * 16 + l15;
        aRow[mt] = (uint32_t)r * 128u;
        aXor[mt] = (uint32_t)(r & 7);
    }
#pragma unroll
    for (int p = 0; p < 2; p++) {
        const int r = n0 + p * 16 + l15;
        bRow[p] = (uint32_t)r * 128u;
        bXor[p] = (uint32_t)(r & 7);
    }

    float accg[2][4][4], accu[2][4][4];
#pragma unroll
    for (int mt = 0; mt < 2; mt++)
#pragma unroll
        for (int nt = 0; nt < 4; nt++)
#pragma unroll
            for (int q = 0; q < 4; q++) { accg[mt][nt][q] = 0.0f; accu[mt][nt][q] = 0.0f; }

    const int NCH = H_DIM / KC;   // 16
    {
        const uint32_t d = sb;
#pragma unroll
        for (int j = 0; j < 4; j++) {
            cp16(d + GU_AH + so + j * 4096u, aHiP[j]);
            cp16(d + GU_AL + so + j * 4096u, aLoP[j]);
        }
#pragma unroll
        for (int j = 0; j < 2; j++) {
            cp16(d + GU_BG + so + j * 4096u, bgP[j]);
            cp16(d + GU_BU + so + j * 4096u, buP[j]);
        }
        cp_commit();
    }

    for (int c = 0; c < NCH; c++) {
        if (c + 1 < NCH) {
            const uint32_t d = sb + ((c + 1) & 1) * STAGE;
            const int k0 = (c + 1) * KC;
#pragma unroll
            for (int j = 0; j < 4; j++) {
                cp16(d + GU_AH + so + j * 4096u, aHiP[j] + k0);
                cp16(d + GU_AL + so + j * 4096u, aLoP[j] + k0);
            }
#pragma unroll
            for (int j = 0; j < 2; j++) {
                cp16(d + GU_BG + so + j * 4096u, bgP[j] + k0);
                cp16(d + GU_BU + so + j * 4096u, buP[j] + k0);
            }
            cp_commit();
            cp_wait<1>();
        } else {
            cp_wait<0>();
        }
        __syncthreads();

        const uint32_t st = sb + (c & 1) * STAGE;
#pragma unroll
        for (int kk = 0; kk < 4; kk++) {
            const uint32_t ku = (uint32_t)(2 * kk + hl);
            uint32_t ah[2][4], al[2][4];
#pragma unroll
            for (int mt = 0; mt < 2; mt++) {
                const uint32_t ao = aRow[mt] + ((ku ^ aXor[mt]) << 4);
                ldsm4(ah[mt], st + GU_AH + ao);
                ldsm4(al[mt], st + GU_AL + ao);
            }
            uint32_t bg[2][4], bu[2][4];
#pragma unroll
            for (int p = 0; p < 2; p++) {
                const uint32_t bo = bRow[p] + ((ku ^ bXor[p]) << 4);
                ldsm4(bg[p], st + GU_BG + bo);
                ldsm4(bu[p], st + GU_BU + bo);
            }
#pragma unroll
            for (int mt = 0; mt < 2; mt++)
#pragma unroll
                for (int p = 0; p < 2; p++)
#pragma unroll
                    for (int q = 0; q < 2; q++) {
                        const int nt = 2 * p + q;
                        mma16816(accg[mt][nt], ah[mt], bg[p][q], bg[p][q + 2]);
                        mma16816(accg[mt][nt], al[mt], bg[p][q], bg[p][q + 2]);
                        mma16816(accu[mt][nt], ah[mt], bu[p][q], bu[p][q + 2]);
                        mma16816(accu[mt][nt], al[mt], bu[p][q], bu[p][q + 2]);
                    }
        }
        __syncthreads();
    }

    // epilogue: inter = gelu(g)*u, split fp16 hi/lo
    const int colq = (lane & 3) * 2;
#pragma unroll
    for (int mt = 0; mt < 2; mt++) {
#pragma unroll
        for (int half = 0; half < 2; half++) {
            const int gm = mb + m0 + mt * 16 + (lane >> 2) + half * 8;
            if (gm >= cnt) continue;
            const size_t orow = ((size_t)(ROUTED ? off + gm : gm)) * I_DIM;
#pragma unroll
            for (int nt = 0; nt < 4; nt++) {
                const float g0 = accg[mt][nt][half * 2 + 0];
                const float g1 = accg[mt][nt][half * 2 + 1];
                const float u0 = accu[mt][nt][half * 2 + 0];
                const float u1 = accu[mt][nt][half * 2 + 1];
                const float v0 = gelu_exact(g0) * u0;
                const float v1 = gelu_exact(g1) * u1;
                uint32_t h, l;
                splitpair(v0, v1, h, l);
                const size_t oc = orow + nb + n0 + nt * 8 + colq;
                *(uint32_t*)(oHi + oc) = h;
                *(uint32_t*)(oLo + oc) = l;
            }
        }
    }
}

// ======================= down GEMM (2-stage, 96KB) =======================
#define DN_AH 0u
#define DN_AL 16384u
#define DN_B  32768u

template <bool ROUTED>
__global__ void __launch_bounds__(256) dn_mma_kernel(const hf* __restrict__ AHi,
                                                     const hf* __restrict__ ALo,
                                                     const hf* __restrict__ B,
                                                     float* __restrict__ out,
                                                     hf* __restrict__ dtmp) {
    const int e   = ROUTED ? blockIdx.z : 0;
    const int cnt = ROUTED ? g_cnt[e] : T_TOT;
    const int off = ROUTED ? g_off[e] : 0;
    const int mb  = blockIdx.y * 128;
    if (mb >= cnt) return;
    const int nb  = blockIdx.x * 128;

    extern __shared__ char dsm[];
    const uint32_t sb = smem_u32(dsm);
    const int tid = threadIdx.x;

    const int cx = tid & 7;
    const int rb = tid >> 3;
    const uint32_t so = (uint32_t)rb * 128u + (uint32_t)(((cx ^ (rb & 7))) * 16);
    const size_t wofs = (size_t)e * H_DIM * I_DIM;

    const hf *aHiP[4], *aLoP[4], *bP[4];
#pragma unroll
    for (int j = 0; j < 4; j++) {
        int lr = mb + rb + 32 * j;
        if (lr >= cnt) lr = cnt - 1;
        const size_t arow = (size_t)(off + lr) * I_DIM + cx * 8;
        aHiP[j] = AHi + arow;
        aLoP[j] = ALo + arow;
        const size_t brow = wofs + (size_t)(nb + rb + 32 * j) * I_DIM + cx * 8;
        bP[j] = B + brow;
    }

    const int warp = tid >> 5, lane = tid & 31;
    const int m0 = (warp & 3) * 32;
    const int n0 = (warp >> 2) * 64;
    const int hl = lane >> 4;
    const int l15 = lane & 15;

    uint32_t aRow[2], aXor[2], bRow[4], bXor[4];
#pragma unroll
    for (int mt = 0; mt < 2; mt++) {
        const int r = m0 + mt * 16 + l15;
        aRow[mt] = (uint32_t)r * 128u;
        aXor[mt] = (uint32_t)(r & 7);
    }
#pragma unroll
    for (int p = 0; p < 4; p++) {
        const int r = n0 + p * 16 + l15;
        bRow[p] = (uint32_t)r * 128u;
        bXor[p] = (uint32_t)(r & 7);
    }

    float acc[2][8][4];
#pragma unroll
    for (int mt = 0; mt < 2; mt++)
#pragma unroll
        for (int nt = 0; nt < 8; nt++)
#pragma unroll
            for (int q = 0; q < 4; q++) acc[mt][nt][q] = 0.0f;

    const int NCH = I_DIM / KC;   // 8
    {
        const uint32_t d = sb;
#pragma unroll
        for (int j = 0; j < 4; j++) {
            cp16(d + DN_AH + so + j * 4096u, aHiP[j]);
            cp16(d + DN_AL + so + j * 4096u, aLoP[j]);
            cp16(d + DN_B  + so + j * 4096u, bP[j]);
        }
        cp_commit();
    }

    for (int c = 0; c < NCH; c++) {
        if (c + 1 < NCH) {
            const uint32_t d = sb + ((c + 1) & 1) * STAGE;
            const int k0 = (c + 1) * KC;
#pragma unroll
            for (int j = 0; j < 4; j++) {
                cp16(d + DN_AH + so + j * 4096u, aHiP[j] + k0);
                cp16(d + DN_AL + so + j * 4096u, aLoP[j] + k0);
                cp16(d + DN_B  + so + j * 4096u, bP[j] + k0);
            }
            cp_commit();
            cp_wait<1>();
        } else {
            cp_wait<0>();
        }
        __syncthreads();

        const uint32_t st = sb + (c & 1) * STAGE;
#pragma unroll
        for (int kk = 0; kk < 4; kk++) {
            const uint32_t ku = (uint32_t)(2 * kk + hl);
            uint32_t ah[2][4], al[2][4];
#pragma unroll
            for (int mt = 0; mt < 2; mt++) {
                const uint32_t ao = aRow[mt] + ((ku ^ aXor[mt]) << 4);
                ldsm4(ah[mt], st + DN_AH + ao);
                ldsm4(al[mt], st + DN_AL + ao);
            }
            uint32_t bh[4][4];
#pragma unroll
            for (int p = 0; p < 4; p++) {
                const uint32_t bo = bRow[p] + ((ku ^ bXor[p]) << 4);
                ldsm4(bh[p], st + DN_B + bo);
            }
#pragma unroll
            for (int mt = 0; mt < 2; mt++)
#pragma unroll
                for (int p = 0; p < 4; p++)
#pragma unroll
                    for (int q = 0; q < 2; q++) {
                        const int nt = 2 * p + q;
                        mma16816(acc[mt][nt], ah[mt], bh[p][q], bh[p][q + 2]);
                        mma16816(acc[mt][nt], al[mt], bh[p][q], bh[p][q + 2]);
                    }
        }
        __syncthreads();
    }

    const int colq = (lane & 3) * 2;
#pragma unroll
    for (int mt = 0; mt < 2; mt++) {
#pragma unroll
        for (int half = 0; half < 2; half++) {
            const int gm = mb + m0 + mt * 16 + (lane >> 2) + half * 8;
            if (gm >= cnt) continue;
            if (ROUTED) {
                const float w = g_aw[off + gm];
                hf* op = dtmp + (size_t)(off + gm) * H_DIM + nb + n0 + colq;
#pragma unroll
                for (int nt = 0; nt < 8; nt++) {
                    __half2 v = __floats2half2_rn(w * acc[mt][nt][half * 2 + 0],
                                                  w * acc[mt][nt][half * 2 + 1]);
                    *(__half2*)(op + nt * 8) = v;
                }
            } else {
                float* op = out + (size_t)gm * H_DIM + nb + n0 + colq;
#pragma unroll
                for (int nt = 0; nt < 8; nt++) {
                    float2 v = {acc[mt][nt][half * 2 + 0], acc[mt][nt][half * 2 + 1]};
                    *(float2*)(op + nt * 8) = v;
                }
            }
        }
    }
}

// ======================= combine =======================
__global__ void __launch_bounds__(256) combine_kernel(float* __restrict__ out) {
    const int t = blockIdx.x;
    const int p0 = g_pos[t * 2 + 0];
    const int p1 = g_pos[t * 2 + 1];
    const int c = threadIdx.x * 4;
    const __half2* a2 = (const __half2*)(g_dtmp + (size_t)p0 * H_DIM + c);
    const __half2* b2 = (const __half2*)(g_dtmp + (size_t)p1 * H_DIM + c);
    const float2 a0 = __half22float2(a2[0]), a1 = __half22float2(a2[1]);
    const float2 b0 = __half22float2(b2[0]), b1 = __half22float2(b2[1]);
    float4 o = *(const float4*)(out + (size_t)t * H_DIM + c);
    o.x += a0.x + b0.x;
    o.y += a0.y + b0.y;
    o.z += a1.x + b1.x;
    o.w += a1.y + b1.y;
    *(float4*)(out + (size_t)t * H_DIM + c) = o;
}

// ======================= launch =======================
extern "C" void kernel_launch(void* const* d_in, const int* in_sizes, int n_in,
                              void* d_out, int out_size) {
    const float* X   = (const float*)d_in[0];
    const float* GW  = (const float*)d_in[1];
    const float* Wg  = (const float*)d_in[2];
    const float* Wu  = (const float*)d_in[3];
    const float* Wd  = (const float*)d_in[4];
    const float* sWg = (const float*)d_in[5];
    const float* sWu = (const float*)d_in[6];
    const float* sWd = (const float*)d_in[7];
    float* out = (float*)d_out;

    cudaFuncSetAttribute(gu_mma_kernel<true>,  cudaFuncAttributeMaxDynamicSharedMemorySize, GEMM_SMEM);
    cudaFuncSetAttribute(gu_mma_kernel<false>, cudaFuncAttributeMaxDynamicSharedMemorySize, GEMM_SMEM);
    cudaFuncSetAttribute(dn_mma_kernel<true>,  cudaFuncAttributeMaxDynamicSharedMemorySize, GEMM_SMEM);
    cudaFuncSetAttribute(dn_mma_kernel<false>, cudaFuncAttributeMaxDynamicSharedMemorySize, GEMM_SMEM);

    hf *wgT, *wuT, *wdT, *sgT, *suT, *sdT, *ihi, *ilo, *sihi, *silo, *dtmp;
    cudaGetSymbolAddress((void**)&wgT, g_wgT);
    cudaGetSymbolAddress((void**)&wuT, g_wuT);
    cudaGetSymbolAddress((void**)&wdT, g_wdT);
    cudaGetSymbolAddress((void**)&sgT, g_swgT);
    cudaGetSymbolAddress((void**)&suT, g_swuT);
    cudaGetSymbolAddress((void**)&sdT, g_swdT);
    cudaGetSymbolAddress((void**)&ihi, g_ihi);   cudaGetSymbolAddress((void**)&ilo, g_ilo);
    cudaGetSymbolAddress((void**)&sihi, g_sihi); cudaGetSymbolAddress((void**)&silo, g_silo);
    cudaGetSymbolAddress((void**)&dtmp, g_dtmp);

    // routing
    init_kernel<<<1, 32>>>();
    router_kernel<<<T_TOT / 8, 256>>>(X, GW);
    scan_kernel<<<1, 32>>>();
    scatter_kernel<<<T_TOT / 256, 256>>>();

    // preprocessing
    split_x_kernel<<<(T_TOT * H_DIM) / (256 * 8), 256>>>(X);
    trans_round_kernel<<<dim3(I_DIM / 32, H_DIM / 32, E_NUM), 256>>>(Wg, wgT, H_DIM, I_DIM);
    trans_round_kernel<<<dim3(I_DIM / 32, H_DIM / 32, E_NUM), 256>>>(Wu, wuT, H_DIM, I_DIM);
    trans_round_kernel<<<dim3(H_DIM / 32, I_DIM / 32, E_NUM), 256>>>(Wd, wdT, I_DIM, H_DIM);
    trans_round_kernel<<<dim3(I_DIM / 32, H_DIM / 32, 1), 256>>>(sWg, sgT, H_DIM, I_DIM);
    trans_round_kernel<<<dim3(I_DIM / 32, H_DIM / 32, 1), 256>>>(sWu, suT, H_DIM, I_DIM);
    trans_round_kernel<<<dim3(H_DIM / 32, I_DIM / 32, 1), 256>>>(sWd, sdT, I_DIM, H_DIM);

    // shared expert
    gu_mma_kernel<false><<<dim3(I_DIM / 64, T_TOT / 128, 1), 256, GEMM_SMEM>>>(
        sgT, suT, sihi, silo);
    dn_mma_kernel<false><<<dim3(H_DIM / 128, T_TOT / 128, 1), 256, GEMM_SMEM>>>(
        sihi, silo, sdT, out, dtmp);

    // routed experts
    gu_mma_kernel<true><<<dim3(I_DIM / 64, T_TOT / 128, E_NUM), 256, GEMM_SMEM>>>(
        wgT, wuT, ihi, ilo);
    dn_mma_kernel<true><<<dim3(H_DIM / 128, T_TOT / 128, E_NUM), 256, GEMM_SMEM>>>(
        ihi, ilo, wdT, out, dtmp);
    combine_kernel<<<T_TOT, 256>>>(out);
}

// round 7
// speedup vs baseline: 1.5982x; 1.3571x over previous
#include <cuda_runtime.h>
#include <cuda_fp16.h>
#include <math.h>
#include <stdint.h>

#define T_TOT   16384
#define H_DIM   1024
#define I_DIM   512
#define E_NUM   8
#define TOPK    2
#define NASSIGN (T_TOT * TOPK)
#define NROWS   (NASSIGN + T_TOT)     // routed assignments + shared-expert rows
#define KC      64

typedef __half hf;

// ======================= scratch =======================
__device__ int   g_topk_idx[NASSIGN];
__device__ float g_topk_w[NASSIGN];
__device__ int   g_cnt[E_NUM];
__device__ int   g_off[E_NUM];
__device__ int   g_fill[E_NUM];
__device__ int   g_tok[NASSIGN];
__device__ float g_aw[NASSIGN];
__device__ int   g_pos[NASSIGN];

__device__ __align__(16) hf g_xhi[(size_t)T_TOT * H_DIM];          // fp16(x)
__device__ __align__(16) hf g_wgT[(size_t)E_NUM * I_DIM * H_DIM];
__device__ __align__(16) hf g_wuT[(size_t)E_NUM * I_DIM * H_DIM];
__device__ __align__(16) hf g_wdT[(size_t)E_NUM * H_DIM * I_DIM];
__device__ __align__(16) hf g_swgT[(size_t)I_DIM * H_DIM];
__device__ __align__(16) hf g_swuT[(size_t)I_DIM * H_DIM];
__device__ __align__(16) hf g_swdT[(size_t)H_DIM * I_DIM];
__device__ __align__(16) hf g_ihi[(size_t)NROWS * I_DIM];          // inter hi (routed + shared)
__device__ __align__(16) hf g_ilo[(size_t)NROWS * I_DIM];          // inter lo
__device__ __align__(16) hf g_dtmp[(size_t)NASSIGN * H_DIM];       // routed down outputs (fp16)

// ======================= helpers =======================
__device__ __forceinline__ uint32_t smem_u32(const void* p) {
    uint32_t a;
    asm("{ .reg .u64 t; cvta.to.shared.u64 t, %1; cvt.u32.u64 %0, t; }" : "=r"(a) : "l"(p));
    return a;
}
__device__ __forceinline__ void cp16(uint32_t dst, const void* src) {
    asm volatile("cp.async.cg.shared.global [%0], [%1], 16;" :: "r"(dst), "l"(src));
}
__device__ __forceinline__ void cp_commit() { asm volatile("cp.async.commit_group;" ::: "memory"); }
template <int N>
__device__ __forceinline__ void cp_wait() { asm volatile("cp.async.wait_group %0;" :: "n"(N) : "memory"); }

__device__ __forceinline__ void ldsm4(uint32_t* r, uint32_t addr) {
    asm volatile("ldmatrix.sync.aligned.m8n8.x4.shared.b16 {%0,%1,%2,%3}, [%4];"
                 : "=r"(r[0]), "=r"(r[1]), "=r"(r[2]), "=r"(r[3]) : "r"(addr));
}
__device__ __forceinline__ void mma16816(float* d, const uint32_t* a, uint32_t b0, uint32_t b1) {
    asm volatile("mma.sync.aligned.m16n8k16.row.col.f32.f16.f16.f32 "
                 "{%0,%1,%2,%3}, {%4,%5,%6,%7}, {%8,%9}, {%0,%1,%2,%3};"
                 : "+f"(d[0]), "+f"(d[1]), "+f"(d[2]), "+f"(d[3])
                 : "r"(a[0]), "r"(a[1]), "r"(a[2]), "r"(a[3]), "r"(b0), "r"(b1));
}
__device__ __forceinline__ float gelu_exact(float x) {
    return 0.5f * x * (1.0f + erff(x * 0.70710678118654752f));
}
__device__ __forceinline__ void splitpair(float v0, float v1, uint32_t& h, uint32_t& l) {
    __half2 ph = __floats2half2_rn(v0, v1);
    float r0 = v0 - __low2float(ph);
    float r1 = v1 - __high2float(ph);
    __half2 pl = __floats2half2_rn(r0, r1);
    h = *reinterpret_cast<uint32_t*>(&ph);
    l = *reinterpret_cast<uint32_t*>(&pl);
}

// ======================= routing =======================
__global__ void init_kernel() {
    if (threadIdx.x < E_NUM) g_cnt[threadIdx.x] = 0;
}

__global__ void __launch_bounds__(256) router_kernel(const float* __restrict__ X,
                                                     const float* __restrict__ GW) {
    __shared__ float sgw[E_NUM * H_DIM];
    for (int i = threadIdx.x; i < E_NUM * H_DIM; i += 256) sgw[i] = GW[i];
    __syncthreads();
    const int warp = threadIdx.x >> 5, lane = threadIdx.x & 31;
    const int t = blockIdx.x * 8 + warp;
    if (t >= T_TOT) return;
    const float* x = X + (size_t)t * H_DIM;
    float acc[E_NUM];
#pragma unroll
    for (int e = 0; e < E_NUM; e++) acc[e] = 0.0f;
    for (int h = lane; h < H_DIM; h += 32) {
        const float xv = x[h];
#pragma unroll
        for (int e = 0; e < E_NUM; e++) acc[e] = fmaf(xv, sgw[e * H_DIM + h], acc[e]);
    }
#pragma unroll
    for (int e = 0; e < E_NUM; e++)
#pragma unroll
        for (int o = 16; o > 0; o >>= 1) acc[e] += __shfl_down_sync(0xffffffffu, acc[e], o);
    if (lane == 0) {
        float l0 = -1e30f, l1 = -1e30f;
        int i0 = 0, i1 = 0;
#pragma unroll
        for (int e = 0; e < E_NUM; e++) {
            const float v = acc[e];
            if (v > l0)      { l1 = l0; i1 = i0; l0 = v; i0 = e; }
            else if (v > l1) { l1 = v; i1 = e; }
        }
        const float w1 = expf(l1 - l0);
        const float inv = 1.0f / (1.0f + w1);
        g_topk_idx[t * 2 + 0] = i0;
        g_topk_idx[t * 2 + 1] = i1;
        g_topk_w[t * 2 + 0] = inv;
        g_topk_w[t * 2 + 1] = w1 * inv;
        atomicAdd(&g_cnt[i0], 1);
        atomicAdd(&g_cnt[i1], 1);
    }
}

__global__ void scan_kernel() {
    if (threadIdx.x == 0) {
        int s = 0;
        for (int e = 0; e < E_NUM; e++) { g_off[e] = s; g_fill[e] = s; s += g_cnt[e]; }
    }
}

__global__ void __launch_bounds__(256) scatter_kernel() {
    const int t = blockIdx.x * 256 + threadIdx.x;
    if (t >= T_TOT) return;
#pragma unroll
    for (int k = 0; k < TOPK; k++) {
        const int e = g_topk_idx[t * 2 + k];
        const float w = g_topk_w[t * 2 + k];
        const int p = atomicAdd(&g_fill[e], 1);
        g_tok[p] = t;
        g_aw[p] = w;
        g_pos[t * 2 + k] = p;
    }
}

// ======================= preprocessing =======================
__global__ void __launch_bounds__(256) round_x_kernel(const float* __restrict__ X) {
    const size_t i = ((size_t)blockIdx.x * 256 + threadIdx.x) * 8;
    const float4 a = *(const float4*)(X + i);
    const float4 b = *(const float4*)(X + i + 4);
    __half2 h0 = __floats2half2_rn(a.x, a.y);
    __half2 h1 = __floats2half2_rn(a.z, a.w);
    __half2 h2 = __floats2half2_rn(b.x, b.y);
    __half2 h3 = __floats2half2_rn(b.z, b.w);
    uint4 H = {*(uint32_t*)&h0, *(uint32_t*)&h1, *(uint32_t*)&h2, *(uint32_t*)&h3};
    *(uint4*)(g_xhi + i) = H;
}

__global__ void __launch_bounds__(256) trans_round_kernel(const float* __restrict__ src,
                                                          hf* __restrict__ dst,
                                                          int R, int C) {
    __shared__ float t[32][33];
    const size_t sb = (size_t)blockIdx.z * R * C;
    const int c0 = blockIdx.x * 32, r0 = blockIdx.y * 32;
    const int tx = threadIdx.x & 31, ty = threadIdx.x >> 5;
#pragma unroll
    for (int j = 0; j < 32; j += 8)
        t[ty + j][tx] = src[sb + (size_t)(r0 + ty + j) * C + c0 + tx];
    __syncthreads();
#pragma unroll
    for (int j = 0; j < 32; j += 8) {
        dst[sb + (size_t)(c0 + ty + j) * R + r0 + tx] = __float2half_rn(t[tx][ty + j]);
    }
}

// ======================= gate+up GEMM (fp16 A, z=0..7 routed, z=8 shared) =======================
#define GU_AH  0u
#define GU_BG  16384u
#define GU_BU  24576u
#define GU_STAGE 32768u
#define GU_SMEM  (2 * 32768)

__global__ void __launch_bounds__(256) gu_mma_kernel(const hf* __restrict__ Wg_all,
                                                     const hf* __restrict__ Wu_all,
                                                     const hf* __restrict__ sWg,
                                                     const hf* __restrict__ sWu,
                                                     hf* __restrict__ oHi,
                                                     hf* __restrict__ oLo) {
    const int e      = blockIdx.z;
    const bool SHARED = (e == E_NUM);
    const int cnt = SHARED ? T_TOT : g_cnt[e];
    const int off = SHARED ? NASSIGN : g_off[e];
    const int mb  = blockIdx.y * 128;
    if (mb >= cnt) return;
    const int nb  = blockIdx.x * 64;

    extern __shared__ char dsm[];
    __shared__ int stok[128];
    const uint32_t sb = smem_u32(dsm);

    const int tid = threadIdx.x;
    if (tid < 128) {
        int r = mb + tid;
        if (r >= cnt) r = cnt - 1;
        stok[tid] = SHARED ? r : g_tok[off + r];
    }
    __syncthreads();

    const int cx = tid & 7;
    const int rb = tid >> 3;
    const uint32_t so = (uint32_t)rb * 128u + (uint32_t)(((cx ^ (rb & 7))) * 16);
    const hf* Bg = SHARED ? sWg : Wg_all + (size_t)e * I_DIM * H_DIM;
    const hf* Bu = SHARED ? sWu : Wu_all + (size_t)e * I_DIM * H_DIM;

    const hf *aP[4], *bgP[2], *buP[2];
#pragma unroll
    for (int j = 0; j < 4; j++)
        aP[j] = g_xhi + (size_t)stok[rb + 32 * j] * H_DIM + cx * 8;
#pragma unroll
    for (int j = 0; j < 2; j++) {
        const size_t brow = (size_t)(nb + rb + 32 * j) * H_DIM + cx * 8;
        bgP[j] = Bg + brow;
        buP[j] = Bu + brow;
    }

    const int warp = tid >> 5, lane = tid & 31;
    const int m0 = (warp & 3) * 32;
    const int n0 = (warp >> 2) * 32;
    const int hl = lane >> 4;
    const int l15 = lane & 15;

    uint32_t aRow[2], aXor[2], bRow[2], bXor[2];
#pragma unroll
    for (int mt = 0; mt < 2; mt++) {
        const int r = m0 + mt * 16 + l15;
        aRow[mt] = (uint32_t)r * 128u;
        aXor[mt] = (uint32_t)(r & 7);
    }
#pragma unroll
    for (int p = 0; p < 2; p++) {
        const int r = n0 + p * 16 + l15;
        bRow[p] = (uint32_t)r * 128u;
        bXor[p] = (uint32_t)(r & 7);
    }

    float accg[2][4][4], accu[2][4][4];
#pragma unroll
    for (int mt = 0; mt < 2; mt++)
#pragma unroll
        for (int nt = 0; nt < 4; nt++)
#pragma unroll
            for (int q = 0; q < 4; q++) { accg[mt][nt][q] = 0.0f; accu[mt][nt][q] = 0.0f; }

    const int NCH = H_DIM / KC;   // 16
    {
        const uint32_t d = sb;
#pragma unroll
        for (int j = 0; j < 4; j++) cp16(d + GU_AH + so + j * 4096u, aP[j]);
#pragma unroll
        for (int j = 0; j < 2; j++) {
            cp16(d + GU_BG + so + j * 4096u, bgP[j]);
            cp16(d + GU_BU + so + j * 4096u, buP[j]);
        }
        cp_commit();
    }

    for (int c = 0; c < NCH; c++) {
        if (c + 1 < NCH) {
            const uint32_t d = sb + ((c + 1) & 1) * GU_STAGE;
            const int k0 = (c + 1) * KC;
#pragma unroll
            for (int j = 0; j < 4; j++) cp16(d + GU_AH + so + j * 4096u, aP[j] + k0);
#pragma unroll
            for (int j = 0; j < 2; j++) {
                cp16(d + GU_BG + so + j * 4096u, bgP[j] + k0);
                cp16(d + GU_BU + so + j * 4096u, buP[j] + k0);
            }
            cp_commit();
            cp_wait<1>();
        } else {
            cp_wait<0>();
        }
        __syncthreads();

        const uint32_t st = sb + (c & 1) * GU_STAGE;
#pragma unroll
        for (int kk = 0; kk < 4; kk++) {
            const uint32_t ku = (uint32_t)(2 * kk + hl);
            uint32_t ah[2][4];
#pragma unroll
            for (int mt = 0; mt < 2; mt++)
                ldsm4(ah[mt], st + GU_AH + aRow[mt] + ((ku ^ aXor[mt]) << 4));
            uint32_t bg[2][4], bu[2][4];
#pragma unroll
            for (int p = 0; p < 2; p++) {
                const uint32_t bo = bRow[p] + ((ku ^ bXor[p]) << 4);
                ldsm4(bg[p], st + GU_BG + bo);
                ldsm4(bu[p], st + GU_BU + bo);
            }
#pragma unroll
            for (int mt = 0; mt < 2; mt++)
#pragma unroll
                for (int p = 0; p < 2; p++)
#pragma unroll
                    for (int q = 0; q < 2; q++) {
                        const int nt = 2 * p + q;
                        mma16816(accg[mt][nt], ah[mt], bg[p][q], bg[p][q + 2]);
                        mma16816(accu[mt][nt], ah[mt], bu[p][q], bu[p][q + 2]);
                    }
        }
        __syncthreads();
    }

    // epilogue: inter = gelu(g)*u, split fp16 hi/lo; rows at off+gm (shared rows at NASSIGN+)
    const int colq = (lane & 3) * 2;
#pragma unroll
    for (int mt = 0; mt < 2; mt++) {
#pragma unroll
        for (int half = 0; half < 2; half++) {
            const int gm = mb + m0 + mt * 16 + (lane >> 2) + half * 8;
            if (gm >= cnt) continue;
            const size_t orow = (size_t)(off + gm) * I_DIM;
#pragma unroll
            for (int nt = 0; nt < 4; nt++) {
                const float g0 = accg[mt][nt][half * 2 + 0];
                const float g1 = accg[mt][nt][half * 2 + 1];
                const float u0 = accu[mt][nt][half * 2 + 0];
                const float u1 = accu[mt][nt][half * 2 + 1];
                const float v0 = gelu_exact(g0) * u0;
                const float v1 = gelu_exact(g1) * u1;
                uint32_t h, l;
                splitpair(v0, v1, h, l);
                const size_t oc = orow + nb + n0 + nt * 8 + colq;
                *(uint32_t*)(oHi + oc) = h;
                *(uint32_t*)(oLo + oc) = l;
            }
        }
    }
}

// ======================= down GEMM (2-term A split; z=0..7 routed -> dtmp, z=8 shared -> out) ===
#define DN_AH 0u
#define DN_AL 16384u
#define DN_B  32768u
#define DN_STAGE 49152u
#define DN_SMEM  (2 * 49152)

__global__ void __launch_bounds__(256) dn_mma_kernel(const hf* __restrict__ AHi,
                                                     const hf* __restrict__ ALo,
                                                     const hf* __restrict__ Wd_all,
                                                     const hf* __restrict__ sWd,
                                                     float* __restrict__ out,
                                                     hf* __restrict__ dtmp) {
    const int e      = blockIdx.z;
    const bool SHARED = (e == E_NUM);
    const int cnt = SHARED ? T_TOT : g_cnt[e];
    const int off = SHARED ? NASSIGN : g_off[e];
    const int mb  = blockIdx.y * 128;
    if (mb >= cnt) return;
    const int nb  = blockIdx.x * 128;

    extern __shared__ char dsm[];
    const uint32_t sb = smem_u32(dsm);
    const int tid = threadIdx.x;

    const int cx = tid & 7;
    const int rb = tid >> 3;
    const uint32_t so = (uint32_t)rb * 128u + (uint32_t)(((cx ^ (rb & 7))) * 16);
    const hf* B = SHARED ? sWd : Wd_all + (size_t)e * H_DIM * I_DIM;

    const hf *aHiP[4], *aLoP[4], *bP[4];
#pragma unroll
    for (int j = 0; j < 4; j++) {
        int lr = mb + rb + 32 * j;
        if (lr >= cnt) lr = cnt - 1;
        const size_t arow = (size_t)(off + lr) * I_DIM + cx * 8;
        aHiP[j] = AHi + arow;
        aLoP[j] = ALo + arow;
        bP[j] = B + (size_t)(nb + rb + 32 * j) * I_DIM + cx * 8;
    }

    const int warp = tid >> 5, lane = tid & 31;
    const int m0 = (warp & 3) * 32;
    const int n0 = (warp >> 2) * 64;
    const int hl = lane >> 4;
    const int l15 = lane & 15;

    uint32_t aRow[2], aXor[2], bRow[4], bXor[4];
#pragma unroll
    for (int mt = 0; mt < 2; mt++) {
        const int r = m0 + mt * 16 + l15;
        aRow[mt] = (uint32_t)r * 128u;
        aXor[mt] = (uint32_t)(r & 7);
    }
#pragma unroll
    for (int p = 0; p < 4; p++) {
        const int r = n0 + p * 16 + l15;
        bRow[p] = (uint32_t)r * 128u;
        bXor[p] = (uint32_t)(r & 7);
    }

    float acc[2][8][4];
#pragma unroll
    for (int mt = 0; mt < 2; mt++)
#pragma unroll
        for (int nt = 0; nt < 8; nt++)
#pragma unroll
            for (int q = 0; q < 4; q++) acc[mt][nt][q] = 0.0f;

    const int NCH = I_DIM / KC;   // 8
    {
        const uint32_t d = sb;
#pragma unroll
        for (int j = 0; j < 4; j++) {
            cp16(d + DN_AH + so + j * 4096u, aHiP[j]);
            cp16(d + DN_AL + so + j * 4096u, aLoP[j]);
            cp16(d + DN_B  + so + j * 4096u, bP[j]);
        }
        cp_commit();
    }

    for (int c = 0; c < NCH; c++) {
        if (c + 1 < NCH) {
            const uint32_t d = sb + ((c + 1) & 1) * DN_STAGE;
            const int k0 = (c + 1) * KC;
#pragma unroll
            for (int j = 0; j < 4; j++) {
                cp16(d + DN_AH + so + j * 4096u, aHiP[j] + k0);
                cp16(d + DN_AL + so + j * 4096u, aLoP[j] + k0);
                cp16(d + DN_B  + so + j * 4096u, bP[j] + k0);
            }
            cp_commit();
            cp_wait<1>();
        } else {
            cp_wait<0>();
        }
        __syncthreads();

        const uint32_t st = sb + (c & 1) * DN_STAGE;
#pragma unroll
        for (int kk = 0; kk < 4; kk++) {
            const uint32_t ku = (uint32_t)(2 * kk + hl);
            uint32_t ah[2][4], al[2][4];
#pragma unroll
            for (int mt = 0; mt < 2; mt++) {
                const uint32_t ao = aRow[mt] + ((ku ^ aXor[mt]) << 4);
                ldsm4(ah[mt], st + DN_AH + ao);
                ldsm4(al[mt], st + DN_AL + ao);
            }
            uint32_t bh[4][4];
#pragma unroll
            for (int p = 0; p < 4; p++)
                ldsm4(bh[p], st + DN_B + bRow[p] + ((ku ^ bXor[p]) << 4));
#pragma unroll
            for (int mt = 0; mt < 2; mt++)
#pragma unroll
                for (int p = 0; p < 4; p++)
#pragma unroll
                    for (int q = 0; q < 2; q++) {
                        const int nt = 2 * p + q;
                        mma16816(acc[mt][nt], ah[mt], bh[p][q], bh[p][q + 2]);
                        mma16816(acc[mt][nt], al[mt], bh[p][q], bh[p][q + 2]);
                    }
        }
        __syncthreads();
    }

    const int colq = (lane & 3) * 2;
#pragma unroll
    for (int mt = 0; mt < 2; mt++) {
#pragma unroll
        for (int half = 0; half < 2; half++) {
            const int gm = mb + m0 + mt * 16 + (lane >> 2) + half * 8;
            if (gm >= cnt) continue;
            if (!SHARED) {
                const float w = g_aw[off + gm];
                hf* op = dtmp + (size_t)(off + gm) * H_DIM + nb + n0 + colq;
#pragma unroll
                for (int nt = 0; nt < 8; nt++) {
                    __half2 v = __floats2half2_rn(w * acc[mt][nt][half * 2 + 0],
                                                  w * acc[mt][nt][half * 2 + 1]);
                    *(__half2*)(op + nt * 8) = v;
                }
            } else {
                float* op = out + (size_t)gm * H_DIM + nb + n0 + colq;
#pragma unroll
                for (int nt = 0; nt < 8; nt++) {
                    float2 v = {acc[mt][nt][half * 2 + 0], acc[mt][nt][half * 2 + 1]};
                    *(float2*)(op + nt * 8) = v;
                }
            }
        }
    }
}

// ======================= combine =======================
__global__ void __launch_bounds__(256) combine_kernel(float* __restrict__ out) {
    const int t = blockIdx.x;
    const int p0 = g_pos[t * 2 + 0];
    const int p1 = g_pos[t * 2 + 1];
    const int c = threadIdx.x * 4;
    const __half2* a2 = (const __half2*)(g_dtmp + (size_t)p0 * H_DIM + c);
    const __half2* b2 = (const __half2*)(g_dtmp + (size_t)p1 * H_DIM + c);
    const float2 a0 = __half22float2(a2[0]), a1 = __half22float2(a2[1]);
    const float2 b0 = __half22float2(b2[0]), b1 = __half22float2(b2[1]);
    float4 o = *(const float4*)(out + (size_t)t * H_DIM + c);
    o.x += a0.x + b0.x;
    o.y += a0.y + b0.y;
    o.z += a1.x + b1.x;
    o.w += a1.y + b1.y;
    *(float4*)(out + (size_t)t * H_DIM + c) = o;
}

// ======================= launch =======================
extern "C" void kernel_launch(void* const* d_in, const int* in_sizes, int n_in,
                              void* d_out, int out_size) {
    const float* X   = (const float*)d_in[0];
    const float* GW  = (const float*)d_in[1];
    const float* Wg  = (const float*)d_in[2];
    const float* Wu  = (const float*)d_in[3];
    const float* Wd  = (const float*)d_in[4];
    const float* sWg = (const float*)d_in[5];
    const float* sWu = (const float*)d_in[6];
    const float* sWd = (const float*)d_in[7];
    float* out = (float*)d_out;

    cudaFuncSetAttribute(gu_mma_kernel, cudaFuncAttributeMaxDynamicSharedMemorySize, GU_SMEM);
    cudaFuncSetAttribute(dn_mma_kernel, cudaFuncAttributeMaxDynamicSharedMemorySize, DN_SMEM);

    hf *wgT, *wuT, *wdT, *sgT, *suT, *sdT, *ihi, *ilo, *dtmp;
    cudaGetSymbolAddress((void**)&wgT, g_wgT);
    cudaGetSymbolAddress((void**)&wuT, g_wuT);
    cudaGetSymbolAddress((void**)&wdT, g_wdT);
    cudaGetSymbolAddress((void**)&sgT, g_swgT);
    cudaGetSymbolAddress((void**)&suT, g_swuT);
    cudaGetSymbolAddress((void**)&sdT, g_swdT);
    cudaGetSymbolAddress((void**)&ihi, g_ihi);
    cudaGetSymbolAddress((void**)&ilo, g_ilo);
    cudaGetSymbolAddress((void**)&dtmp, g_dtmp);

    // routing
    init_kernel<<<1, 32>>>();
    router_kernel<<<T_TOT / 8, 256>>>(X, GW);
    scan_kernel<<<1, 32>>>();
    scatter_kernel<<<T_TOT / 256, 256>>>();

    // preprocessing
    round_x_kernel<<<(T_TOT * H_DIM) / (256 * 8), 256>>>(X);
    trans_round_kernel<<<dim3(I_DIM / 32, H_DIM / 32, E_NUM), 256>>>(Wg, wgT, H_DIM, I_DIM);
    trans_round_kernel<<<dim3(I_DIM / 32, H_DIM / 32, E_NUM), 256>>>(Wu, wuT, H_DIM, I_DIM);
    trans_round_kernel<<<dim3(H_DIM / 32, I_DIM / 32, E_NUM), 256>>>(Wd, wdT, I_DIM, H_DIM);
    trans_round_kernel<<<dim3(I_DIM / 32, H_DIM / 32, 1), 256>>>(sWg, sgT, H_DIM, I_DIM);
    trans_round_kernel<<<dim3(I_DIM / 32, H_DIM / 32, 1), 256>>>(sWu, suT, H_DIM, I_DIM);
    trans_round_kernel<<<dim3(H_DIM / 32, I_DIM / 32, 1), 256>>>(sWd, sdT, I_DIM, H_DIM);

    // fused gate+up for routed experts (z=0..7) + shared expert (z=8)
    gu_mma_kernel<<<dim3(I_DIM / 64, T_TOT / 128, E_NUM + 1), 256, GU_SMEM>>>(
        wgT, wuT, sgT, suT, ihi, ilo);
    // fused down: routed -> dtmp (weighted fp16), shared -> out (fp32)
    dn_mma_kernel<<<dim3(H_DIM / 128, T_TOT / 128, E_NUM + 1), 256, DN_SMEM>>>(
        ihi, ilo, wdT, sdT, out, dtmp);
    combine_kernel<<<T_TOT, 256>>>(out);
}

// round 8
// speedup vs baseline: 1.9413x; 1.2147x over previous
#include <cuda_runtime.h>
#include <cuda_fp16.h>
#include <math.h>
#include <stdint.h>

#define T_TOT   16384
#define H_DIM   1024
#define I_DIM   512
#define E_NUM   8
#define TOPK    2
#define NASSIGN (T_TOT * TOPK)
#define NROWS   (NASSIGN + T_TOT)     // routed assignments + shared-expert rows
#define KC      64

typedef __half hf;

// ======================= scratch =======================
__device__ int   g_topk_idx[NASSIGN];
__device__ float g_topk_w[NASSIGN];
__device__ int   g_cnt[E_NUM];
__device__ int   g_off[E_NUM];
__device__ int   g_fill[E_NUM];
__device__ int   g_tok[NASSIGN];
__device__ float g_aw[NASSIGN];
__device__ int   g_pos[NASSIGN];

__device__ __align__(16) hf g_xhi[(size_t)T_TOT * H_DIM];          // fp16(x)
__device__ __align__(16) hf g_wgT[(size_t)E_NUM * I_DIM * H_DIM];
__device__ __align__(16) hf g_wuT[(size_t)E_NUM * I_DIM * H_DIM];
__device__ __align__(16) hf g_wdT[(size_t)E_NUM * H_DIM * I_DIM];
__device__ __align__(16) hf g_swgT[(size_t)I_DIM * H_DIM];
__device__ __align__(16) hf g_swuT[(size_t)I_DIM * H_DIM];
__device__ __align__(16) hf g_swdT[(size_t)H_DIM * I_DIM];
__device__ __align__(16) hf g_inter[(size_t)NROWS * I_DIM];        // inter fp16 (routed + shared)
__device__ __align__(16) hf g_dtmp[(size_t)NASSIGN * H_DIM];       // routed down outputs (fp16)

// ======================= helpers =======================
__device__ __forceinline__ uint32_t smem_u32(const void* p) {
    uint32_t a;
    asm("{ .reg .u64 t; cvta.to.shared.u64 t, %1; cvt.u32.u64 %0, t; }" : "=r"(a) : "l"(p));
    return a;
}
__device__ __forceinline__ void cp16(uint32_t dst, const void* src) {
    asm volatile("cp.async.cg.shared.global [%0], [%1], 16;" :: "r"(dst), "l"(src));
}
__device__ __forceinline__ void cp_commit() { asm volatile("cp.async.commit_group;" ::: "memory"); }
template <int N>
__device__ __forceinline__ void cp_wait() { asm volatile("cp.async.wait_group %0;" :: "n"(N) : "memory"); }

__device__ __forceinline__ void ldsm4(uint32_t* r, uint32_t addr) {
    asm volatile("ldmatrix.sync.aligned.m8n8.x4.shared.b16 {%0,%1,%2,%3}, [%4];"
                 : "=r"(r[0]), "=r"(r[1]), "=r"(r[2]), "=r"(r[3]) : "r"(addr));
}
__device__ __forceinline__ void mma16816(float* d, const uint32_t* a, uint32_t b0, uint32_t b1) {
    asm volatile("mma.sync.aligned.m16n8k16.row.col.f32.f16.f16.f32 "
                 "{%0,%1,%2,%3}, {%4,%5,%6,%7}, {%8,%9}, {%0,%1,%2,%3};"
                 : "+f"(d[0]), "+f"(d[1]), "+f"(d[2]), "+f"(d[3])
                 : "r"(a[0]), "r"(a[1]), "r"(a[2]), "r"(a[3]), "r"(b0), "r"(b1));
}
__device__ __forceinline__ float gelu_exact(float x) {
    return 0.5f * x * (1.0f + erff(x * 0.70710678118654752f));
}

// ======================= routing =======================
__global__ void init_kernel() {
    if (threadIdx.x < E_NUM) g_cnt[threadIdx.x] = 0;
}

__global__ void __launch_bounds__(256) router_kernel(const float* __restrict__ X,
                                                     const float* __restrict__ GW) {
    __shared__ float sgw[E_NUM * H_DIM];
    for (int i = threadIdx.x; i < E_NUM * H_DIM; i += 256) sgw[i] = GW[i];
    __syncthreads();
    const int warp = threadIdx.x >> 5, lane = threadIdx.x & 31;
    const int t = blockIdx.x * 8 + warp;
    if (t >= T_TOT) return;
    const float* x = X + (size_t)t * H_DIM;
    float acc[E_NUM];
#pragma unroll
    for (int e = 0; e < E_NUM; e++) acc[e] = 0.0f;
    for (int h = lane; h < H_DIM; h += 32) {
        const float xv = x[h];
#pragma unroll
        for (int e = 0; e < E_NUM; e++) acc[e] = fmaf(xv, sgw[e * H_DIM + h], acc[e]);
    }
#pragma unroll
    for (int e = 0; e < E_NUM; e++)
#pragma unroll
        for (int o = 16; o > 0; o >>= 1) acc[e] += __shfl_down_sync(0xffffffffu, acc[e], o);
    if (lane == 0) {
        float l0 = -1e30f, l1 = -1e30f;
        int i0 = 0, i1 = 0;
#pragma unroll
        for (int e = 0; e < E_NUM; e++) {
            const float v = acc[e];
            if (v > l0)      { l1 = l0; i1 = i0; l0 = v; i0 = e; }
            else if (v > l1) { l1 = v; i1 = e; }
        }
        const float w1 = expf(l1 - l0);
        const float inv = 1.0f / (1.0f + w1);
        g_topk_idx[t * 2 + 0] = i0;
        g_topk_idx[t * 2 + 1] = i1;
        g_topk_w[t * 2 + 0] = inv;
        g_topk_w[t * 2 + 1] = w1 * inv;
        atomicAdd(&g_cnt[i0], 1);
        atomicAdd(&g_cnt[i1], 1);
    }
}

__global__ void scan_kernel() {
    if (threadIdx.x == 0) {
        int s = 0;
        for (int e = 0; e < E_NUM; e++) { g_off[e] = s; g_fill[e] = s; s += g_cnt[e]; }
    }
}

__global__ void __launch_bounds__(256) scatter_kernel() {
    const int t = blockIdx.x * 256 + threadIdx.x;
    if (t >= T_TOT) return;
#pragma unroll
    for (int k = 0; k < TOPK; k++) {
        const int e = g_topk_idx[t * 2 + k];
        const float w = g_topk_w[t * 2 + k];
        const int p = atomicAdd(&g_fill[e], 1);
        g_tok[p] = t;
        g_aw[p] = w;
        g_pos[t * 2 + k] = p;
    }
}

// ======================= preprocessing =======================
__global__ void __launch_bounds__(256) round_x_kernel(const float* __restrict__ X) {
    const size_t i = ((size_t)blockIdx.x * 256 + threadIdx.x) * 8;
    const float4 a = *(const float4*)(X + i);
    const float4 b = *(const float4*)(X + i + 4);
    __half2 h0 = __floats2half2_rn(a.x, a.y);
    __half2 h1 = __floats2half2_rn(a.z, a.w);
    __half2 h2 = __floats2half2_rn(b.x, b.y);
    __half2 h3 = __floats2half2_rn(b.z, b.w);
    uint4 H = {*(uint32_t*)&h0, *(uint32_t*)&h1, *(uint32_t*)&h2, *(uint32_t*)&h3};
    *(uint4*)(g_xhi + i) = H;
}

__global__ void __launch_bounds__(256) trans_round_kernel(const float* __restrict__ src,
                                                          hf* __restrict__ dst,
                                                          int R, int C) {
    __shared__ float t[32][33];
    const size_t sb = (size_t)blockIdx.z * R * C;
    const int c0 = blockIdx.x * 32, r0 = blockIdx.y * 32;
    const int tx = threadIdx.x & 31, ty = threadIdx.x >> 5;
#pragma unroll
    for (int j = 0; j < 32; j += 8)
        t[ty + j][tx] = src[sb + (size_t)(r0 + ty + j) * C + c0 + tx];
    __syncthreads();
#pragma unroll
    for (int j = 0; j < 32; j += 8) {
        dst[sb + (size_t)(c0 + ty + j) * R + r0 + tx] = __float2half_rn(t[tx][ty + j]);
    }
}

// ======================= gate+up GEMM (fp16 A, z=0..7 routed, z=8 shared) =======================
#define GU_AH  0u
#define GU_BG  16384u
#define GU_BU  24576u
#define GU_STAGE 32768u
#define GU_SMEM  (2 * 32768)

__global__ void __launch_bounds__(256) gu_mma_kernel(const hf* __restrict__ Wg_all,
                                                     const hf* __restrict__ Wu_all,
                                                     const hf* __restrict__ sWg,
                                                     const hf* __restrict__ sWu,
                                                     hf* __restrict__ oInter) {
    const int e      = blockIdx.z;
    const bool SHARED = (e == E_NUM);
    const int cnt = SHARED ? T_TOT : g_cnt[e];
    const int off = SHARED ? NASSIGN : g_off[e];
    const int mb  = blockIdx.y * 128;
    if (mb >= cnt) return;
    const int nb  = blockIdx.x * 64;

    extern __shared__ char dsm[];
    __shared__ int stok[128];
    const uint32_t sb = smem_u32(dsm);

    const int tid = threadIdx.x;
    if (tid < 128) {
        int r = mb + tid;
        if (r >= cnt) r = cnt - 1;
        stok[tid] = SHARED ? r : g_tok[off + r];
    }
    __syncthreads();

    const int cx = tid & 7;
    const int rb = tid >> 3;
    const uint32_t so = (uint32_t)rb * 128u + (uint32_t)(((cx ^ (rb & 7))) * 16);
    const hf* Bg = SHARED ? sWg : Wg_all + (size_t)e * I_DIM * H_DIM;
    const hf* Bu = SHARED ? sWu : Wu_all + (size_t)e * I_DIM * H_DIM;

    const hf *aP[4], *bgP[2], *buP[2];
#pragma unroll
    for (int j = 0; j < 4; j++)
        aP[j] = g_xhi + (size_t)stok[rb + 32 * j] * H_DIM + cx * 8;
#pragma unroll
    for (int j = 0; j < 2; j++) {
        const size_t brow = (size_t)(nb + rb + 32 * j) * H_DIM + cx * 8;
        bgP[j] = Bg + brow;
        buP[j] = Bu + brow;
    }

    const int warp = tid >> 5, lane = tid & 31;
    const int m0 = (warp & 3) * 32;
    const int n0 = (warp >> 2) * 32;
    const int hl = lane >> 4;
    const int l15 = lane & 15;

    uint32_t aRow[2], aXor[2], bRow[2], bXor[2];
#pragma unroll
    for (int mt = 0; mt < 2; mt++) {
        const int r = m0 + mt * 16 + l15;
        aRow[mt] = (uint32_t)r * 128u;
        aXor[mt] = (uint32_t)(r & 7);
    }
#pragma unroll
    for (int p = 0; p < 2; p++) {
        const int r = n0 + p * 16 + l15;
        bRow[p] = (uint32_t)r * 128u;
        bXor[p] = (uint32_t)(r & 7);
    }

    float accg[2][4][4], accu[2][4][4];
#pragma unroll
    for (int mt = 0; mt < 2; mt++)
#pragma unroll
        for (int nt = 0; nt < 4; nt++)
#pragma unroll
            for (int q = 0; q < 4; q++) { accg[mt][nt][q] = 0.0f; accu[mt][nt][q] = 0.0f; }

    const int NCH = H_DIM / KC;   // 16
    {
        const uint32_t d = sb;
#pragma unroll
        for (int j = 0; j < 4; j++) cp16(d + GU_AH + so + j * 4096u, aP[j]);
#pragma unroll
        for (int j = 0; j < 2; j++) {
            cp16(d + GU_BG + so + j * 4096u, bgP[j]);
            cp16(d + GU_BU + so + j * 4096u, buP[j]);
        }
        cp_commit();
    }

    for (int c = 0; c < NCH; c++) {
        if (c + 1 < NCH) {
            const uint32_t d = sb + ((c + 1) & 1) * GU_STAGE;
            const int k0 = (c + 1) * KC;
#pragma unroll
            for (int j = 0; j < 4; j++) cp16(d + GU_AH + so + j * 4096u, aP[j] + k0);
#pragma unroll
            for (int j = 0; j < 2; j++) {
                cp16(d + GU_BG + so + j * 4096u, bgP[j] + k0);
                cp16(d + GU_BU + so + j * 4096u, buP[j] + k0);
            }
            cp_commit();
            cp_wait<1>();
        } else {
            cp_wait<0>();
        }
        __syncthreads();

        const uint32_t st = sb + (c & 1) * GU_STAGE;
#pragma unroll
        for (int kk = 0; kk < 4; kk++) {
            const uint32_t ku = (uint32_t)(2 * kk + hl);
            uint32_t ah[2][4];
#pragma unroll
            for (int mt = 0; mt < 2; mt++)
                ldsm4(ah[mt], st + GU_AH + aRow[mt] + ((ku ^ aXor[mt]) << 4));
            uint32_t bg[2][4], bu[2][4];
#pragma unroll
            for (int p = 0; p < 2; p++) {
                const uint32_t bo = bRow[p] + ((ku ^ bXor[p]) << 4);
                ldsm4(bg[p], st + GU_BG + bo);
                ldsm4(bu[p], st + GU_BU + bo);
            }
#pragma unroll
            for (int mt = 0; mt < 2; mt++)
#pragma unroll
                for (int p = 0; p < 2; p++)
#pragma unroll
                    for (int q = 0; q < 2; q++) {
                        const int nt = 2 * p + q;
                        mma16816(accg[mt][nt], ah[mt], bg[p][q], bg[p][q + 2]);
                        mma16816(accu[mt][nt], ah[mt], bu[p][q], bu[p][q + 2]);
                    }
        }
        __syncthreads();
    }

    // epilogue: inter = fp16(gelu(g)*u)
    const int colq = (lane & 3) * 2;
#pragma unroll
    for (int mt = 0; mt < 2; mt++) {
#pragma unroll
        for (int half = 0; half < 2; half++) {
            const int gm = mb + m0 + mt * 16 + (lane >> 2) + half * 8;
            if (gm >= cnt) continue;
            const size_t orow = (size_t)(off + gm) * I_DIM;
#pragma unroll
            for (int nt = 0; nt < 4; nt++) {
                const float g0 = accg[mt][nt][half * 2 + 0];
                const float g1 = accg[mt][nt][half * 2 + 1];
                const float u0 = accu[mt][nt][half * 2 + 0];
                const float u1 = accu[mt][nt][half * 2 + 1];
                __half2 v = __floats2half2_rn(gelu_exact(g0) * u0, gelu_exact(g1) * u1);
                *(__half2*)(oInter + orow + nb + n0 + nt * 8 + colq) = v;
            }
        }
    }
}

// ======================= down GEMM (single fp16 A; z=0..7 routed -> dtmp, z=8 shared -> out) ===
#define DN_AH 0u
#define DN_B  16384u
#define DN_STAGE 32768u
#define DN_SMEM  (2 * 32768)

__global__ void __launch_bounds__(256) dn_mma_kernel(const hf* __restrict__ Inter,
                                                     const hf* __restrict__ Wd_all,
                                                     const hf* __restrict__ sWd,
                                                     float* __restrict__ out,
                                                     hf* __restrict__ dtmp) {
    const int e      = blockIdx.z;
    const bool SHARED = (e == E_NUM);
    const int cnt = SHARED ? T_TOT : g_cnt[e];
    const int off = SHARED ? NASSIGN : g_off[e];
    const int mb  = blockIdx.y * 128;
    if (mb >= cnt) return;
    const int nb  = blockIdx.x * 128;

    extern __shared__ char dsm[];
    const uint32_t sb = smem_u32(dsm);
    const int tid = threadIdx.x;

    const int cx = tid & 7;
    const int rb = tid >> 3;
    const uint32_t so = (uint32_t)rb * 128u + (uint32_t)(((cx ^ (rb & 7))) * 16);
    const hf* B = SHARED ? sWd : Wd_all + (size_t)e * H_DIM * I_DIM;

    const hf *aP[4], *bP[4];
#pragma unroll
    for (int j = 0; j < 4; j++) {
        int lr = mb + rb + 32 * j;
        if (lr >= cnt) lr = cnt - 1;
        aP[j] = Inter + (size_t)(off + lr) * I_DIM + cx * 8;
        bP[j] = B + (size_t)(nb + rb + 32 * j) * I_DIM + cx * 8;
    }

    const int warp = tid >> 5, lane = tid & 31;
    const int m0 = (warp & 3) * 32;
    const int n0 = (warp >> 2) * 64;
    const int hl = lane >> 4;
    const int l15 = lane & 15;

    uint32_t aRow[2], aXor[2], bRow[4], bXor[4];
#pragma unroll
    for (int mt = 0; mt < 2; mt++) {
        const int r = m0 + mt * 16 + l15;
        aRow[mt] = (uint32_t)r * 128u;
        aXor[mt] = (uint32_t)(r & 7);
    }
#pragma unroll
    for (int p = 0; p < 4; p++) {
        const int r = n0 + p * 16 + l15;
        bRow[p] = (uint32_t)r * 128u;
        bXor[p] = (uint32_t)(r & 7);
    }

    float acc[2][8][4];
#pragma unroll
    for (int mt = 0; mt < 2; mt++)
#pragma unroll
        for (int nt = 0; nt < 8; nt++)
#pragma unroll
            for (int q = 0; q < 4; q++) acc[mt][nt][q] = 0.0f;

    const int NCH = I_DIM / KC;   // 8
    {
        const uint32_t d = sb;
#pragma unroll
        for (int j = 0; j < 4; j++) {
            cp16(d + DN_AH + so + j * 4096u, aP[j]);
            cp16(d + DN_B  + so + j * 4096u, bP[j]);
        }
        cp_commit();
    }

    for (int c = 0; c < NCH; c++) {
        if (c + 1 < NCH) {
            const uint32_t d = sb + ((c + 1) & 1) * DN_STAGE;
            const int k0 = (c + 1) * KC;
#pragma unroll
            for (int j = 0; j < 4; j++) {
                cp16(d + DN_AH + so + j * 4096u, aP[j] + k0);
                cp16(d + DN_B  + so + j * 4096u, bP[j] + k0);
            }
            cp_commit();
            cp_wait<1>();
        } else {
            cp_wait<0>();
        }
        __syncthreads();

        const uint32_t st = sb + (c & 1) * DN_STAGE;
#pragma unroll
        for (int kk = 0; kk < 4; kk++) {
            const uint32_t ku = (uint32_t)(2 * kk + hl);
            uint32_t ah[2][4];
#pragma unroll
            for (int mt = 0; mt < 2; mt++)
                ldsm4(ah[mt], st + DN_AH + aRow[mt] + ((ku ^ aXor[mt]) << 4));
            uint32_t bh[4][4];
#pragma unroll
            for (int p = 0; p < 4; p++)
                ldsm4(bh[p], st + DN_B + bRow[p] + ((ku ^ bXor[p]) << 4));
#pragma unroll
            for (int mt = 0; mt < 2; mt++)
#pragma unroll
                for (int p = 0; p < 4; p++)
#pragma unroll
                    for (int q = 0; q < 2; q++) {
                        const int nt = 2 * p + q;
                        mma16816(acc[mt][nt], ah[mt], bh[p][q], bh[p][q + 2]);
                    }
        }
        __syncthreads();
    }

    const int colq = (lane & 3) * 2;
#pragma unroll
    for (int mt = 0; mt < 2; mt++) {
#pragma unroll
        for (int half = 0; half < 2; half++) {
            const int gm = mb + m0 + mt * 16 + (lane >> 2) + half * 8;
            if (gm >= cnt) continue;
            if (!SHARED) {
                const float w = g_aw[off + gm];
                hf* op = dtmp + (size_t)(off + gm) * H_DIM + nb + n0 + colq;
#pragma unroll
                for (int nt = 0; nt < 8; nt++) {
                    __half2 v = __floats2half2_rn(w * acc[mt][nt][half * 2 + 0],
                                                  w * acc[mt][nt][half * 2 + 1]);
                    *(__half2*)(op + nt * 8) = v;
                }
            } else {
                float* op = out + (size_t)gm * H_DIM + nb + n0 + colq;
#pragma unroll
                for (int nt = 0; nt < 8; nt++) {
                    float2 v = {acc[mt][nt][half * 2 + 0], acc[mt][nt][half * 2 + 1]};
                    *(float2*)(op + nt * 8) = v;
                }
            }
        }
    }
}

// ======================= combine =======================
__global__ void __launch_bounds__(256) combine_kernel(float* __restrict__ out) {
    const int t = blockIdx.x;
    const int p0 = g_pos[t * 2 + 0];
    const int p1 = g_pos[t * 2 + 1];
    const int c = threadIdx.x * 4;
    const __half2* a2 = (const __half2*)(g_dtmp + (size_t)p0 * H_DIM + c);
    const __half2* b2 = (const __half2*)(g_dtmp + (size_t)p1 * H_DIM + c);
    const float2 a0 = __half22float2(a2[0]), a1 = __half22float2(a2[1]);
    const float2 b0 = __half22float2(b2[0]), b1 = __half22float2(b2[1]);
    float4 o = *(const float4*)(out + (size_t)t * H_DIM + c);
    o.x += a0.x + b0.x;
    o.y += a0.y + b0.y;
    o.z += a1.x + b1.x;
    o.w += a1.y + b1.y;
    *(float4*)(out + (size_t)t * H_DIM + c) = o;
}

// ======================= launch =======================
extern "C" void kernel_launch(void* const* d_in, const int* in_sizes, int n_in,
                              void* d_out, int out_size) {
    const float* X   = (const float*)d_in[0];
    const float* GW  = (const float*)d_in[1];
    const float* Wg  = (const float*)d_in[2];
    const float* Wu  = (const float*)d_in[3];
    const float* Wd  = (const float*)d_in[4];
    const float* sWg = (const float*)d_in[5];
    const float* sWu = (const float*)d_in[6];
    const float* sWd = (const float*)d_in[7];
    float* out = (float*)d_out;

    cudaFuncSetAttribute(gu_mma_kernel, cudaFuncAttributeMaxDynamicSharedMemorySize, GU_SMEM);
    cudaFuncSetAttribute(dn_mma_kernel, cudaFuncAttributeMaxDynamicSharedMemorySize, DN_SMEM);

    hf *wgT, *wuT, *wdT, *sgT, *suT, *sdT, *inter, *dtmp;
    cudaGetSymbolAddress((void**)&wgT, g_wgT);
    cudaGetSymbolAddress((void**)&wuT, g_wuT);
    cudaGetSymbolAddress((void**)&wdT, g_wdT);
    cudaGetSymbolAddress((void**)&sgT, g_swgT);
    cudaGetSymbolAddress((void**)&suT, g_swuT);
    cudaGetSymbolAddress((void**)&sdT, g_swdT);
    cudaGetSymbolAddress((void**)&inter, g_inter);
    cudaGetSymbolAddress((void**)&dtmp, g_dtmp);

    // routing
    init_kernel<<<1, 32>>>();
    router_kernel<<<T_TOT / 8, 256>>>(X, GW);
    scan_kernel<<<1, 32>>>();
    scatter_kernel<<<T_TOT / 256, 256>>>();

    // preprocessing
    round_x_kernel<<<(T_TOT * H_DIM) / (256 * 8), 256>>>(X);
    trans_round_kernel<<<dim3(I_DIM / 32, H_DIM / 32, E_NUM), 256>>>(Wg, wgT, H_DIM, I_DIM);
    trans_round_kernel<<<dim3(I_DIM / 32, H_DIM / 32, E_NUM), 256>>>(Wu, wuT, H_DIM, I_DIM);
    trans_round_kernel<<<dim3(H_DIM / 32, I_DIM / 32, E_NUM), 256>>>(Wd, wdT, I_DIM, H_DIM);
    trans_round_kernel<<<dim3(I_DIM / 32, H_DIM / 32, 1), 256>>>(sWg, sgT, H_DIM, I_DIM);
    trans_round_kernel<<<dim3(I_DIM / 32, H_DIM / 32, 1), 256>>>(sWu, suT, H_DIM, I_DIM);
    trans_round_kernel<<<dim3(H_DIM / 32, I_DIM / 32, 1), 256>>>(sWd, sdT, I_DIM, H_DIM);

    // fused gate+up for routed experts (z=0..7) + shared expert (z=8)
    gu_mma_kernel<<<dim3(I_DIM / 64, T_TOT / 128, E_NUM + 1), 256, GU_SMEM>>>(
        wgT, wuT, sgT, suT, inter);
    // fused down: routed -> dtmp (weighted fp16), shared -> out (fp32)
    dn_mma_kernel<<<dim3(H_DIM / 128, T_TOT / 128, E_NUM + 1), 256, DN_SMEM>>>(
        inter, wdT, sdT, out, dtmp);
    combine_kernel<<<T_TOT, 256>>>(out);
}

// round 9
// speedup vs baseline: 1.9689x; 1.0142x over previous
#include <cuda_runtime.h>
#include <cuda_fp16.h>
#include <math.h>
#include <stdint.h>

#define T_TOT   16384
#define H_DIM   1024
#define I_DIM   512
#define E_NUM   8
#define TOPK    2
#define NASSIGN (T_TOT * TOPK)
#define NROWS   (NASSIGN + T_TOT)     // routed assignments + shared-expert rows
#define KC      64

typedef __half hf;

// ======================= scratch =======================
__device__ int   g_topk_idx[NASSIGN];
__device__ float g_topk_w[NASSIGN];
__device__ int   g_cnt[E_NUM];
__device__ int   g_off[E_NUM];
__device__ int   g_fill[E_NUM];
__device__ int   g_tok[NASSIGN];
__device__ float g_aw[NASSIGN];
__device__ int   g_pos[NASSIGN];

__device__ __align__(16) hf g_xhi[(size_t)T_TOT * H_DIM];          // fp16(x), written by router
__device__ __align__(16) hf g_wgT[(size_t)E_NUM * I_DIM * H_DIM];
__device__ __align__(16) hf g_wuT[(size_t)E_NUM * I_DIM * H_DIM];
__device__ __align__(16) hf g_wdT[(size_t)E_NUM * H_DIM * I_DIM];
__device__ __align__(16) hf g_swgT[(size_t)I_DIM * H_DIM];
__device__ __align__(16) hf g_swuT[(size_t)I_DIM * H_DIM];
__device__ __align__(16) hf g_swdT[(size_t)H_DIM * I_DIM];
__device__ __align__(16) hf g_inter[(size_t)NROWS * I_DIM];        // inter fp16 (routed + shared)
__device__ __align__(16) hf g_dtmp[(size_t)NROWS * H_DIM];         // down outputs fp16 (routed + shared)

// ======================= helpers =======================
__device__ __forceinline__ uint32_t smem_u32(const void* p) {
    uint32_t a;
    asm("{ .reg .u64 t; cvta.to.shared.u64 t, %1; cvt.u32.u64 %0, t; }" : "=r"(a) : "l"(p));
    return a;
}
__device__ __forceinline__ void cp16(uint32_t dst, const void* src) {
    asm volatile("cp.async.cg.shared.global [%0], [%1], 16;" :: "r"(dst), "l"(src));
}
__device__ __forceinline__ void cp_commit() { asm volatile("cp.async.commit_group;" ::: "memory"); }
template <int N>
__device__ __forceinline__ void cp_wait() { asm volatile("cp.async.wait_group %0;" :: "n"(N) : "memory"); }

__device__ __forceinline__ void ldsm4(uint32_t* r, uint32_t addr) {
    asm volatile("ldmatrix.sync.aligned.m8n8.x4.shared.b16 {%0,%1,%2,%3}, [%4];"
                 : "=r"(r[0]), "=r"(r[1]), "=r"(r[2]), "=r"(r[3]) : "r"(addr));
}
__device__ __forceinline__ void mma16816(float* d, const uint32_t* a, uint32_t b0, uint32_t b1) {
    asm volatile("mma.sync.aligned.m16n8k16.row.col.f32.f16.f16.f32 "
                 "{%0,%1,%2,%3}, {%4,%5,%6,%7}, {%8,%9}, {%0,%1,%2,%3};"
                 : "+f"(d[0]), "+f"(d[1]), "+f"(d[2]), "+f"(d[3])
                 : "r"(a[0]), "r"(a[1]), "r"(a[2]), "r"(a[3]), "r"(b0), "r"(b1));
}
__device__ __forceinline__ float gelu_exact(float x) {
    return 0.5f * x * (1.0f + erff(x * 0.70710678118654752f));
}

// ======================= routing (router also emits fp16(x)) =======================
__global__ void init_kernel() {
    if (threadIdx.x < E_NUM) g_cnt[threadIdx.x] = 0;
}

__global__ void __launch_bounds__(256) router_kernel(const float* __restrict__ X,
                                                     const float* __restrict__ GW) {
    __shared__ float sgw[E_NUM * H_DIM];
    for (int i = threadIdx.x; i < E_NUM * H_DIM; i += 256) sgw[i] = GW[i];
    __syncthreads();
    const int warp = threadIdx.x >> 5, lane = threadIdx.x & 31;
    const int t = blockIdx.x * 8 + warp;
    if (t >= T_TOT) return;
    const float* x = X + (size_t)t * H_DIM;
    hf* xo = g_xhi + (size_t)t * H_DIM;

    float acc[E_NUM];
#pragma unroll
    for (int e = 0; e < E_NUM; e++) acc[e] = 0.0f;

    for (int h = lane * 4; h < H_DIM; h += 128) {
        const float4 v = *(const float4*)(x + h);
        // write fp16(x) on the way
        __half2 p0 = __floats2half2_rn(v.x, v.y);
        __half2 p1 = __floats2half2_rn(v.z, v.w);
        uint2 w = {*(uint32_t*)&p0, *(uint32_t*)&p1};
        *(uint2*)(xo + h) = w;
#pragma unroll
        for (int e = 0; e < E_NUM; e++) {
            const float4 g = *(const float4*)(sgw + e * H_DIM + h);
            acc[e] += v.x * g.x + v.y * g.y + v.z * g.z + v.w * g.w;
        }
    }
#pragma unroll
    for (int e = 0; e < E_NUM; e++)
#pragma unroll
        for (int o = 16; o > 0; o >>= 1) acc[e] += __shfl_down_sync(0xffffffffu, acc[e], o);
    if (lane == 0) {
        float l0 = -1e30f, l1 = -1e30f;
        int i0 = 0, i1 = 0;
#pragma unroll
        for (int e = 0; e < E_NUM; e++) {
            const float v = acc[e];
            if (v > l0)      { l1 = l0; i1 = i0; l0 = v; i0 = e; }
            else if (v > l1) { l1 = v; i1 = e; }
        }
        const float w1 = expf(l1 - l0);
        const float inv = 1.0f / (1.0f + w1);
        g_topk_idx[t * 2 + 0] = i0;
        g_topk_idx[t * 2 + 1] = i1;
        g_topk_w[t * 2 + 0] = inv;
        g_topk_w[t * 2 + 1] = w1 * inv;
        atomicAdd(&g_cnt[i0], 1);
        atomicAdd(&g_cnt[i1], 1);
    }
}

__global__ void scan_kernel() {
    if (threadIdx.x == 0) {
        int s = 0;
        for (int e = 0; e < E_NUM; e++) { g_off[e] = s; g_fill[e] = s; s += g_cnt[e]; }
    }
}

__global__ void __launch_bounds__(256) scatter_kernel() {
    const int t = blockIdx.x * 256 + threadIdx.x;
    if (t >= T_TOT) return;
#pragma unroll
    for (int k = 0; k < TOPK; k++) {
        const int e = g_topk_idx[t * 2 + k];
        const float w = g_topk_w[t * 2 + k];
        const int p = atomicAdd(&g_fill[e], 1);
        g_tok[p] = t;
        g_aw[p] = w;
        g_pos[t * 2 + k] = p;
    }
}

// ======================= weight preprocessing (2 batched launches) =======================
// shape A: src [H, I] -> dst [I, H]   (Wg z=0..7, Wu z=8..15, sWg z=16, sWu z=17)
__global__ void __launch_bounds__(256) trans_w1_kernel(const float* __restrict__ Wg,
                                                       const float* __restrict__ Wu,
                                                       const float* __restrict__ sWg,
                                                       const float* __restrict__ sWu) {
    const int z = blockIdx.z;
    const float* src;
    hf* dst;
    if (z < 8)       { src = Wg + (size_t)z * H_DIM * I_DIM;        dst = g_wgT + (size_t)z * I_DIM * H_DIM; }
    else if (z < 16) { src = Wu + (size_t)(z - 8) * H_DIM * I_DIM;  dst = g_wuT + (size_t)(z - 8) * I_DIM * H_DIM; }
    else if (z == 16){ src = sWg;                                   dst = g_swgT; }
    else             { src = sWu;                                   dst = g_swuT; }

    __shared__ float t[32][33];
    const int c0 = blockIdx.x * 32, r0 = blockIdx.y * 32;   // c over I, r over H
    const int tx = threadIdx.x & 31, ty = threadIdx.x >> 5;
#pragma unroll
    for (int j = 0; j < 32; j += 8)
        t[ty + j][tx] = src[(size_t)(r0 + ty + j) * I_DIM + c0 + tx];
    __syncthreads();
#pragma unroll
    for (int j = 0; j < 32; j += 8)
        dst[(size_t)(c0 + ty + j) * H_DIM + r0 + tx] = __float2half_rn(t[tx][ty + j]);
}

// shape B: src [I, H] -> dst [H, I]   (Wd z=0..7, sWd z=8)
__global__ void __launch_bounds__(256) trans_w2_kernel(const float* __restrict__ Wd,
                                                       const float* __restrict__ sWd) {
    const int z = blockIdx.z;
    const float* src;
    hf* dst;
    if (z < 8) { src = Wd + (size_t)z * I_DIM * H_DIM; dst = g_wdT + (size_t)z * H_DIM * I_DIM; }
    else       { src = sWd;                            dst = g_swdT; }

    __shared__ float t[32][33];
    const int c0 = blockIdx.x * 32, r0 = blockIdx.y * 32;   // c over H, r over I
    const int tx = threadIdx.x & 31, ty = threadIdx.x >> 5;
#pragma unroll
    for (int j = 0; j < 32; j += 8)
        t[ty + j][tx] = src[(size_t)(r0 + ty + j) * H_DIM + c0 + tx];
    __syncthreads();
#pragma unroll
    for (int j = 0; j < 32; j += 8)
        dst[(size_t)(c0 + ty + j) * I_DIM + r0 + tx] = __float2half_rn(t[tx][ty + j]);
}

// ======================= gate+up GEMM (fp16 A, z=0..7 routed, z=8 shared) =======================
#define GU_AH  0u
#define GU_BG  16384u
#define GU_BU  24576u
#define GU_STAGE 32768u
#define GU_SMEM  (2 * 32768)

__global__ void __launch_bounds__(256) gu_mma_kernel(const hf* __restrict__ Wg_all,
                                                     const hf* __restrict__ Wu_all,
                                                     const hf* __restrict__ sWg,
                                                     const hf* __restrict__ sWu,
                                                     hf* __restrict__ oInter) {
    const int e      = blockIdx.z;
    const bool SHARED = (e == E_NUM);
    const int cnt = SHARED ? T_TOT : g_cnt[e];
    const int off = SHARED ? NASSIGN : g_off[e];
    const int mb  = blockIdx.y * 128;
    if (mb >= cnt) return;
    const int nb  = blockIdx.x * 64;

    extern __shared__ char dsm[];
    __shared__ int stok[128];
    const uint32_t sb = smem_u32(dsm);

    const int tid = threadIdx.x;
    if (tid < 128) {
        int r = mb + tid;
        if (r >= cnt) r = cnt - 1;
        stok[tid] = SHARED ? r : g_tok[off + r];
    }
    __syncthreads();

    const int cx = tid & 7;
    const int rb = tid >> 3;
    const uint32_t so = (uint32_t)rb * 128u + (uint32_t)(((cx ^ (rb & 7))) * 16);
    const hf* Bg = SHARED ? sWg : Wg_all + (size_t)e * I_DIM * H_DIM;
    const hf* Bu = SHARED ? sWu : Wu_all + (size_t)e * I_DIM * H_DIM;

    const hf *aP[4], *bgP[2], *buP[2];
#pragma unroll
    for (int j = 0; j < 4; j++)
        aP[j] = g_xhi + (size_t)stok[rb + 32 * j] * H_DIM + cx * 8;
#pragma unroll
    for (int j = 0; j < 2; j++) {
        const size_t brow = (size_t)(nb + rb + 32 * j) * H_DIM + cx * 8;
        bgP[j] = Bg + brow;
        buP[j] = Bu + brow;
    }

    const int warp = tid >> 5, lane = tid & 31;
    const int m0 = (warp & 3) * 32;
    const int n0 = (warp >> 2) * 32;
    const int hl = lane >> 4;
    const int l15 = lane & 15;

    uint32_t aRow[2], aXor[2], bRow[2], bXor[2];
#pragma unroll
    for (int mt = 0; mt < 2; mt++) {
        const int r = m0 + mt * 16 + l15;
        aRow[mt] = (uint32_t)r * 128u;
        aXor[mt] = (uint32_t)(r & 7);
    }
#pragma unroll
    for (int p = 0; p < 2; p++) {
        const int r = n0 + p * 16 + l15;
        bRow[p] = (uint32_t)r * 128u;
        bXor[p] = (uint32_t)(r & 7);
    }

    float accg[2][4][4], accu[2][4][4];
#pragma unroll
    for (int mt = 0; mt < 2; mt++)
#pragma unroll
        for (int nt = 0; nt < 4; nt++)
#pragma unroll
            for (int q = 0; q < 4; q++) { accg[mt][nt][q] = 0.0f; accu[mt][nt][q] = 0.0f; }

    const int NCH = H_DIM / KC;   // 16
    {
        const uint32_t d = sb;
#pragma unroll
        for (int j = 0; j < 4; j++) cp16(d + GU_AH + so + j * 4096u, aP[j]);
#pragma unroll
        for (int j = 0; j < 2; j++) {
            cp16(d + GU_BG + so + j * 4096u, bgP[j]);
            cp16(d + GU_BU + so + j * 4096u, buP[j]);
        }
        cp_commit();
    }

    for (int c = 0; c < NCH; c++) {
        if (c + 1 < NCH) {
            const uint32_t d = sb + ((c + 1) & 1) * GU_STAGE;
            const int k0 = (c + 1) * KC;
#pragma unroll
            for (int j = 0; j < 4; j++) cp16(d + GU_AH + so + j * 4096u, aP[j] + k0);
#pragma unroll
            for (int j = 0; j < 2; j++) {
                cp16(d + GU_BG + so + j * 4096u, bgP[j] + k0);
                cp16(d + GU_BU + so + j * 4096u, buP[j] + k0);
            }
            cp_commit();
            cp_wait<1>();
        } else {
            cp_wait<0>();
        }
        __syncthreads();

        const uint32_t st = sb + (c & 1) * GU_STAGE;
#pragma unroll
        for (int kk = 0; kk < 4; kk++) {
            const uint32_t ku = (uint32_t)(2 * kk + hl);
            uint32_t ah[2][4];
#pragma unroll
            for (int mt = 0; mt < 2; mt++)
                ldsm4(ah[mt], st + GU_AH + aRow[mt] + ((ku ^ aXor[mt]) << 4));
            uint32_t bg[2][4], bu[2][4];
#pragma unroll
            for (int p = 0; p < 2; p++) {
                const uint32_t bo = bRow[p] + ((ku ^ bXor[p]) << 4);
                ldsm4(bg[p], st + GU_BG + bo);
                ldsm4(bu[p], st + GU_BU + bo);
            }
#pragma unroll
            for (int mt = 0; mt < 2; mt++)
#pragma unroll
                for (int p = 0; p < 2; p++)
#pragma unroll
                    for (int q = 0; q < 2; q++) {
                        const int nt = 2 * p + q;
                        mma16816(accg[mt][nt], ah[mt], bg[p][q], bg[p][q + 2]);
                        mma16816(accu[mt][nt], ah[mt], bu[p][q], bu[p][q + 2]);
                    }
        }
        __syncthreads();
    }

    // epilogue: inter = fp16(gelu(g)*u)
    const int colq = (lane & 3) * 2;
#pragma unroll
    for (int mt = 0; mt < 2; mt++) {
#pragma unroll
        for (int half = 0; half < 2; half++) {
            const int gm = mb + m0 + mt * 16 + (lane >> 2) + half * 8;
            if (gm >= cnt) continue;
            const size_t orow = (size_t)(off + gm) * I_DIM;
#pragma unroll
            for (int nt = 0; nt < 4; nt++) {
                const float g0 = accg[mt][nt][half * 2 + 0];
                const float g1 = accg[mt][nt][half * 2 + 1];
                const float u0 = accu[mt][nt][half * 2 + 0];
                const float u1 = accu[mt][nt][half * 2 + 1];
                __half2 v = __floats2half2_rn(gelu_exact(g0) * u0, gelu_exact(g1) * u1);
                *(__half2*)(oInter + orow + nb + n0 + nt * 8 + colq) = v;
            }
        }
    }
}

// ======================= down GEMM (single fp16 A; all outputs -> g_dtmp fp16) ===
#define DN_AH 0u
#define DN_B  16384u
#define DN_STAGE 32768u
#define DN_SMEM  (2 * 32768)

__global__ void __launch_bounds__(256) dn_mma_kernel(const hf* __restrict__ Inter,
                                                     const hf* __restrict__ Wd_all,
                                                     const hf* __restrict__ sWd,
                                                     hf* __restrict__ dtmp) {
    const int e      = blockIdx.z;
    const bool SHARED = (e == E_NUM);
    const int cnt = SHARED ? T_TOT : g_cnt[e];
    const int off = SHARED ? NASSIGN : g_off[e];
    const int mb  = blockIdx.y * 128;
    if (mb >= cnt) return;
    const int nb  = blockIdx.x * 128;

    extern __shared__ char dsm[];
    const uint32_t sb = smem_u32(dsm);
    const int tid = threadIdx.x;

    const int cx = tid & 7;
    const int rb = tid >> 3;
    const uint32_t so = (uint32_t)rb * 128u + (uint32_t)(((cx ^ (rb & 7))) * 16);
    const hf* B = SHARED ? sWd : Wd_all + (size_t)e * H_DIM * I_DIM;

    const hf *aP[4], *bP[4];
#pragma unroll
    for (int j = 0; j < 4; j++) {
        int lr = mb + rb + 32 * j;
        if (lr >= cnt) lr = cnt - 1;
        aP[j] = Inter + (size_t)(off + lr) * I_DIM + cx * 8;
        bP[j] = B + (size_t)(nb + rb + 32 * j) * I_DIM + cx * 8;
    }

    const int warp = tid >> 5, lane = tid & 31;
    const int m0 = (warp & 3) * 32;
    const int n0 = (warp >> 2) * 64;
    const int hl = lane >> 4;
    const int l15 = lane & 15;

    uint32_t aRow[2], aXor[2], bRow[4], bXor[4];
#pragma unroll
    for (int mt = 0; mt < 2; mt++) {
        const int r = m0 + mt * 16 + l15;
        aRow[mt] = (uint32_t)r * 128u;
        aXor[mt] = (uint32_t)(r & 7);
    }
#pragma unroll
    for (int p = 0; p < 4; p++) {
        const int r = n0 + p * 16 + l15;
        bRow[p] = (uint32_t)r * 128u;
        bXor[p] = (uint32_t)(r & 7);
    }

    float acc[2][8][4];
#pragma unroll
    for (int mt = 0; mt < 2; mt++)
#pragma unroll
        for (int nt = 0; nt < 8; nt++)
#pragma unroll
            for (int q = 0; q < 4; q++) acc[mt][nt][q] = 0.0f;

    const int NCH = I_DIM / KC;   // 8
    {
        const uint32_t d = sb;
#pragma unroll
        for (int j = 0; j < 4; j++) {
            cp16(d + DN_AH + so + j * 4096u, aP[j]);
            cp16(d + DN_B  + so + j * 4096u, bP[j]);
        }
        cp_commit();
    }

    for (int c = 0; c < NCH; c++) {
        if (c + 1 < NCH) {
            const uint32_t d = sb + ((c + 1) & 1) * DN_STAGE;
            const int k0 = (c + 1) * KC;
#pragma unroll
            for (int j = 0; j < 4; j++) {
                cp16(d + DN_AH + so + j * 4096u, aP[j] + k0);
                cp16(d + DN_B  + so + j * 4096u, bP[j] + k0);
            }
            cp_commit();
            cp_wait<1>();
        } else {
            cp_wait<0>();
        }
        __syncthreads();

        const uint32_t st = sb + (c & 1) * DN_STAGE;
#pragma unroll
        for (int kk = 0; kk < 4; kk++) {
            const uint32_t ku = (uint32_t)(2 * kk + hl);
            uint32_t ah[2][4];
#pragma unroll
            for (int mt = 0; mt < 2; mt++)
                ldsm4(ah[mt], st + DN_AH + aRow[mt] + ((ku ^ aXor[mt]) << 4));
            uint32_t bh[4][4];
#pragma unroll
            for (int p = 0; p < 4; p++)
                ldsm4(bh[p], st + DN_B + bRow[p] + ((ku ^ bXor[p]) << 4));
#pragma unroll
            for (int mt = 0; mt < 2; mt++)
#pragma unroll
                for (int p = 0; p < 4; p++)
#pragma unroll
                    for (int q = 0; q < 2; q++) {
                        const int nt = 2 * p + q;
                        mma16816(acc[mt][nt], ah[mt], bh[p][q], bh[p][q + 2]);
                    }
        }
        __syncthreads();
    }

    const int colq = (lane & 3) * 2;
#pragma unroll
    for (int mt = 0; mt < 2; mt++) {
#pragma unroll
        for (int half = 0; half < 2; half++) {
            const int gm = mb + m0 + mt * 16 + (lane >> 2) + half * 8;
            if (gm >= cnt) continue;
            const float w = SHARED ? 1.0f : g_aw[off + gm];
            hf* op = dtmp + (size_t)(off + gm) * H_DIM + nb + n0 + colq;
#pragma unroll
            for (int nt = 0; nt < 8; nt++) {
                __half2 v = __floats2half2_rn(w * acc[mt][nt][half * 2 + 0],
                                              w * acc[mt][nt][half * 2 + 1]);
                *(__half2*)(op + nt * 8) = v;
            }
        }
    }
}

// ======================= combine: out[t] = sh + a + b (writes every element) =======================
__global__ void __launch_bounds__(256) combine_kernel(float* __restrict__ out) {
    const int t = blockIdx.x;
    const int p0 = g_pos[t * 2 + 0];
    const int p1 = g_pos[t * 2 + 1];
    const int c = threadIdx.x * 4;
    const __half2* a2 = (const __half2*)(g_dtmp + (size_t)p0 * H_DIM + c);
    const __half2* b2 = (const __half2*)(g_dtmp + (size_t)p1 * H_DIM + c);
    const __half2* s2 = (const __half2*)(g_dtmp + (size_t)(NASSIGN + t) * H_DIM + c);
    const float2 a0 = __half22float2(a2[0]), a1 = __half22float2(a2[1]);
    const float2 b0 = __half22float2(b2[0]), b1 = __half22float2(b2[1]);
    const float2 s0 = __half22float2(s2[0]), s1 = __half22float2(s2[1]);
    float4 o;
    o.x = s0.x + a0.x + b0.x;
    o.y = s0.y + a0.y + b0.y;
    o.z = s1.x + a1.x + b1.x;
    o.w = s1.y + a1.y + b1.y;
    *(float4*)(out + (size_t)t * H_DIM + c) = o;
}

// ======================= launch =======================
extern "C" void kernel_launch(void* const* d_in, const int* in_sizes, int n_in,
                              void* d_out, int out_size) {
    const float* X   = (const float*)d_in[0];
    const float* GW  = (const float*)d_in[1];
    const float* Wg  = (const float*)d_in[2];
    const float* Wu  = (const float*)d_in[3];
    const float* Wd  = (const float*)d_in[4];
    const float* sWg = (const float*)d_in[5];
    const float* sWu = (const float*)d_in[6];
    const float* sWd = (const float*)d_in[7];
    float* out = (float*)d_out;

    cudaFuncSetAttribute(gu_mma_kernel, cudaFuncAttributeMaxDynamicSharedMemorySize, GU_SMEM);
    cudaFuncSetAttribute(dn_mma_kernel, cudaFuncAttributeMaxDynamicSharedMemorySize, DN_SMEM);

    hf *wgT, *wuT, *wdT, *sgT, *suT, *sdT, *inter, *dtmp;
    cudaGetSymbolAddress((void**)&wgT, g_wgT);
    cudaGetSymbolAddress((void**)&wuT, g_wuT);
    cudaGetSymbolAddress((void**)&wdT, g_wdT);
    cudaGetSymbolAddress((void**)&sgT, g_swgT);
    cudaGetSymbolAddress((void**)&suT, g_swuT);
    cudaGetSymbolAddress((void**)&sdT, g_swdT);
    cudaGetSymbolAddress((void**)&inter, g_inter);
    cudaGetSymbolAddress((void**)&dtmp, g_dtmp);

    // routing (router also writes fp16(x))
    init_kernel<<<1, 32>>>();
    router_kernel<<<T_TOT / 8, 256>>>(X, GW);
    scan_kernel<<<1, 32>>>();
    scatter_kernel<<<T_TOT / 256, 256>>>();

    // weight preprocessing (2 batched launches)
    trans_w1_kernel<<<dim3(I_DIM / 32, H_DIM / 32, 18), 256>>>(Wg, Wu, sWg, sWu);
    trans_w2_kernel<<<dim3(H_DIM / 32, I_DIM / 32, 9), 256>>>(Wd, sWd);

    // fused gate+up for routed experts (z=0..7) + shared expert (z=8)
    gu_mma_kernel<<<dim3(I_DIM / 64, T_TOT / 128, E_NUM + 1), 256, GU_SMEM>>>(
        wgT, wuT, sgT, suT, inter);
    // fused down: all outputs -> dtmp fp16 (routed weighted, shared w=1)
    dn_mma_kernel<<<dim3(H_DIM / 128, T_TOT / 128, E_NUM + 1), 256, DN_SMEM>>>(
        inter, wdT, sdT, dtmp);
    // out = shared + routed0 + routed1
    combine_kernel<<<T_TOT, 256>>>(out);
}

// round 10
// speedup vs baseline: 2.0053x; 1.0185x over previous
#include <cuda_runtime.h>
#include <cuda_fp16.h>
#include <math.h>
#include <stdint.h>

#define T_TOT   16384
#define H_DIM   1024
#define I_DIM   512
#define E_NUM   8
#define TOPK    2
#define NASSIGN (T_TOT * TOPK)
#define NROWS   (NASSIGN + T_TOT)     // routed assignments + shared-expert rows
#define KC      64

typedef __half hf;

// ======================= scratch =======================
__device__ int   g_topk_idx[NASSIGN];
__device__ float g_topk_w[NASSIGN];
__device__ int   g_cnt[E_NUM];
__device__ int   g_fill[E_NUM];
__device__ int   g_tok[NASSIGN];
__device__ float g_aw[NASSIGN];
__device__ int   g_pos[NASSIGN];

__device__ __align__(16) hf g_xhi[(size_t)T_TOT * H_DIM];          // fp16(x), written by router
__device__ __align__(16) hf g_wgT[(size_t)E_NUM * I_DIM * H_DIM];
__device__ __align__(16) hf g_wuT[(size_t)E_NUM * I_DIM * H_DIM];
__device__ __align__(16) hf g_wdT[(size_t)E_NUM * H_DIM * I_DIM];
__device__ __align__(16) hf g_swgT[(size_t)I_DIM * H_DIM];
__device__ __align__(16) hf g_swuT[(size_t)I_DIM * H_DIM];
__device__ __align__(16) hf g_swdT[(size_t)H_DIM * I_DIM];
__device__ __align__(16) hf g_inter[(size_t)NROWS * I_DIM];        // inter fp16 (routed + shared)
__device__ __align__(16) hf g_dtmp[(size_t)NROWS * H_DIM];         // down outputs fp16 (routed + shared)

// ======================= helpers =======================
__device__ __forceinline__ uint32_t smem_u32(const void* p) {
    uint32_t a;
    asm("{ .reg .u64 t; cvta.to.shared.u64 t, %1; cvt.u32.u64 %0, t; }" : "=r"(a) : "l"(p));
    return a;
}
__device__ __forceinline__ void cp16(uint32_t dst, const void* src) {
    asm volatile("cp.async.cg.shared.global [%0], [%1], 16;" :: "r"(dst), "l"(src));
}
__device__ __forceinline__ void cp_commit() { asm volatile("cp.async.commit_group;" ::: "memory"); }
template <int N>
__device__ __forceinline__ void cp_wait() { asm volatile("cp.async.wait_group %0;" :: "n"(N) : "memory"); }

__device__ __forceinline__ void ldsm4(uint32_t* r, uint32_t addr) {
    asm volatile("ldmatrix.sync.aligned.m8n8.x4.shared.b16 {%0,%1,%2,%3}, [%4];"
                 : "=r"(r[0]), "=r"(r[1]), "=r"(r[2]), "=r"(r[3]) : "r"(addr));
}
__device__ __forceinline__ void mma16816(float* d, const uint32_t* a, uint32_t b0, uint32_t b1) {
    asm volatile("mma.sync.aligned.m16n8k16.row.col.f32.f16.f16.f32 "
                 "{%0,%1,%2,%3}, {%4,%5,%6,%7}, {%8,%9}, {%0,%1,%2,%3};"
                 : "+f"(d[0]), "+f"(d[1]), "+f"(d[2]), "+f"(d[3])
                 : "r"(a[0]), "r"(a[1]), "r"(a[2]), "r"(a[3]), "r"(b0), "r"(b1));
}
__device__ __forceinline__ float gelu_exact(float x) {
    return 0.5f * x * (1.0f + erff(x * 0.70710678118654752f));
}

// ======================= routing (router also emits fp16(x)) =======================
__global__ void init_kernel() {
    if (threadIdx.x < E_NUM) { g_cnt[threadIdx.x] = 0; g_fill[threadIdx.x] = 0; }
}

__global__ void __launch_bounds__(256) router_kernel(const float* __restrict__ X,
                                                     const float* __restrict__ GW) {
    __shared__ float sgw[E_NUM * H_DIM];
    for (int i = threadIdx.x; i < E_NUM * H_DIM; i += 256) sgw[i] = GW[i];
    __syncthreads();
    const int warp = threadIdx.x >> 5, lane = threadIdx.x & 31;
    const int t = blockIdx.x * 8 + warp;
    if (t >= T_TOT) return;
    const float* x = X + (size_t)t * H_DIM;
    hf* xo = g_xhi + (size_t)t * H_DIM;

    float acc[E_NUM];
#pragma unroll
    for (int e = 0; e < E_NUM; e++) acc[e] = 0.0f;

    for (int h = lane * 4; h < H_DIM; h += 128) {
        const float4 v = *(const float4*)(x + h);
        __half2 p0 = __floats2half2_rn(v.x, v.y);
        __half2 p1 = __floats2half2_rn(v.z, v.w);
        uint2 w = {*(uint32_t*)&p0, *(uint32_t*)&p1};
        *(uint2*)(xo + h) = w;
#pragma unroll
        for (int e = 0; e < E_NUM; e++) {
            const float4 g = *(const float4*)(sgw + e * H_DIM + h);
            acc[e] += v.x * g.x + v.y * g.y + v.z * g.z + v.w * g.w;
        }
    }
#pragma unroll
    for (int e = 0; e < E_NUM; e++)
#pragma unroll
        for (int o = 16; o > 0; o >>= 1) acc[e] += __shfl_down_sync(0xffffffffu, acc[e], o);
    if (lane == 0) {
        float l0 = -1e30f, l1 = -1e30f;
        int i0 = 0, i1 = 0;
#pragma unroll
        for (int e = 0; e < E_NUM; e++) {
            const float v = acc[e];
            if (v > l0)      { l1 = l0; i1 = i0; l0 = v; i0 = e; }
            else if (v > l1) { l1 = v; i1 = e; }
        }
        const float w1 = expf(l1 - l0);
        const float inv = 1.0f / (1.0f + w1);
        g_topk_idx[t * 2 + 0] = i0;
        g_topk_idx[t * 2 + 1] = i1;
        g_topk_w[t * 2 + 0] = inv;
        g_topk_w[t * 2 + 1] = w1 * inv;
        atomicAdd(&g_cnt[i0], 1);
        atomicAdd(&g_cnt[i1], 1);
    }
}

// scatter with inline 8-entry prefix scan (scan kernel removed)
__global__ void __launch_bounds__(256) scatter_kernel() {
    __shared__ int soff[E_NUM];
    if (threadIdx.x == 0) {
        int s = 0;
#pragma unroll
        for (int e = 0; e < E_NUM; e++) { soff[e] = s; s += g_cnt[e]; }
    }
    __syncthreads();
    const int t = blockIdx.x * 256 + threadIdx.x;
    if (t >= T_TOT) return;
#pragma unroll
    for (int k = 0; k < TOPK; k++) {
        const int e = g_topk_idx[t * 2 + k];
        const float w = g_topk_w[t * 2 + k];
        const int p = soff[e] + atomicAdd(&g_fill[e], 1);
        g_tok[p] = t;
        g_aw[p] = w;
        g_pos[t * 2 + k] = p;
    }
}

// ======================= weight preprocessing (side stream) =======================
// shape A: src [H, I] -> dst [I, H]   (Wg z=0..7, Wu z=8..15, sWg z=16, sWu z=17)
__global__ void __launch_bounds__(256) trans_w1_kernel(const float* __restrict__ Wg,
                                                       const float* __restrict__ Wu,
                                                       const float* __restrict__ sWg,
                                                       const float* __restrict__ sWu) {
    const int z = blockIdx.z;
    const float* src;
    hf* dst;
    if (z < 8)       { src = Wg + (size_t)z * H_DIM * I_DIM;        dst = g_wgT + (size_t)z * I_DIM * H_DIM; }
    else if (z < 16) { src = Wu + (size_t)(z - 8) * H_DIM * I_DIM;  dst = g_wuT + (size_t)(z - 8) * I_DIM * H_DIM; }
    else if (z == 16){ src = sWg;                                   dst = g_swgT; }
    else             { src = sWu;                                   dst = g_swuT; }

    __shared__ float t[32][33];
    const int c0 = blockIdx.x * 32, r0 = blockIdx.y * 32;
    const int tx = threadIdx.x & 31, ty = threadIdx.x >> 5;
#pragma unroll
    for (int j = 0; j < 32; j += 8)
        t[ty + j][tx] = src[(size_t)(r0 + ty + j) * I_DIM + c0 + tx];
    __syncthreads();
#pragma unroll
    for (int j = 0; j < 32; j += 8)
        dst[(size_t)(c0 + ty + j) * H_DIM + r0 + tx] = __float2half_rn(t[tx][ty + j]);
}

// shape B: src [I, H] -> dst [H, I]   (Wd z=0..7, sWd z=8)
__global__ void __launch_bounds__(256) trans_w2_kernel(const float* __restrict__ Wd,
                                                       const float* __restrict__ sWd) {
    const int z = blockIdx.z;
    const float* src;
    hf* dst;
    if (z < 8) { src = Wd + (size_t)z * I_DIM * H_DIM; dst = g_wdT + (size_t)z * H_DIM * I_DIM; }
    else       { src = sWd;                            dst = g_swdT; }

    __shared__ float t[32][33];
    const int c0 = blockIdx.x * 32, r0 = blockIdx.y * 32;
    const int tx = threadIdx.x & 31, ty = threadIdx.x >> 5;
#pragma unroll
    for (int j = 0; j < 32; j += 8)
        t[ty + j][tx] = src[(size_t)(r0 + ty + j) * H_DIM + c0 + tx];
    __syncthreads();
#pragma unroll
    for (int j = 0; j < 32; j += 8)
        dst[(size_t)(c0 + ty + j) * I_DIM + r0 + tx] = __float2half_rn(t[tx][ty + j]);
}

// expert offset helper: prefix sum of g_cnt below e (inline, replaces scan kernel)
__device__ __forceinline__ int expert_off(int e) {
    int s = 0;
#pragma unroll
    for (int i = 0; i < E_NUM; i++) {
        const int c = g_cnt[i];
        if (i < e) s += c;
    }
    return s;
}

// ======================= gate+up GEMM (fp16 A, z=0..7 routed, z=8 shared) =======================
#define GU_AH  0u
#define GU_BG  16384u
#define GU_BU  24576u
#define GU_STAGE 32768u
#define GU_SMEM  (2 * 32768)

__global__ void __launch_bounds__(256) gu_mma_kernel(const hf* __restrict__ Wg_all,
                                                     const hf* __restrict__ Wu_all,
                                                     const hf* __restrict__ sWg,
                                                     const hf* __restrict__ sWu,
                                                     hf* __restrict__ oInter) {
    const int e      = blockIdx.z;
    const bool SHARED = (e == E_NUM);
    const int cnt = SHARED ? T_TOT : g_cnt[e];
    const int mb  = blockIdx.y * 128;
    if (mb >= cnt) return;
    const int off = SHARED ? NASSIGN : expert_off(e);
    const int nb  = blockIdx.x * 64;

    extern __shared__ char dsm[];
    __shared__ int stok[128];
    const uint32_t sb = smem_u32(dsm);

    const int tid = threadIdx.x;
    if (tid < 128) {
        int r = mb + tid;
        if (r >= cnt) r = cnt - 1;
        stok[tid] = SHARED ? r : g_tok[off + r];
    }
    __syncthreads();

    const int cx = tid & 7;
    const int rb = tid >> 3;
    const uint32_t so = (uint32_t)rb * 128u + (uint32_t)(((cx ^ (rb & 7))) * 16);
    const hf* Bg = SHARED ? sWg : Wg_all + (size_t)e * I_DIM * H_DIM;
    const hf* Bu = SHARED ? sWu : Wu_all + (size_t)e * I_DIM * H_DIM;

    const hf *aP[4], *bgP[2], *buP[2];
#pragma unroll
    for (int j = 0; j < 4; j++)
        aP[j] = g_xhi + (size_t)stok[rb + 32 * j] * H_DIM + cx * 8;
#pragma unroll
    for (int j = 0; j < 2; j++) {
        const size_t brow = (size_t)(nb + rb + 32 * j) * H_DIM + cx * 8;
        bgP[j] = Bg + brow;
        buP[j] = Bu + brow;
    }

    const int warp = tid >> 5, lane = tid & 31;
    const int m0 = (warp & 3) * 32;
    const int n0 = (warp >> 2) * 32;
    const int hl = lane >> 4;
    const int l15 = lane & 15;

    uint32_t aRow[2], aXor[2], bRow[2], bXor[2];
#pragma unroll
    for (int mt = 0; mt < 2; mt++) {
        const int r = m0 + mt * 16 + l15;
        aRow[mt] = (uint32_t)r * 128u;
        aXor[mt] = (uint32_t)(r & 7);
    }
#pragma unroll
    for (int p = 0; p < 2; p++) {
        const int r = n0 + p * 16 + l15;
        bRow[p] = (uint32_t)r * 128u;
        bXor[p] = (uint32_t)(r & 7);
    }

    float accg[2][4][4], accu[2][4][4];
#pragma unroll
    for (int mt = 0; mt < 2; mt++)
#pragma unroll
        for (int nt = 0; nt < 4; nt++)
#pragma unroll
            for (int q = 0; q < 4; q++) { accg[mt][nt][q] = 0.0f; accu[mt][nt][q] = 0.0f; }

    const int NCH = H_DIM / KC;   // 16
    {
        const uint32_t d = sb;
#pragma unroll
        for (int j = 0; j < 4; j++) cp16(d + GU_AH + so + j * 4096u, aP[j]);
#pragma unroll
        for (int j = 0; j < 2; j++) {
            cp16(d + GU_BG + so + j * 4096u, bgP[j]);
            cp16(d + GU_BU + so + j * 4096u, buP[j]);
        }
        cp_commit();
    }

    for (int c = 0; c < NCH; c++) {
        if (c + 1 < NCH) {
            const uint32_t d = sb + ((c + 1) & 1) * GU_STAGE;
            const int k0 = (c + 1) * KC;
#pragma unroll
            for (int j = 0; j < 4; j++) cp16(d + GU_AH + so + j * 4096u, aP[j] + k0);
#pragma unroll
            for (int j = 0; j < 2; j++) {
                cp16(d + GU_BG + so + j * 4096u, bgP[j] + k0);
                cp16(d + GU_BU + so + j * 4096u, buP[j] + k0);
            }
            cp_commit();
            cp_wait<1>();
        } else {
            cp_wait<0>();
        }
        __syncthreads();

        const uint32_t st = sb + (c & 1) * GU_STAGE;
#pragma unroll
        for (int kk = 0; kk < 4; kk++) {
            const uint32_t ku = (uint32_t)(2 * kk + hl);
            uint32_t ah[2][4];
#pragma unroll
            for (int mt = 0; mt < 2; mt++)
                ldsm4(ah[mt], st + GU_AH + aRow[mt] + ((ku ^ aXor[mt]) << 4));
            uint32_t bg[2][4], bu[2][4];
#pragma unroll
            for (int p = 0; p < 2; p++) {
                const uint32_t bo = bRow[p] + ((ku ^ bXor[p]) << 4);
                ldsm4(bg[p], st + GU_BG + bo);
                ldsm4(bu[p], st + GU_BU + bo);
            }
#pragma unroll
            for (int mt = 0; mt < 2; mt++)
#pragma unroll
                for (int p = 0; p < 2; p++)
#pragma unroll
                    for (int q = 0; q < 2; q++) {
                        const int nt = 2 * p + q;
                        mma16816(accg[mt][nt], ah[mt], bg[p][q], bg[p][q + 2]);
                        mma16816(accu[mt][nt], ah[mt], bu[p][q], bu[p][q + 2]);
                    }
        }
        __syncthreads();
    }

    // epilogue: inter = fp16(gelu(g)*u)
    const int colq = (lane & 3) * 2;
#pragma unroll
    for (int mt = 0; mt < 2; mt++) {
#pragma unroll
        for (int half = 0; half < 2; half++) {
            const int gm = mb + m0 + mt * 16 + (lane >> 2) + half * 8;
            if (gm >= cnt) continue;
            const size_t orow = (size_t)(off + gm) * I_DIM;
#pragma unroll
            for (int nt = 0; nt < 4; nt++) {
                const float g0 = accg[mt][nt][half * 2 + 0];
                const float g1 = accg[mt][nt][half * 2 + 1];
                const float u0 = accu[mt][nt][half * 2 + 0];
                const float u1 = accu[mt][nt][half * 2 + 1];
                __half2 v = __floats2half2_rn(gelu_exact(g0) * u0, gelu_exact(g1) * u1);
                *(__half2*)(oInter + orow + nb + n0 + nt * 8 + colq) = v;
            }
        }
    }
}

// ======================= down GEMM (single fp16 A; all outputs -> g_dtmp fp16) ===
#define DN_AH 0u
#define DN_B  16384u
#define DN_STAGE 32768u
#define DN_SMEM  (2 * 32768)

__global__ void __launch_bounds__(256) dn_mma_kernel(const hf* __restrict__ Inter,
                                                     const hf* __restrict__ Wd_all,
                                                     const hf* __restrict__ sWd,
                                                     hf* __restrict__ dtmp) {
    const int e      = blockIdx.z;
    const bool SHARED = (e == E_NUM);
    const int cnt = SHARED ? T_TOT : g_cnt[e];
    const int mb  = blockIdx.y * 128;
    if (mb >= cnt) return;
    const int off = SHARED ? NASSIGN : expert_off(e);
    const int nb  = blockIdx.x * 128;

    extern __shared__ char dsm[];
    const uint32_t sb = smem_u32(dsm);
    const int tid = threadIdx.x;

    const int cx = tid & 7;
    const int rb = tid >> 3;
    const uint32_t so = (uint32_t)rb * 128u + (uint32_t)(((cx ^ (rb & 7))) * 16);
    const hf* B = SHARED ? sWd : Wd_all + (size_t)e * H_DIM * I_DIM;

    const hf *aP[4], *bP[4];
#pragma unroll
    for (int j = 0; j < 4; j++) {
        int lr = mb + rb + 32 * j;
        if (lr >= cnt) lr = cnt - 1;
        aP[j] = Inter + (size_t)(off + lr) * I_DIM + cx * 8;
        bP[j] = B + (size_t)(nb + rb + 32 * j) * I_DIM + cx * 8;
    }

    const int warp = tid >> 5, lane = tid & 31;
    const int m0 = (warp & 3) * 32;
    const int n0 = (warp >> 2) * 64;
    const int hl = lane >> 4;
    const int l15 = lane & 15;

    uint32_t aRow[2], aXor[2], bRow[4], bXor[4];
#pragma unroll
    for (int mt = 0; mt < 2; mt++) {
        const int r = m0 + mt * 16 + l15;
        aRow[mt] = (uint32_t)r * 128u;
        aXor[mt] = (uint32_t)(r & 7);
    }
#pragma unroll
    for (int p = 0; p < 4; p++) {
        const int r = n0 + p * 16 + l15;
        bRow[p] = (uint32_t)r * 128u;
        bXor[p] = (uint32_t)(r & 7);
    }

    float acc[2][8][4];
#pragma unroll
    for (int mt = 0; mt < 2; mt++)
#pragma unroll
        for (int nt = 0; nt < 8; nt++)
#pragma unroll
            for (int q = 0; q < 4; q++) acc[mt][nt][q] = 0.0f;

    const int NCH = I_DIM / KC;   // 8
    {
        const uint32_t d = sb;
#pragma unroll
        for (int j = 0; j < 4; j++) {
            cp16(d + DN_AH + so + j * 4096u, aP[j]);
            cp16(d + DN_B  + so + j * 4096u, bP[j]);
        }
        cp_commit();
    }

    for (int c = 0; c < NCH; c++) {
        if (c + 1 < NCH) {
            const uint32_t d = sb + ((c + 1) & 1) * DN_STAGE;
            const int k0 = (c + 1) * KC;
#pragma unroll
            for (int j = 0; j < 4; j++) {
                cp16(d + DN_AH + so + j * 4096u, aP[j] + k0);
                cp16(d + DN_B  + so + j * 4096u, bP[j] + k0);
            }
            cp_commit();
            cp_wait<1>();
        } else {
            cp_wait<0>();
        }
        __syncthreads();

        const uint32_t st = sb + (c & 1) * DN_STAGE;
#pragma unroll
        for (int kk = 0; kk < 4; kk++) {
            const uint32_t ku = (uint32_t)(2 * kk + hl);
            uint32_t ah[2][4];
#pragma unroll
            for (int mt = 0; mt < 2; mt++)
                ldsm4(ah[mt], st + DN_AH + aRow[mt] + ((ku ^ aXor[mt]) << 4));
            uint32_t bh[4][4];
#pragma unroll
            for (int p = 0; p < 4; p++)
                ldsm4(bh[p], st + DN_B + bRow[p] + ((ku ^ bXor[p]) << 4));
#pragma unroll
            for (int mt = 0; mt < 2; mt++)
#pragma unroll
                for (int p = 0; p < 4; p++)
#pragma unroll
                    for (int q = 0; q < 2; q++) {
                        const int nt = 2 * p + q;
                        mma16816(acc[mt][nt], ah[mt], bh[p][q], bh[p][q + 2]);
                    }
        }
        __syncthreads();
    }

    const int colq = (lane & 3) * 2;
#pragma unroll
    for (int mt = 0; mt < 2; mt++) {
#pragma unroll
        for (int half = 0; half < 2; half++) {
            const int gm = mb + m0 + mt * 16 + (lane >> 2) + half * 8;
            if (gm >= cnt) continue;
            const float w = SHARED ? 1.0f : g_aw[off + gm];
            hf* op = dtmp + (size_t)(off + gm) * H_DIM + nb + n0 + colq;
#pragma unroll
            for (int nt = 0; nt < 8; nt++) {
                __half2 v = __floats2half2_rn(w * acc[mt][nt][half * 2 + 0],
                                              w * acc[mt][nt][half * 2 + 1]);
                *(__half2*)(op + nt * 8) = v;
            }
        }
    }
}

// ======================= combine: out[t] = sh + a + b (2 tokens/block, 8 floats/thread) ==========
__global__ void __launch_bounds__(256) combine_kernel(float* __restrict__ out) {
    const int t = blockIdx.x * 2 + (threadIdx.x >> 7);
    const int c = (threadIdx.x & 127) * 8;
    const int p0 = g_pos[t * 2 + 0];
    const int p1 = g_pos[t * 2 + 1];
    const uint4 av = *(const uint4*)(g_dtmp + (size_t)p0 * H_DIM + c);
    const uint4 bv = *(const uint4*)(g_dtmp + (size_t)p1 * H_DIM + c);
    const uint4 sv = *(const uint4*)(g_dtmp + (size_t)(NASSIGN + t) * H_DIM + c);
    const uint32_t aw[4] = {av.x, av.y, av.z, av.w};
    const uint32_t bw[4] = {bv.x, bv.y, bv.z, bv.w};
    const uint32_t sw[4] = {sv.x, sv.y, sv.z, sv.w};
    float o[8];
#pragma unroll
    for (int i = 0; i < 4; i++) {
        const float2 a = __half22float2(*(const __half2*)&aw[i]);
        const float2 b = __half22float2(*(const __half2*)&bw[i]);
        const float2 s = __half22float2(*(const __half2*)&sw[i]);
        o[i * 2 + 0] = s.x + a.x + b.x;
        o[i * 2 + 1] = s.y + a.y + b.y;
    }
    float* op = out + (size_t)t * H_DIM + c;
    *(float4*)(op + 0) = make_float4(o[0], o[1], o[2], o[3]);
    *(float4*)(op + 4) = make_float4(o[4], o[5], o[6], o[7]);
}

// ======================= launch =======================
extern "C" void kernel_launch(void* const* d_in, const int* in_sizes, int n_in,
                              void* d_out, int out_size) {
    const float* X   = (const float*)d_in[0];
    const float* GW  = (const float*)d_in[1];
    const float* Wg  = (const float*)d_in[2];
    const float* Wu  = (const float*)d_in[3];
    const float* Wd  = (const float*)d_in[4];
    const float* sWg = (const float*)d_in[5];
    const float* sWu = (const float*)d_in[6];
    const float* sWd = (const float*)d_in[7];
    float* out = (float*)d_out;

    // one-time setup (runs during the uncaptured correctness call; reused under capture)
    static cudaStream_t s_side = nullptr;
    static cudaEvent_t  s_evFork = nullptr, s_evJoin = nullptr;
    if (s_side == nullptr) {
        cudaStreamCreateWithFlags(&s_side, cudaStreamNonBlocking);
        cudaEventCreateWithFlags(&s_evFork, cudaEventDisableTiming);
        cudaEventCreateWithFlags(&s_evJoin, cudaEventDisableTiming);
        cudaFuncSetAttribute(gu_mma_kernel, cudaFuncAttributeMaxDynamicSharedMemorySize, GU_SMEM);
        cudaFuncSetAttribute(dn_mma_kernel, cudaFuncAttributeMaxDynamicSharedMemorySize, DN_SMEM);
    }

    hf *wgT, *wuT, *wdT, *sgT, *suT, *sdT, *inter, *dtmp;
    cudaGetSymbolAddress((void**)&wgT, g_wgT);
    cudaGetSymbolAddress((void**)&wuT, g_wuT);
    cudaGetSymbolAddress((void**)&wdT, g_wdT);
    cudaGetSymbolAddress((void**)&sgT, g_swgT);
    cudaGetSymbolAddress((void**)&suT, g_swuT);
    cudaGetSymbolAddress((void**)&sdT, g_swdT);
    cudaGetSymbolAddress((void**)&inter, g_inter);
    cudaGetSymbolAddress((void**)&dtmp, g_dtmp);

    // fork: weight preprocessing on side stream, overlapping the routing chain
    cudaEventRecord(s_evFork, (cudaStream_t)0);
    cudaStreamWaitEvent(s_side, s_evFork, 0);
    trans_w1_kernel<<<dim3(I_DIM / 32, H_DIM / 32, 18), 256, 0, s_side>>>(Wg, Wu, sWg, sWu);
    trans_w2_kernel<<<dim3(H_DIM / 32, I_DIM / 32, 9), 256, 0, s_side>>>(Wd, sWd);
    cudaEventRecord(s_evJoin, s_side);

    // routing chain on main stream (router also writes fp16(x))
    init_kernel<<<1, 32>>>();
    router_kernel<<<T_TOT / 8, 256>>>(X, GW);
    scatter_kernel<<<T_TOT / 256, 256>>>();

    // join: GEMMs need both routing results and converted weights
    cudaStreamWaitEvent((cudaStream_t)0, s_evJoin, 0);

    // fused gate+up for routed experts (z=0..7) + shared expert (z=8)
    gu_mma_kernel<<<dim3(I_DIM / 64, T_TOT / 128, E_NUM + 1), 256, GU_SMEM>>>(
        wgT, wuT, sgT, suT, inter);
    // fused down: all outputs -> dtmp fp16 (routed weighted, shared w=1)
    dn_mma_kernel<<<dim3(H_DIM / 128, T_TOT / 128, E_NUM + 1), 256, DN_SMEM>>>(
        inter, wdT, sdT, dtmp);
    // out = shared + routed0 + routed1
    combine_kernel<<<T_TOT / 2, 256>>>(out);
}

// round 11
// speedup vs baseline: 2.0154x; 1.0050x over previous
#include <cuda_runtime.h>
#include <cuda_fp16.h>
#include <math.h>
#include <stdint.h>

#define T_TOT   16384
#define H_DIM   1024
#define I_DIM   512
#define E_NUM   8
#define TOPK    2
#define NASSIGN (T_TOT * TOPK)
#define NROWS   (NASSIGN + T_TOT)
#define KC      64

typedef __half hf;

// ======================= scratch =======================
__device__ int   g_topk_idx[NASSIGN];
__device__ float g_topk_w[NASSIGN];
__device__ int   g_cnt[E_NUM];
__device__ int   g_fill[E_NUM];
__device__ int   g_tok[NASSIGN];
__device__ float g_aw[NASSIGN];
__device__ int   g_pos[NASSIGN];

__device__ __align__(16) hf g_xhi[(size_t)T_TOT * H_DIM];
__device__ __align__(16) hf g_wgT[(size_t)E_NUM * I_DIM * H_DIM];
__device__ __align__(16) hf g_wuT[(size_t)E_NUM * I_DIM * H_DIM];
__device__ __align__(16) hf g_wdT[(size_t)E_NUM * H_DIM * I_DIM];
__device__ __align__(16) hf g_swgT[(size_t)I_DIM * H_DIM];
__device__ __align__(16) hf g_swuT[(size_t)I_DIM * H_DIM];
__device__ __align__(16) hf g_swdT[(size_t)H_DIM * I_DIM];
__device__ __align__(16) hf g_inter[(size_t)NROWS * I_DIM];
__device__ __align__(16) hf g_dtmp[(size_t)NROWS * H_DIM];

// ======================= helpers =======================
__device__ __forceinline__ uint32_t smem_u32(const void* p) {
    uint32_t a;
    asm("{ .reg .u64 t; cvta.to.shared.u64 t, %1; cvt.u32.u64 %0, t; }" : "=r"(a) : "l"(p));
    return a;
}
__device__ __forceinline__ void cp16(uint32_t dst, const void* src) {
    asm volatile("cp.async.cg.shared.global [%0], [%1], 16;" :: "r"(dst), "l"(src));
}
__device__ __forceinline__ void cp_commit() { asm volatile("cp.async.commit_group;" ::: "memory"); }
template <int N>
__device__ __forceinline__ void cp_wait() { asm volatile("cp.async.wait_group %0;" :: "n"(N) : "memory"); }

__device__ __forceinline__ void ldsm4(uint32_t* r, uint32_t addr) {
    asm volatile("ldmatrix.sync.aligned.m8n8.x4.shared.b16 {%0,%1,%2,%3}, [%4];"
                 : "=r"(r[0]), "=r"(r[1]), "=r"(r[2]), "=r"(r[3]) : "r"(addr));
}
__device__ __forceinline__ void mma16816(float* d, const uint32_t* a, uint32_t b0, uint32_t b1) {
    asm volatile("mma.sync.aligned.m16n8k16.row.col.f32.f16.f16.f32 "
                 "{%0,%1,%2,%3}, {%4,%5,%6,%7}, {%8,%9}, {%0,%1,%2,%3};"
                 : "+f"(d[0]), "+f"(d[1]), "+f"(d[2]), "+f"(d[3])
                 : "r"(a[0]), "r"(a[1]), "r"(a[2]), "r"(a[3]), "r"(b0), "r"(b1));
}
__device__ __forceinline__ float gelu_exact(float x) {
    return 0.5f * x * (1.0f + erff(x * 0.70710678118654752f));
}

// ======================= routing =======================
__global__ void init_kernel() {
    if (threadIdx.x < E_NUM) { g_cnt[threadIdx.x] = 0; g_fill[threadIdx.x] = 0; }
}

// 4 tokens per warp: sgw reuse x4, 4 independent global load streams.
__global__ void __launch_bounds__(256) router_kernel(const float* __restrict__ X,
                                                     const float* __restrict__ GW) {
    __shared__ float sgw[E_NUM * H_DIM];
    for (int i = threadIdx.x; i < E_NUM * H_DIM; i += 256) sgw[i] = GW[i];
    __syncthreads();
    const int warp = threadIdx.x >> 5, lane = threadIdx.x & 31;
    const int t0 = blockIdx.x * 32 + warp * 4;
    const float* x0 = X + (size_t)t0 * H_DIM;
    hf* xo0 = g_xhi + (size_t)t0 * H_DIM;

    float acc[4][E_NUM];
#pragma unroll
    for (int k = 0; k < 4; k++)
#pragma unroll
        for (int e = 0; e < E_NUM; e++) acc[k][e] = 0.0f;

    for (int h = lane * 4; h < H_DIM; h += 128) {
        float4 v[4];
#pragma unroll
        for (int k = 0; k < 4; k++) v[k] = *(const float4*)(x0 + (size_t)k * H_DIM + h);
#pragma unroll
        for (int k = 0; k < 4; k++) {
            __half2 p0 = __floats2half2_rn(v[k].x, v[k].y);
            __half2 p1 = __floats2half2_rn(v[k].z, v[k].w);
            uint2 w = {*(uint32_t*)&p0, *(uint32_t*)&p1};
            *(uint2*)(xo0 + (size_t)k * H_DIM + h) = w;
        }
#pragma unroll
        for (int e = 0; e < E_NUM; e++) {
            const float4 g = *(const float4*)(sgw + e * H_DIM + h);
#pragma unroll
            for (int k = 0; k < 4; k++)
                acc[k][e] += v[k].x * g.x + v[k].y * g.y + v[k].z * g.z + v[k].w * g.w;
        }
    }
#pragma unroll
    for (int k = 0; k < 4; k++)
#pragma unroll
        for (int e = 0; e < E_NUM; e++)
#pragma unroll
            for (int o = 16; o > 0; o >>= 1)
                acc[k][e] += __shfl_down_sync(0xffffffffu, acc[k][e], o);

#pragma unroll
    for (int k = 0; k < 4; k++) {
        if (lane == 0) {
            const int t = t0 + k;
            float l0 = -1e30f, l1 = -1e30f;
            int i0 = 0, i1 = 0;
#pragma unroll
            for (int e = 0; e < E_NUM; e++) {
                const float v = acc[k][e];
                if (v > l0)      { l1 = l0; i1 = i0; l0 = v; i0 = e; }
                else if (v > l1) { l1 = v; i1 = e; }
            }
            const float w1 = expf(l1 - l0);
            const float inv = 1.0f / (1.0f + w1);
            g_topk_idx[t * 2 + 0] = i0;
            g_topk_idx[t * 2 + 1] = i1;
            g_topk_w[t * 2 + 0] = inv;
            g_topk_w[t * 2 + 1] = w1 * inv;
            atomicAdd(&g_cnt[i0], 1);
            atomicAdd(&g_cnt[i1], 1);
        }
    }
}

// scatter with smem-aggregated atomics (8 global atomics per block)
__global__ void __launch_bounds__(256) scatter_kernel() {
    __shared__ int soff[E_NUM];    // global segment starts (prefix of g_cnt)
    __shared__ int scnt[E_NUM];    // block-local counts
    __shared__ int sbase[E_NUM];   // block base within segment
    const int tid = threadIdx.x;
    if (tid < E_NUM) scnt[tid] = 0;
    if (tid == 0) {
        int s = 0;
#pragma unroll
        for (int e = 0; e < E_NUM; e++) { soff[e] = s; s += g_cnt[e]; }
    }
    __syncthreads();
    const int t = blockIdx.x * 256 + tid;
    const int e0 = g_topk_idx[t * 2 + 0];
    const int e1 = g_topk_idx[t * 2 + 1];
    const int r0 = atomicAdd(&scnt[e0], 1);
    const int r1 = atomicAdd(&scnt[e1], 1);
    __syncthreads();
    if (tid < E_NUM) sbase[tid] = atomicAdd(&g_fill[tid], scnt[tid]);
    __syncthreads();
    const int p0 = soff[e0] + sbase[e0] + r0;
    const int p1 = soff[e1] + sbase[e1] + r1;
    g_tok[p0] = t;  g_aw[p0] = g_topk_w[t * 2 + 0];  g_pos[t * 2 + 0] = p0;
    g_tok[p1] = t;  g_aw[p1] = g_topk_w[t * 2 + 1];  g_pos[t * 2 + 1] = p1;
}

// ======================= weight preprocessing (side stream) =======================
__global__ void __launch_bounds__(256) trans_w1_kernel(const float* __restrict__ Wg,
                                                       const float* __restrict__ Wu,
                                                       const float* __restrict__ sWg,
                                                       const float* __restrict__ sWu) {
    const int z = blockIdx.z;
    const float* src;
    hf* dst;
    if (z < 8)       { src = Wg + (size_t)z * H_DIM * I_DIM;        dst = g_wgT + (size_t)z * I_DIM * H_DIM; }
    else if (z < 16) { src = Wu + (size_t)(z - 8) * H_DIM * I_DIM;  dst = g_wuT + (size_t)(z - 8) * I_DIM * H_DIM; }
    else if (z == 16){ src = sWg;                                   dst = g_swgT; }
    else             { src = sWu;                                   dst = g_swuT; }

    __shared__ float t[32][33];
    const int c0 = blockIdx.x * 32, r0 = blockIdx.y * 32;
    const int tx = threadIdx.x & 31, ty = threadIdx.x >> 5;
#pragma unroll
    for (int j = 0; j < 32; j += 8)
        t[ty + j][tx] = src[(size_t)(r0 + ty + j) * I_DIM + c0 + tx];
    __syncthreads();
#pragma unroll
    for (int j = 0; j < 32; j += 8)
        dst[(size_t)(c0 + ty + j) * H_DIM + r0 + tx] = __float2half_rn(t[tx][ty + j]);
}

__global__ void __launch_bounds__(256) trans_w2_kernel(const float* __restrict__ Wd,
                                                       const float* __restrict__ sWd) {
    const int z = blockIdx.z;
    const float* src;
    hf* dst;
    if (z < 8) { src = Wd + (size_t)z * I_DIM * H_DIM; dst = g_wdT + (size_t)z * H_DIM * I_DIM; }
    else       { src = sWd;                            dst = g_swdT; }

    __shared__ float t[32][33];
    const int c0 = blockIdx.x * 32, r0 = blockIdx.y * 32;
    const int tx = threadIdx.x & 31, ty = threadIdx.x >> 5;
#pragma unroll
    for (int j = 0; j < 32; j += 8)
        t[ty + j][tx] = src[(size_t)(r0 + ty + j) * H_DIM + c0 + tx];
    __syncthreads();
#pragma unroll
    for (int j = 0; j < 32; j += 8)
        dst[(size_t)(c0 + ty + j) * I_DIM + r0 + tx] = __float2half_rn(t[tx][ty + j]);
}

__device__ __forceinline__ int expert_off(int e) {
    int s = 0;
#pragma unroll
    for (int i = 0; i < E_NUM; i++) {
        const int c = g_cnt[i];
        if (i < e) s += c;
    }
    return s;
}

// ======================= gate+up GEMM =======================
#define GU_AH  0u
#define GU_BG  16384u
#define GU_BU  24576u
#define GU_STAGE 32768u
#define GU_SMEM  (2 * 32768)

__global__ void __launch_bounds__(256) gu_mma_kernel(const hf* __restrict__ Wg_all,
                                                     const hf* __restrict__ Wu_all,
                                                     const hf* __restrict__ sWg,
                                                     const hf* __restrict__ sWu,
                                                     hf* __restrict__ oInter) {
    const int e      = blockIdx.z;
    const bool SHARED = (e == E_NUM);
    const int cnt = SHARED ? T_TOT : g_cnt[e];
    const int mb  = blockIdx.y * 128;
    if (mb >= cnt) return;
    const int off = SHARED ? NASSIGN : expert_off(e);
    const int nb  = blockIdx.x * 64;

    extern __shared__ char dsm[];
    __shared__ int stok[128];
    const uint32_t sb = smem_u32(dsm);

    const int tid = threadIdx.x;
    if (tid < 128) {
        int r = mb + tid;
        if (r >= cnt) r = cnt - 1;
        stok[tid] = SHARED ? r : g_tok[off + r];
    }
    __syncthreads();

    const int cx = tid & 7;
    const int rb = tid >> 3;
    const uint32_t so = (uint32_t)rb * 128u + (uint32_t)(((cx ^ (rb & 7))) * 16);
    const hf* Bg = SHARED ? sWg : Wg_all + (size_t)e * I_DIM * H_DIM;
    const hf* Bu = SHARED ? sWu : Wu_all + (size_t)e * I_DIM * H_DIM;

    const hf *aP[4], *bgP[2], *buP[2];
#pragma unroll
    for (int j = 0; j < 4; j++)
        aP[j] = g_xhi + (size_t)stok[rb + 32 * j] * H_DIM + cx * 8;
#pragma unroll
    for (int j = 0; j < 2; j++) {
        const size_t brow = (size_t)(nb + rb + 32 * j) * H_DIM + cx * 8;
        bgP[j] = Bg + brow;
        buP[j] = Bu + brow;
    }

    const int warp = tid >> 5, lane = tid & 31;
    const int m0 = (warp & 3) * 32;
    const int n0 = (warp >> 2) * 32;
    const int hl = lane >> 4;
    const int l15 = lane & 15;

    uint32_t aRow[2], aXor[2], bRow[2], bXor[2];
#pragma unroll
    for (int mt = 0; mt < 2; mt++) {
        const int r = m0 + mt * 16 + l15;
        aRow[mt] = (uint32_t)r * 128u;
        aXor[mt] = (uint32_t)(r & 7);
    }
#pragma unroll
    for (int p = 0; p < 2; p++) {
        const int r = n0 + p * 16 + l15;
        bRow[p] = (uint32_t)r * 128u;
        bXor[p] = (uint32_t)(r & 7);
    }

    float accg[2][4][4], accu[2][4][4];
#pragma unroll
    for (int mt = 0; mt < 2; mt++)
#pragma unroll
        for (int nt = 0; nt < 4; nt++)
#pragma unroll
            for (int q = 0; q < 4; q++) { accg[mt][nt][q] = 0.0f; accu[mt][nt][q] = 0.0f; }

    const int NCH = H_DIM / KC;   // 16
    {
        const uint32_t d = sb;
#pragma unroll
        for (int j = 0; j < 4; j++) cp16(d + GU_AH + so + j * 4096u, aP[j]);
#pragma unroll
        for (int j = 0; j < 2; j++) {
            cp16(d + GU_BG + so + j * 4096u, bgP[j]);
            cp16(d + GU_BU + so + j * 4096u, buP[j]);
        }
        cp_commit();
    }

    for (int c = 0; c < NCH; c++) {
        if (c + 1 < NCH) {
            const uint32_t d = sb + ((c + 1) & 1) * GU_STAGE;
            const int k0 = (c + 1) * KC;
#pragma unroll
            for (int j = 0; j < 4; j++) cp16(d + GU_AH + so + j * 4096u, aP[j] + k0);
#pragma unroll
            for (int j = 0; j < 2; j++) {
                cp16(d + GU_BG + so + j * 4096u, bgP[j] + k0);
                cp16(d + GU_BU + so + j * 4096u, buP[j] + k0);
            }
            cp_commit();
            cp_wait<1>();
        } else {
            cp_wait<0>();
        }
        __syncthreads();

        const uint32_t st = sb + (c & 1) * GU_STAGE;
#pragma unroll
        for (int kk = 0; kk < 4; kk++) {
            const uint32_t ku = (uint32_t)(2 * kk + hl);
            uint32_t ah[2][4];
#pragma unroll
            for (int mt = 0; mt < 2; mt++)
                ldsm4(ah[mt], st + GU_AH + aRow[mt] + ((ku ^ aXor[mt]) << 4));
            uint32_t bg[2][4], bu[2][4];
#pragma unroll
            for (int p = 0; p < 2; p++) {
                const uint32_t bo = bRow[p] + ((ku ^ bXor[p]) << 4);
                ldsm4(bg[p], st + GU_BG + bo);
                ldsm4(bu[p], st + GU_BU + bo);
            }
#pragma unroll
            for (int mt = 0; mt < 2; mt++)
#pragma unroll
                for (int p = 0; p < 2; p++)
#pragma unroll
                    for (int q = 0; q < 2; q++) {
                        const int nt = 2 * p + q;
                        mma16816(accg[mt][nt], ah[mt], bg[p][q], bg[p][q + 2]);
                        mma16816(accu[mt][nt], ah[mt], bu[p][q], bu[p][q + 2]);
                    }
        }
        __syncthreads();
    }

    const int colq = (lane & 3) * 2;
#pragma unroll
    for (int mt = 0; mt < 2; mt++) {
#pragma unroll
        for (int half = 0; half < 2; half++) {
            const int gm = mb + m0 + mt * 16 + (lane >> 2) + half * 8;
            if (gm >= cnt) continue;
            const size_t orow = (size_t)(off + gm) * I_DIM;
#pragma unroll
            for (int nt = 0; nt < 4; nt++) {
                const float g0 = accg[mt][nt][half * 2 + 0];
                const float g1 = accg[mt][nt][half * 2 + 1];
                const float u0 = accu[mt][nt][half * 2 + 0];
                const float u1 = accu[mt][nt][half * 2 + 1];
                __half2 v = __floats2half2_rn(gelu_exact(g0) * u0, gelu_exact(g1) * u1);
                *(__half2*)(oInter + orow + nb + n0 + nt * 8 + colq) = v;
            }
        }
    }
}

// ======================= down GEMM =======================
#define DN_AH 0u
#define DN_B  16384u
#define DN_STAGE 32768u
#define DN_SMEM  (2 * 32768)

__global__ void __launch_bounds__(256) dn_mma_kernel(const hf* __restrict__ Inter,
                                                     const hf* __restrict__ Wd_all,
                                                     const hf* __restrict__ sWd,
                                                     hf* __restrict__ dtmp) {
    const int e      = blockIdx.z;
    const bool SHARED = (e == E_NUM);
    const int cnt = SHARED ? T_TOT : g_cnt[e];
    const int mb  = blockIdx.y * 128;
    if (mb >= cnt) return;
    const int off = SHARED ? NASSIGN : expert_off(e);
    const int nb  = blockIdx.x * 128;

    extern __shared__ char dsm[];
    const uint32_t sb = smem_u32(dsm);
    const int tid = threadIdx.x;

    const int cx = tid & 7;
    const int rb = tid >> 3;
    const uint32_t so = (uint32_t)rb * 128u + (uint32_t)(((cx ^ (rb & 7))) * 16);
    const hf* B = SHARED ? sWd : Wd_all + (size_t)e * H_DIM * I_DIM;

    const hf *aP[4], *bP[4];
#pragma unroll
    for (int j = 0; j < 4; j++) {
        int lr = mb + rb + 32 * j;
        if (lr >= cnt) lr = cnt - 1;
        aP[j] = Inter + (size_t)(off + lr) * I_DIM + cx * 8;
        bP[j] = B + (size_t)(nb + rb + 32 * j) * I_DIM + cx * 8;
    }

    const int warp = tid >> 5, lane = tid & 31;
    const int m0 = (warp & 3) * 32;
    const int n0 = (warp >> 2) * 64;
    const int hl = lane >> 4;
    const int l15 = lane & 15;

    uint32_t aRow[2], aXor[2], bRow[4], bXor[4];
#pragma unroll
    for (int mt = 0; mt < 2; mt++) {
        const int r = m0 + mt * 16 + l15;
        aRow[mt] = (uint32_t)r * 128u;
        aXor[mt] = (uint32_t)(r & 7);
    }
#pragma unroll
    for (int p = 0; p < 4; p++) {
        const int r = n0 + p * 16 + l15;
        bRow[p] = (uint32_t)r * 128u;
        bXor[p] = (uint32_t)(r & 7);
    }

    float acc[2][8][4];
#pragma unroll
    for (int mt = 0; mt < 2; mt++)
#pragma unroll
        for (int nt = 0; nt < 8; nt++)
#pragma unroll
            for (int q = 0; q < 4; q++) acc[mt][nt][q] = 0.0f;

    const int NCH = I_DIM / KC;   // 8
    {
        const uint32_t d = sb;
#pragma unroll
        for (int j = 0; j < 4; j++) {
            cp16(d + DN_AH + so + j * 4096u, aP[j]);
            cp16(d + DN_B  + so + j * 4096u, bP[j]);
        }
        cp_commit();
    }

    for (int c = 0; c < NCH; c++) {
        if (c + 1 < NCH) {
            const uint32_t d = sb + ((c + 1) & 1) * DN_STAGE;
            const int k0 = (c + 1) * KC;
#pragma unroll
            for (int j = 0; j < 4; j++) {
                cp16(d + DN_AH + so + j * 4096u, aP[j] + k0);
                cp16(d + DN_B  + so + j * 4096u, bP[j] + k0);
            }
            cp_commit();
            cp_wait<1>();
        } else {
            cp_wait<0>();
        }
        __syncthreads();

        const uint32_t st = sb + (c & 1) * DN_STAGE;
#pragma unroll
        for (int kk = 0; kk < 4; kk++) {
            const uint32_t ku = (uint32_t)(2 * kk + hl);
            uint32_t ah[2][4];
#pragma unroll
            for (int mt = 0; mt < 2; mt++)
                ldsm4(ah[mt], st + DN_AH + aRow[mt] + ((ku ^ aXor[mt]) << 4));
            uint32_t bh[4][4];
#pragma unroll
            for (int p = 0; p < 4; p++)
                ldsm4(bh[p], st + DN_B + bRow[p] + ((ku ^ bXor[p]) << 4));
#pragma unroll
            for (int mt = 0; mt < 2; mt++)
#pragma unroll
                for (int p = 0; p < 4; p++)
#pragma unroll
                    for (int q = 0; q < 2; q++) {
                        const int nt = 2 * p + q;
                        mma16816(acc[mt][nt], ah[mt], bh[p][q], bh[p][q + 2]);
                    }
        }
        __syncthreads();
    }

    const int colq = (lane & 3) * 2;
#pragma unroll
    for (int mt = 0; mt < 2; mt++) {
#pragma unroll
        for (int half = 0; half < 2; half++) {
            const int gm = mb + m0 + mt * 16 + (lane >> 2) + half * 8;
            if (gm >= cnt) continue;
            const float w = SHARED ? 1.0f : g_aw[off + gm];
            hf* op = dtmp + (size_t)(off + gm) * H_DIM + nb + n0 + colq;
#pragma unroll
            for (int nt = 0; nt < 8; nt++) {
                __half2 v = __floats2half2_rn(w * acc[mt][nt][half * 2 + 0],
                                              w * acc[mt][nt][half * 2 + 1]);
                *(__half2*)(op + nt * 8) = v;
            }
        }
    }
}

// ======================= combine =======================
__global__ void __launch_bounds__(256) combine_kernel(float* __restrict__ out) {
    const int t = blockIdx.x * 2 + (threadIdx.x >> 7);
    const int c = (threadIdx.x & 127) * 8;
    const int p0 = g_pos[t * 2 + 0];
    const int p1 = g_pos[t * 2 + 1];
    const uint4 av = *(const uint4*)(g_dtmp + (size_t)p0 * H_DIM + c);
    const uint4 bv = *(const uint4*)(g_dtmp + (size_t)p1 * H_DIM + c);
    const uint4 sv = *(const uint4*)(g_dtmp + (size_t)(NASSIGN + t) * H_DIM + c);
    const uint32_t aw[4] = {av.x, av.y, av.z, av.w};
    const uint32_t bw[4] = {bv.x, bv.y, bv.z, bv.w};
    const uint32_t sw[4] = {sv.x, sv.y, sv.z, sv.w};
    float o[8];
#pragma unroll
    for (int i = 0; i < 4; i++) {
        const float2 a = __half22float2(*(const __half2*)&aw[i]);
        const float2 b = __half22float2(*(const __half2*)&bw[i]);
        const float2 s = __half22float2(*(const __half2*)&sw[i]);
        o[i * 2 + 0] = s.x + a.x + b.x;
        o[i * 2 + 1] = s.y + a.y + b.y;
    }
    float* op = out + (size_t)t * H_DIM + c;
    *(float4*)(op + 0) = make_float4(o[0], o[1], o[2], o[3]);
    *(float4*)(op + 4) = make_float4(o[4], o[5], o[6], o[7]);
}

// ======================= launch =======================
extern "C" void kernel_launch(void* const* d_in, const int* in_sizes, int n_in,
                              void* d_out, int out_size) {
    const float* X   = (const float*)d_in[0];
    const float* GW  = (const float*)d_in[1];
    const float* Wg  = (const float*)d_in[2];
    const float* Wu  = (const float*)d_in[3];
    const float* Wd  = (const float*)d_in[4];
    const float* sWg = (const float*)d_in[5];
    const float* sWu = (const float*)d_in[6];
    const float* sWd = (const float*)d_in[7];
    float* out = (float*)d_out;

    static cudaStream_t s_side = nullptr;
    static cudaEvent_t  s_evFork = nullptr, s_evJoin = nullptr;
    if (s_side == nullptr) {
        cudaStreamCreateWithFlags(&s_side, cudaStreamNonBlocking);
        cudaEventCreateWithFlags(&s_evFork, cudaEventDisableTiming);
        cudaEventCreateWithFlags(&s_evJoin, cudaEventDisableTiming);
        cudaFuncSetAttribute(gu_mma_kernel, cudaFuncAttributeMaxDynamicSharedMemorySize, GU_SMEM);
        cudaFuncSetAttribute(dn_mma_kernel, cudaFuncAttributeMaxDynamicSharedMemorySize, DN_SMEM);
    }

    hf *wgT, *wuT, *wdT, *sgT, *suT, *sdT, *inter, *dtmp;
    cudaGetSymbolAddress((void**)&wgT, g_wgT);
    cudaGetSymbolAddress((void**)&wuT, g_wuT);
    cudaGetSymbolAddress((void**)&wdT, g_wdT);
    cudaGetSymbolAddress((void**)&sgT, g_swgT);
    cudaGetSymbolAddress((void**)&suT, g_swuT);
    cudaGetSymbolAddress((void**)&sdT, g_swdT);
    cudaGetSymbolAddress((void**)&inter, g_inter);
    cudaGetSymbolAddress((void**)&dtmp, g_dtmp);

    // fork: weight preprocessing on side stream, overlapping the routing chain
    cudaEventRecord(s_evFork, (cudaStream_t)0);
    cudaStreamWaitEvent(s_side, s_evFork, 0);
    trans_w1_kernel<<<dim3(I_DIM / 32, H_DIM / 32, 18), 256, 0, s_side>>>(Wg, Wu, sWg, sWu);
    trans_w2_kernel<<<dim3(H_DIM / 32, I_DIM / 32, 9), 256, 0, s_side>>>(Wd, sWd);
    cudaEventRecord(s_evJoin, s_side);

    // routing chain on main stream (router also writes fp16(x))
    init_kernel<<<1, 32>>>();
    router_kernel<<<T_TOT / 32, 256>>>(X, GW);
    scatter_kernel<<<T_TOT / 256, 256>>>();

    // join: GEMMs need both routing results and converted weights
    cudaStreamWaitEvent((cudaStream_t)0, s_evJoin, 0);

    gu_mma_kernel<<<dim3(I_DIM / 64, T_TOT / 128, E_NUM + 1), 256, GU_SMEM>>>(
        wgT, wuT, sgT, suT, inter);
    dn_mma_kernel<<<dim3(H_DIM / 128, T_TOT / 128, E_NUM + 1), 256, DN_SMEM>>>(
        inter, wdT, sdT, dtmp);
    combine_kernel<<<T_TOT / 2, 256>>>(out);
}

// round 12
// speedup vs baseline: 2.0372x; 1.0108x over previous
#include <cuda_runtime.h>
#include <cuda_fp16.h>
#include <math.h>
#include <stdint.h>

#define T_TOT   16384
#define H_DIM   1024
#define I_DIM   512
#define E_NUM   8
#define TOPK    2
#define NASSIGN (T_TOT * TOPK)
#define NROWS   (NASSIGN + T_TOT)
#define KC      64

typedef __half hf;

// ======================= scratch =======================
__device__ int   g_topk_idx[NASSIGN];
__device__ float g_topk_w[NASSIGN];
__device__ int   g_cnt[E_NUM];
__device__ int   g_fill[E_NUM];
__device__ int   g_tok[NASSIGN];
__device__ float g_aw[NASSIGN];
__device__ int   g_pos[NASSIGN];

__device__ __align__(16) hf g_xhi[(size_t)T_TOT * H_DIM];
__device__ __align__(16) hf g_wgT[(size_t)E_NUM * I_DIM * H_DIM];
__device__ __align__(16) hf g_wuT[(size_t)E_NUM * I_DIM * H_DIM];
__device__ __align__(16) hf g_wdT[(size_t)E_NUM * H_DIM * I_DIM];
__device__ __align__(16) hf g_swgT[(size_t)I_DIM * H_DIM];
__device__ __align__(16) hf g_swuT[(size_t)I_DIM * H_DIM];
__device__ __align__(16) hf g_swdT[(size_t)H_DIM * I_DIM];
__device__ __align__(16) hf g_inter[(size_t)NROWS * I_DIM];
__device__ __align__(16) hf g_dtmp[(size_t)NROWS * H_DIM];

// ======================= helpers =======================
__device__ __forceinline__ uint32_t smem_u32(const void* p) {
    uint32_t a;
    asm("{ .reg .u64 t; cvta.to.shared.u64 t, %1; cvt.u32.u64 %0, t; }" : "=r"(a) : "l"(p));
    return a;
}
__device__ __forceinline__ void cp16(uint32_t dst, const void* src) {
    asm volatile("cp.async.cg.shared.global [%0], [%1], 16;" :: "r"(dst), "l"(src));
}
__device__ __forceinline__ void cp_commit() { asm volatile("cp.async.commit_group;" ::: "memory"); }
template <int N>
__device__ __forceinline__ void cp_wait() { asm volatile("cp.async.wait_group %0;" :: "n"(N) : "memory"); }

__device__ __forceinline__ void ldsm4(uint32_t* r, uint32_t addr) {
    asm volatile("ldmatrix.sync.aligned.m8n8.x4.shared.b16 {%0,%1,%2,%3}, [%4];"
                 : "=r"(r[0]), "=r"(r[1]), "=r"(r[2]), "=r"(r[3]) : "r"(addr));
}
__device__ __forceinline__ void mma16816(float* d, const uint32_t* a, uint32_t b0, uint32_t b1) {
    asm volatile("mma.sync.aligned.m16n8k16.row.col.f32.f16.f16.f32 "
                 "{%0,%1,%2,%3}, {%4,%5,%6,%7}, {%8,%9}, {%0,%1,%2,%3};"
                 : "+f"(d[0]), "+f"(d[1]), "+f"(d[2]), "+f"(d[3])
                 : "r"(a[0]), "r"(a[1]), "r"(a[2]), "r"(a[3]), "r"(b0), "r"(b1));
}
__device__ __forceinline__ float gelu_exact(float x) {
    return 0.5f * x * (1.0f + erff(x * 0.70710678118654752f));
}

// ======================= routing =======================
__global__ void init_kernel() {
    if (threadIdx.x < E_NUM) { g_cnt[threadIdx.x] = 0; g_fill[threadIdx.x] = 0; }
}

__global__ void __launch_bounds__(256) router_kernel(const float* __restrict__ X,
                                                     const float* __restrict__ GW) {
    __shared__ float sgw[E_NUM * H_DIM];
    for (int i = threadIdx.x; i < E_NUM * H_DIM; i += 256) sgw[i] = GW[i];
    __syncthreads();
    const int warp = threadIdx.x >> 5, lane = threadIdx.x & 31;
    const int t0 = blockIdx.x * 32 + warp * 4;
    const float* x0 = X + (size_t)t0 * H_DIM;
    hf* xo0 = g_xhi + (size_t)t0 * H_DIM;

    float acc[4][E_NUM];
#pragma unroll
    for (int k = 0; k < 4; k++)
#pragma unroll
        for (int e = 0; e < E_NUM; e++) acc[k][e] = 0.0f;

    for (int h = lane * 4; h < H_DIM; h += 128) {
        float4 v[4];
#pragma unroll
        for (int k = 0; k < 4; k++) v[k] = *(const float4*)(x0 + (size_t)k * H_DIM + h);
#pragma unroll
        for (int k = 0; k < 4; k++) {
            __half2 p0 = __floats2half2_rn(v[k].x, v[k].y);
            __half2 p1 = __floats2half2_rn(v[k].z, v[k].w);
            uint2 w = {*(uint32_t*)&p0, *(uint32_t*)&p1};
            *(uint2*)(xo0 + (size_t)k * H_DIM + h) = w;
        }
#pragma unroll
        for (int e = 0; e < E_NUM; e++) {
            const float4 g = *(const float4*)(sgw + e * H_DIM + h);
#pragma unroll
            for (int k = 0; k < 4; k++)
                acc[k][e] += v[k].x * g.x + v[k].y * g.y + v[k].z * g.z + v[k].w * g.w;
        }
    }
#pragma unroll
    for (int k = 0; k < 4; k++)
#pragma unroll
        for (int e = 0; e < E_NUM; e++)
#pragma unroll
            for (int o = 16; o > 0; o >>= 1)
                acc[k][e] += __shfl_down_sync(0xffffffffu, acc[k][e], o);

#pragma unroll
    for (int k = 0; k < 4; k++) {
        if (lane == 0) {
            const int t = t0 + k;
            float l0 = -1e30f, l1 = -1e30f;
            int i0 = 0, i1 = 0;
#pragma unroll
            for (int e = 0; e < E_NUM; e++) {
                const float v = acc[k][e];
                if (v > l0)      { l1 = l0; i1 = i0; l0 = v; i0 = e; }
                else if (v > l1) { l1 = v; i1 = e; }
            }
            const float w1 = expf(l1 - l0);
            const float inv = 1.0f / (1.0f + w1);
            g_topk_idx[t * 2 + 0] = i0;
            g_topk_idx[t * 2 + 1] = i1;
            g_topk_w[t * 2 + 0] = inv;
            g_topk_w[t * 2 + 1] = w1 * inv;
            atomicAdd(&g_cnt[i0], 1);
            atomicAdd(&g_cnt[i1], 1);
        }
    }
}

// scatter with smem-aggregated atomics
__global__ void __launch_bounds__(256) scatter_kernel() {
    __shared__ int soff[E_NUM];
    __shared__ int scnt[E_NUM];
    __shared__ int sbase[E_NUM];
    const int tid = threadIdx.x;
    if (tid < E_NUM) scnt[tid] = 0;
    if (tid == 0) {
        int s = 0;
#pragma unroll
        for (int e = 0; e < E_NUM; e++) { soff[e] = s; s += g_cnt[e]; }
    }
    __syncthreads();
    const int t = blockIdx.x * 256 + tid;
    const int e0 = g_topk_idx[t * 2 + 0];
    const int e1 = g_topk_idx[t * 2 + 1];
    const int r0 = atomicAdd(&scnt[e0], 1);
    const int r1 = atomicAdd(&scnt[e1], 1);
    __syncthreads();
    if (tid < E_NUM) sbase[tid] = atomicAdd(&g_fill[tid], scnt[tid]);
    __syncthreads();
    const int p0 = soff[e0] + sbase[e0] + r0;
    const int p1 = soff[e1] + sbase[e1] + r1;
    g_tok[p0] = t;  g_aw[p0] = g_topk_w[t * 2 + 0];  g_pos[t * 2 + 0] = p0;
    g_tok[p1] = t;  g_aw[p1] = g_topk_w[t * 2 + 1];  g_pos[t * 2 + 1] = p1;
}

// ======================= weight preprocessing (side stream) =======================
__global__ void __launch_bounds__(256) trans_w1_kernel(const float* __restrict__ Wg,
                                                       const float* __restrict__ Wu,
                                                       const float* __restrict__ sWg,
                                                       const float* __restrict__ sWu) {
    const int z = blockIdx.z;
    const float* src;
    hf* dst;
    if (z < 8)       { src = Wg + (size_t)z * H_DIM * I_DIM;        dst = g_wgT + (size_t)z * I_DIM * H_DIM; }
    else if (z < 16) { src = Wu + (size_t)(z - 8) * H_DIM * I_DIM;  dst = g_wuT + (size_t)(z - 8) * I_DIM * H_DIM; }
    else if (z == 16){ src = sWg;                                   dst = g_swgT; }
    else             { src = sWu;                                   dst = g_swuT; }

    __shared__ float t[32][33];
    const int c0 = blockIdx.x * 32, r0 = blockIdx.y * 32;
    const int tx = threadIdx.x & 31, ty = threadIdx.x >> 5;
#pragma unroll
    for (int j = 0; j < 32; j += 8)
        t[ty + j][tx] = src[(size_t)(r0 + ty + j) * I_DIM + c0 + tx];
    __syncthreads();
#pragma unroll
    for (int j = 0; j < 32; j += 8)
        dst[(size_t)(c0 + ty + j) * H_DIM + r0 + tx] = __float2half_rn(t[tx][ty + j]);
}

__global__ void __launch_bounds__(256) trans_w2_kernel(const float* __restrict__ Wd,
                                                       const float* __restrict__ sWd) {
    const int z = blockIdx.z;
    const float* src;
    hf* dst;
    if (z < 8) { src = Wd + (size_t)z * I_DIM * H_DIM; dst = g_wdT + (size_t)z * H_DIM * I_DIM; }
    else       { src = sWd;                            dst = g_swdT; }

    __shared__ float t[32][33];
    const int c0 = blockIdx.x * 32, r0 = blockIdx.y * 32;
    const int tx = threadIdx.x & 31, ty = threadIdx.x >> 5;
#pragma unroll
    for (int j = 0; j < 32; j += 8)
        t[ty + j][tx] = src[(size_t)(r0 + ty + j) * H_DIM + c0 + tx];
    __syncthreads();
#pragma unroll
    for (int j = 0; j < 32; j += 8)
        dst[(size_t)(c0 + ty + j) * I_DIM + r0 + tx] = __float2half_rn(t[tx][ty + j]);
}

__device__ __forceinline__ int expert_off(int e) {
    int s = 0;
#pragma unroll
    for (int i = 0; i < E_NUM; i++) {
        const int c = g_cnt[i];
        if (i < e) s += c;
    }
    return s;
}

// ======================= gate+up GEMM (3-stage pipeline, 96KB, 2 CTA/SM) ==============
#define GU_AH  0u
#define GU_BG  16384u
#define GU_BU  24576u
#define GU_STAGE 32768u
#define GU_SMEM  (3 * 32768)

__global__ void __launch_bounds__(256) gu_mma_kernel(const hf* __restrict__ Wg_all,
                                                     const hf* __restrict__ Wu_all,
                                                     const hf* __restrict__ sWg,
                                                     const hf* __restrict__ sWu,
                                                     hf* __restrict__ oInter) {
    const int e      = blockIdx.z;
    const bool SHARED = (e == E_NUM);
    const int cnt = SHARED ? T_TOT : g_cnt[e];
    const int mb  = blockIdx.y * 128;
    if (mb >= cnt) return;
    const int off = SHARED ? NASSIGN : expert_off(e);
    const int nb  = blockIdx.x * 64;

    extern __shared__ char dsm[];
    __shared__ int stok[128];
    const uint32_t sb = smem_u32(dsm);

    const int tid = threadIdx.x;
    if (tid < 128) {
        int r = mb + tid;
        if (r >= cnt) r = cnt - 1;
        stok[tid] = SHARED ? r : g_tok[off + r];
    }
    __syncthreads();

    const int cx = tid & 7;
    const int rb = tid >> 3;
    const uint32_t so = (uint32_t)rb * 128u + (uint32_t)(((cx ^ (rb & 7))) * 16);
    const hf* Bg = SHARED ? sWg : Wg_all + (size_t)e * I_DIM * H_DIM;
    const hf* Bu = SHARED ? sWu : Wu_all + (size_t)e * I_DIM * H_DIM;

    const hf *aP[4], *bgP[2], *buP[2];
#pragma unroll
    for (int j = 0; j < 4; j++)
        aP[j] = g_xhi + (size_t)stok[rb + 32 * j] * H_DIM + cx * 8;
#pragma unroll
    for (int j = 0; j < 2; j++) {
        const size_t brow = (size_t)(nb + rb + 32 * j) * H_DIM + cx * 8;
        bgP[j] = Bg + brow;
        buP[j] = Bu + brow;
    }

    const int warp = tid >> 5, lane = tid & 31;
    const int m0 = (warp & 3) * 32;
    const int n0 = (warp >> 2) * 32;
    const int hl = lane >> 4;
    const int l15 = lane & 15;

    uint32_t aRow[2], aXor[2], bRow[2], bXor[2];
#pragma unroll
    for (int mt = 0; mt < 2; mt++) {
        const int r = m0 + mt * 16 + l15;
        aRow[mt] = (uint32_t)r * 128u;
        aXor[mt] = (uint32_t)(r & 7);
    }
#pragma unroll
    for (int p = 0; p < 2; p++) {
        const int r = n0 + p * 16 + l15;
        bRow[p] = (uint32_t)r * 128u;
        bXor[p] = (uint32_t)(r & 7);
    }

    float accg[2][4][4], accu[2][4][4];
#pragma unroll
    for (int mt = 0; mt < 2; mt++)
#pragma unroll
        for (int nt = 0; nt < 4; nt++)
#pragma unroll
            for (int q = 0; q < 4; q++) { accg[mt][nt][q] = 0.0f; accu[mt][nt][q] = 0.0f; }

    const int NCH = H_DIM / KC;   // 16
    // prologue: chunks 0,1
#pragma unroll
    for (int pc = 0; pc < 2; pc++) {
        const uint32_t d = sb + (uint32_t)pc * GU_STAGE;
        const int k0 = pc * KC;
#pragma unroll
        for (int j = 0; j < 4; j++) cp16(d + GU_AH + so + j * 4096u, aP[j] + k0);
#pragma unroll
        for (int j = 0; j < 2; j++) {
            cp16(d + GU_BG + so + j * 4096u, bgP[j] + k0);
            cp16(d + GU_BU + so + j * 4096u, buP[j] + k0);
        }
        cp_commit();
    }

    int wst = 2;   // stage slot for chunk c+2
    for (int c = 0; c < NCH; c++) {
        cp_wait<1>();
        __syncthreads();
        if (c + 2 < NCH) {
            const uint32_t d = sb + (uint32_t)wst * GU_STAGE;
            const int k0 = (c + 2) * KC;
#pragma unroll
            for (int j = 0; j < 4; j++) cp16(d + GU_AH + so + j * 4096u, aP[j] + k0);
#pragma unroll
            for (int j = 0; j < 2; j++) {
                cp16(d + GU_BG + so + j * 4096u, bgP[j] + k0);
                cp16(d + GU_BU + so + j * 4096u, buP[j] + k0);
            }
        }
        cp_commit();

        const uint32_t st = sb + (uint32_t)((wst + 1) % 3) * GU_STAGE;   // stage of chunk c
        wst = (wst + 1) % 3;
#pragma unroll
        for (int kk = 0; kk < 4; kk++) {
            const uint32_t ku = (uint32_t)(2 * kk + hl);
            uint32_t ah[2][4];
#pragma unroll
            for (int mt = 0; mt < 2; mt++)
                ldsm4(ah[mt], st + GU_AH + aRow[mt] + ((ku ^ aXor[mt]) << 4));
            uint32_t bg[2][4], bu[2][4];
#pragma unroll
            for (int p = 0; p < 2; p++) {
                const uint32_t bo = bRow[p] + ((ku ^ bXor[p]) << 4);
                ldsm4(bg[p], st + GU_BG + bo);
                ldsm4(bu[p], st + GU_BU + bo);
            }
#pragma unroll
            for (int mt = 0; mt < 2; mt++)
#pragma unroll
                for (int p = 0; p < 2; p++)
#pragma unroll
                    for (int q = 0; q < 2; q++) {
                        const int nt = 2 * p + q;
                        mma16816(accg[mt][nt], ah[mt], bg[p][q], bg[p][q + 2]);
                        mma16816(accu[mt][nt], ah[mt], bu[p][q], bu[p][q + 2]);
                    }
        }
    }

    const int colq = (lane & 3) * 2;
#pragma unroll
    for (int mt = 0; mt < 2; mt++) {
#pragma unroll
        for (int half = 0; half < 2; half++) {
            const int gm = mb + m0 + mt * 16 + (lane >> 2) + half * 8;
            if (gm >= cnt) continue;
            const size_t orow = (size_t)(off + gm) * I_DIM;
#pragma unroll
            for (int nt = 0; nt < 4; nt++) {
                const float g0 = accg[mt][nt][half * 2 + 0];
                const float g1 = accg[mt][nt][half * 2 + 1];
                const float u0 = accu[mt][nt][half * 2 + 0];
                const float u1 = accu[mt][nt][half * 2 + 1];
                __half2 v = __floats2half2_rn(gelu_exact(g0) * u0, gelu_exact(g1) * u1);
                *(__half2*)(oInter + orow + nb + n0 + nt * 8 + colq) = v;
            }
        }
    }
}

// ======================= down GEMM (3-stage pipeline, 96KB, 2 CTA/SM) =======================
#define DN_AH 0u
#define DN_B  16384u
#define DN_STAGE 32768u
#define DN_SMEM  (3 * 32768)

__global__ void __launch_bounds__(256) dn_mma_kernel(const hf* __restrict__ Inter,
                                                     const hf* __restrict__ Wd_all,
                                                     const hf* __restrict__ sWd,
                                                     hf* __restrict__ dtmp) {
    const int e      = blockIdx.z;
    const bool SHARED = (e == E_NUM);
    const int cnt = SHARED ? T_TOT : g_cnt[e];
    const int mb  = blockIdx.y * 128;
    if (mb >= cnt) return;
    const int off = SHARED ? NASSIGN : expert_off(e);
    const int nb  = blockIdx.x * 128;

    extern __shared__ char dsm[];
    const uint32_t sb = smem_u32(dsm);
    const int tid = threadIdx.x;

    const int cx = tid & 7;
    const int rb = tid >> 3;
    const uint32_t so = (uint32_t)rb * 128u + (uint32_t)(((cx ^ (rb & 7))) * 16);
    const hf* B = SHARED ? sWd : Wd_all + (size_t)e * H_DIM * I_DIM;

    const hf *aP[4], *bP[4];
#pragma unroll
    for (int j = 0; j < 4; j++) {
        int lr = mb + rb + 32 * j;
        if (lr >= cnt) lr = cnt - 1;
        aP[j] = Inter + (size_t)(off + lr) * I_DIM + cx * 8;
        bP[j] = B + (size_t)(nb + rb + 32 * j) * I_DIM + cx * 8;
    }

    const int warp = tid >> 5, lane = tid & 31;
    const int m0 = (warp & 3) * 32;
    const int n0 = (warp >> 2) * 64;
    const int hl = lane >> 4;
    const int l15 = lane & 15;

    uint32_t aRow[2], aXor[2], bRow[4], bXor[4];
#pragma unroll
    for (int mt = 0; mt < 2; mt++) {
        const int r = m0 + mt * 16 + l15;
        aRow[mt] = (uint32_t)r * 128u;
        aXor[mt] = (uint32_t)(r & 7);
    }
#pragma unroll
    for (int p = 0; p < 4; p++) {
        const int r = n0 + p * 16 + l15;
        bRow[p] = (uint32_t)r * 128u;
        bXor[p] = (uint32_t)(r & 7);
    }

    float acc[2][8][4];
#pragma unroll
    for (int mt = 0; mt < 2; mt++)
#pragma unroll
        for (int nt = 0; nt < 8; nt++)
#pragma unroll
            for (int q = 0; q < 4; q++) acc[mt][nt][q] = 0.0f;

    const int NCH = I_DIM / KC;   // 8
#pragma unroll
    for (int pc = 0; pc < 2; pc++) {
        const uint32_t d = sb + (uint32_t)pc * DN_STAGE;
        const int k0 = pc * KC;
#pragma unroll
        for (int j = 0; j < 4; j++) {
            cp16(d + DN_AH + so + j * 4096u, aP[j] + k0);
            cp16(d + DN_B  + so + j * 4096u, bP[j] + k0);
        }
        cp_commit();
    }

    int wst = 2;
    for (int c = 0; c < NCH; c++) {
        cp_wait<1>();
        __syncthreads();
        if (c + 2 < NCH) {
            const uint32_t d = sb + (uint32_t)wst * DN_STAGE;
            const int k0 = (c + 2) * KC;
#pragma unroll
            for (int j = 0; j < 4; j++) {
                cp16(d + DN_AH + so + j * 4096u, aP[j] + k0);
                cp16(d + DN_B  + so + j * 4096u, bP[j] + k0);
            }
        }
        cp_commit();

        const uint32_t st = sb + (uint32_t)((wst + 1) % 3) * DN_STAGE;
        wst = (wst + 1) % 3;
#pragma unroll
        for (int kk = 0; kk < 4; kk++) {
            const uint32_t ku = (uint32_t)(2 * kk + hl);
            uint32_t ah[2][4];
#pragma unroll
            for (int mt = 0; mt < 2; mt++)
                ldsm4(ah[mt], st + DN_AH + aRow[mt] + ((ku ^ aXor[mt]) << 4));
            uint32_t bh[4][4];
#pragma unroll
            for (int p = 0; p < 4; p++)
                ldsm4(bh[p], st + DN_B + bRow[p] + ((ku ^ bXor[p]) << 4));
#pragma unroll
            for (int mt = 0; mt < 2; mt++)
#pragma unroll
                for (int p = 0; p < 4; p++)
#pragma unroll
                    for (int q = 0; q < 2; q++) {
                        const int nt = 2 * p + q;
                        mma16816(acc[mt][nt], ah[mt], bh[p][q], bh[p][q + 2]);
                    }
        }
    }

    const int colq = (lane & 3) * 2;
#pragma unroll
    for (int mt = 0; mt < 2; mt++) {
#pragma unroll
        for (int half = 0; half < 2; half++) {
            const int gm = mb + m0 + mt * 16 + (lane >> 2) + half * 8;
            if (gm >= cnt) continue;
            const float w = SHARED ? 1.0f : g_aw[off + gm];
            hf* op = dtmp + (size_t)(off + gm) * H_DIM + nb + n0 + colq;
#pragma unroll
            for (int nt = 0; nt < 8; nt++) {
                __half2 v = __floats2half2_rn(w * acc[mt][nt][half * 2 + 0],
                                              w * acc[mt][nt][half * 2 + 1]);
                *(__half2*)(op + nt * 8) = v;
            }
        }
    }
}

// ======================= combine =======================
__global__ void __launch_bounds__(256) combine_kernel(float* __restrict__ out) {
    const int t = blockIdx.x * 2 + (threadIdx.x >> 7);
    const int c = (threadIdx.x & 127) * 8;
    const int p0 = g_pos[t * 2 + 0];
    const int p1 = g_pos[t * 2 + 1];
    const uint4 av = *(const uint4*)(g_dtmp + (size_t)p0 * H_DIM + c);
    const uint4 bv = *(const uint4*)(g_dtmp + (size_t)p1 * H_DIM + c);
    const uint4 sv = *(const uint4*)(g_dtmp + (size_t)(NASSIGN + t) * H_DIM + c);
    const uint32_t aw[4] = {av.x, av.y, av.z, av.w};
    const uint32_t bw[4] = {bv.x, bv.y, bv.z, bv.w};
    const uint32_t sw[4] = {sv.x, sv.y, sv.z, sv.w};
    float o[8];
#pragma unroll
    for (int i = 0; i < 4; i++) {
        const float2 a = __half22float2(*(const __half2*)&aw[i]);
        const float2 b = __half22float2(*(const __half2*)&bw[i]);
        const float2 s = __half22float2(*(const __half2*)&sw[i]);
        o[i * 2 + 0] = s.x + a.x + b.x;
        o[i * 2 + 1] = s.y + a.y + b.y;
    }
    float* op = out + (size_t)t * H_DIM + c;
    *(float4*)(op + 0) = make_float4(o[0], o[1], o[2], o[3]);
    *(float4*)(op + 4) = make_float4(o[4], o[5], o[6], o[7]);
}

// ======================= launch =======================
extern "C" void kernel_launch(void* const* d_in, const int* in_sizes, int n_in,
                              void* d_out, int out_size) {
    const float* X   = (const float*)d_in[0];
    const float* GW  = (const float*)d_in[1];
    const float* Wg  = (const float*)d_in[2];
    const float* Wu  = (const float*)d_in[3];
    const float* Wd  = (const float*)d_in[4];
    const float* sWg = (const float*)d_in[5];
    const float* sWu = (const float*)d_in[6];
    const float* sWd = (const float*)d_in[7];
    float* out = (float*)d_out;

    static cudaStream_t s_side = nullptr;
    static cudaEvent_t  s_evFork = nullptr, s_evJoin = nullptr;
    if (s_side == nullptr) {
        cudaStreamCreateWithFlags(&s_side, cudaStreamNonBlocking);
        cudaEventCreateWithFlags(&s_evFork, cudaEventDisableTiming);
        cudaEventCreateWithFlags(&s_evJoin, cudaEventDisableTiming);
        cudaFuncSetAttribute(gu_mma_kernel, cudaFuncAttributeMaxDynamicSharedMemorySize, GU_SMEM);
        cudaFuncSetAttribute(dn_mma_kernel, cudaFuncAttributeMaxDynamicSharedMemorySize, DN_SMEM);
    }

    hf *wgT, *wuT, *wdT, *sgT, *suT, *sdT, *inter, *dtmp;
    cudaGetSymbolAddress((void**)&wgT, g_wgT);
    cudaGetSymbolAddress((void**)&wuT, g_wuT);
    cudaGetSymbolAddress((void**)&wdT, g_wdT);
    cudaGetSymbolAddress((void**)&sgT, g_swgT);
    cudaGetSymbolAddress((void**)&suT, g_swuT);
    cudaGetSymbolAddress((void**)&sdT, g_swdT);
    cudaGetSymbolAddress((void**)&inter, g_inter);
    cudaGetSymbolAddress((void**)&dtmp, g_dtmp);

    // fork: weight preprocessing on side stream
    cudaEventRecord(s_evFork, (cudaStream_t)0);
    cudaStreamWaitEvent(s_side, s_evFork, 0);
    trans_w1_kernel<<<dim3(I_DIM / 32, H_DIM / 32, 18), 256, 0, s_side>>>(Wg, Wu, sWg, sWu);
    trans_w2_kernel<<<dim3(H_DIM / 32, I_DIM / 32, 9), 256, 0, s_side>>>(Wd, sWd);
    cudaEventRecord(s_evJoin, s_side);

    // routing chain on main stream
    init_kernel<<<1, 32>>>();
    router_kernel<<<T_TOT / 32, 256>>>(X, GW);
    scatter_kernel<<<T_TOT / 256, 256>>>();

    // join
    cudaStreamWaitEvent((cudaStream_t)0, s_evJoin, 0);

    gu_mma_kernel<<<dim3(I_DIM / 64, T_TOT / 128, E_NUM + 1), 256, GU_SMEM>>>(
        wgT, wuT, sgT, suT, inter);
    dn_mma_kernel<<<dim3(H_DIM / 128, T_TOT / 128, E_NUM + 1), 256, DN_SMEM>>>(
        inter, wdT, sdT, dtmp);
    combine_kernel<<<T_TOT / 2, 256>>>(out);
}